// round 11
// baseline (speedup 1.0000x reference)
#include <cuda_runtime.h>
#include <cstdint>

#define HH 96
#define WW 96
#define CC 512
#define DD 64
#define N_POS 73728   // 8*96*96

// ---------------- scratch (device globals: no allocations allowed) ----------
__device__ float g_q[N_POS * DD];
__device__ float g_k[N_POS * DD];
__device__ float g_v[N_POS * CC];
__device__ float g_accv[N_POS * CC];
__device__ float g_mv[N_POS];
__device__ float g_lv[N_POS];
__device__ float g_wt[640 * 512];   // W pre-converted to tf32 (rna), n-major [n][k]

// ---------------- helpers ----------------------------------------------------
__device__ __forceinline__ uint32_t f2tf32(float f) {
    uint32_t u;
    asm("cvt.rna.tf32.f32 %0, %1;" : "=r"(u) : "f"(f));
    return u;
}

__device__ __forceinline__ void mma_tf32(float* c, const uint32_t* a, const uint32_t* b) {
    asm volatile(
        "mma.sync.aligned.m16n8k8.row.col.f32.tf32.tf32.f32 "
        "{%0,%1,%2,%3}, {%4,%5,%6,%7}, {%8,%9}, {%0,%1,%2,%3};\n"
        : "+f"(c[0]), "+f"(c[1]), "+f"(c[2]), "+f"(c[3])
        : "r"(a[0]), "r"(a[1]), "r"(a[2]), "r"(a[3]),
          "r"(b[0]), "r"(b[1]));
}

__device__ __forceinline__ uint32_t s2u(const void* p) {
    return (uint32_t)__cvta_generic_to_shared(p);
}

__device__ __forceinline__ void ldsm4(uint32_t* r, uint32_t addr) {
    asm volatile("ldmatrix.sync.aligned.m8n8.x4.shared.b16 {%0,%1,%2,%3}, [%4];"
        : "=r"(r[0]), "=r"(r[1]), "=r"(r[2]), "=r"(r[3]) : "r"(addr));
}

__device__ __forceinline__ void ldsm2(uint32_t* r, uint32_t addr) {
    asm volatile("ldmatrix.sync.aligned.m8n8.x2.shared.b16 {%0,%1}, [%2];"
        : "=r"(r[0]), "=r"(r[1]) : "r"(addr));
}

__device__ __forceinline__ void cpa16(uint32_t dst, const void* src) {
    asm volatile("cp.async.cg.shared.global [%0], [%1], 16;"
                 :: "r"(dst), "l"(src) : "memory");
}
__device__ __forceinline__ void cpa_commit() {
    asm volatile("cp.async.commit_group;" ::: "memory");
}
__device__ __forceinline__ void cpa_wait0() {
    asm volatile("cp.async.wait_group 0;" ::: "memory");
}
__device__ __forceinline__ void cpa_wait1() {
    asm volatile("cp.async.wait_group 1;" ::: "memory");
}
__device__ __forceinline__ void cpa_wait_all() {
    asm volatile("cp.async.wait_all;" ::: "memory");
}

// ---------------- Kernel 0: convert W to tf32, n-major ----------------------
__global__ __launch_bounds__(256) void cvt_w(
    const float* __restrict__ Wq, const float* __restrict__ Wk,
    const float* __restrict__ Wv)
{
    int i = blockIdx.x * 256 + threadIdx.x;      // < 640*512
    int n = i >> 9, k = i & 511;
    float v;
    if (n < 64)       v = Wq[k * 64 + n];
    else if (n < 128) v = Wk[k * 64 + (n - 64)];
    else              v = Wv[k * 512 + (n - 128)];
    g_wt[i] = __uint_as_float(f2tf32(v));
}

// ---------------- Kernel 1: fused QKV projection GEMM (tf32 tensor) ---------
// Grid: (5, 576). ct 0 -> q|k, ct 1..4 -> v cols. 128x128 tile, 3-stage async.
#define QKV_SMEM_BYTES (3 * 9216 * 4)

__global__ __launch_bounds__(256, 2) void qkv_gemm(
    const float* __restrict__ x,
    const float* __restrict__ bq, const float* __restrict__ bk,
    const float* __restrict__ bv)
{
    extern __shared__ uint32_t smQ[];

    const int ct = blockIdx.x;
    const int rowBase = blockIdx.y * 128;
    const int ctBase = ct * 128;

    const int tid  = threadIdx.x;
    const int lane = tid & 31;
    const int warp = tid >> 5;
    const int wm   = warp >> 1;
    const int wn   = warp & 1;
    const int g8   = lane >> 2;
    const int t4   = lane & 3;

    const uint32_t smBase = s2u(smQ);
    uint32_t aOff[2], bOff[4];
    #pragma unroll
    for (int mi = 0; mi < 2; ++mi)
        aOff[mi] = ((wm * 32 + mi * 16 + (lane & 15)) * 36 + 4 * (lane >> 4)) * 4;
    #pragma unroll
    for (int g = 0; g < 4; ++g)
        bOff[g] = (4608 + (wn * 64 + g * 16 + ((lane & 16) >> 1) + (lane & 7)) * 36
                   + 4 * ((lane >> 3) & 1)) * 4;

    float acc[2][8][4] = {};

    auto issue_chunk = [&](int c, int s) {
        const uint32_t aDst = smBase + (s * 9216) * 4;
        const uint32_t bDst = smBase + (s * 9216 + 4608) * 4;
        const int k0 = c * 32;
        #pragma unroll
        for (int i = 0; i < 4; ++i) {
            int idx = tid + i * 256;
            int row = idx >> 3, seg = idx & 7;
            cpa16(aDst + (row * 36 + seg * 4) * 4,
                  x + (size_t)(rowBase + row) * CC + k0 + seg * 4);
        }
        #pragma unroll
        for (int i = 0; i < 4; ++i) {
            int idx = tid + i * 256;
            int row = idx >> 3, seg = idx & 7;
            cpa16(bDst + (row * 36 + seg * 4) * 4,
                  g_wt + (size_t)(ctBase + row) * 512 + k0 + seg * 4);
        }
        cpa_commit();
    };

    issue_chunk(0, 0);
    issue_chunk(1, 1);

    for (int c = 0; c < 16; ++c) {
        const int s = c % 3;
        cpa_wait1();
        __syncthreads();

        if (c + 2 < 16) issue_chunk(c + 2, (c + 2) % 3);

        const uint32_t aStage = smBase + (s * 9216) * 4;
        #pragma unroll
        for (int kk = 0; kk < 4; ++kk) {
            const uint32_t kbB = kk * 32;
            uint32_t a[2][4], bf[4][4];
            ldsm4(a[0], aStage + aOff[0] + kbB);
            ldsm4(a[1], aStage + aOff[1] + kbB);
            ldsm4(bf[0], aStage + bOff[0] + kbB);
            ldsm4(bf[1], aStage + bOff[1] + kbB);
            ldsm4(bf[2], aStage + bOff[2] + kbB);
            ldsm4(bf[3], aStage + bOff[3] + kbB);
            #pragma unroll
            for (int mi = 0; mi < 2; ++mi)
                #pragma unroll
                for (int g = 0; g < 4; ++g) {
                    mma_tf32(acc[mi][g * 2    ], a[mi], bf[g]);
                    mma_tf32(acc[mi][g * 2 + 1], a[mi], bf[g] + 2);
                }
        }
    }

    float* dstBase; const float* biasBase; int ldw;
    if (ct == 0) {
        if (wn == 0) { dstBase = g_q; biasBase = bq; ldw = 64; }
        else         { dstBase = g_k; biasBase = bk; ldw = 64; }
    } else {
        dstBase = g_v + (ct - 1) * 128 + wn * 64;
        biasBase = bv + (ct - 1) * 128 + wn * 64;
        ldw = CC;
    }

    #pragma unroll
    for (int ni = 0; ni < 8; ++ni) {
        const int colL = ni * 8 + 2 * t4;
        const float b0 = biasBase[colL], b1 = biasBase[colL + 1];
        #pragma unroll
        for (int mi = 0; mi < 2; ++mi) {
            const int r0 = rowBase + wm * 32 + mi * 16 + g8;
            float2 o0 = { __uint_as_float(f2tf32(acc[mi][ni][0] + b0)),
                          __uint_as_float(f2tf32(acc[mi][ni][1] + b1)) };
            float2 o1 = { __uint_as_float(f2tf32(acc[mi][ni][2] + b0)),
                          __uint_as_float(f2tf32(acc[mi][ni][3] + b1)) };
            *(float2*)(dstBase + (size_t)r0 * ldw + colL) = o0;
            *(float2*)(dstBase + (size_t)(r0 + 8) * ldw + colL) = o1;
        }
    }
}

// ---------------- shared-memory layout for attention kernels ----------------
// words (float/u32):
// [0 .. 6528)     Qs (96x68)        -- overlaid by V chunk buffer (96x68)
// [6528 .. 8704)  Ks (32x68)        -- one 32-key pass buffer
// [8704 .. 18304) Ps (96x100)       cols 96..99 = stats (ms, ls, fv, fh)
#define QK_STRIDE 68
#define PS_STRIDE 100
#define VCH_STRIDE 68
#define SM_KS   6528
#define SM_PS   8704
#define SMEM_FLOATS 18304
#define SMEM_BYTES  (SMEM_FLOATS * 4)
#define NCHUNK 8   // 8 V chunks of 64 channels

// ---------------- Kernel 2: column attention pass (per (b,w)) ---------------
__global__ __launch_bounds__(256, 3) void col_attn()
{
    extern __shared__ float sm[];
    uint32_t* Qs  = (uint32_t*)sm;
    uint32_t* Ks  = (uint32_t*)(sm + SM_KS);
    float*    Ps  = sm + SM_PS;
    uint32_t* Psu = (uint32_t*)Ps;
    uint32_t* Vsu = (uint32_t*)sm;

    const int tid = threadIdx.x;
    const int lane = tid & 31;
    const int warp = tid >> 5;
    const int g8 = lane >> 2, t4 = lane & 3;
    const int b = blockIdx.x / WW;
    const int w = blockIdx.x % WW;

    const uint32_t qBase = s2u(Qs), kBase = s2u(Ks), pBase = s2u(Psu), vBase = s2u(Vsu);

    // fill Q (96 rows) + K pass 0 (rows 0..31)
    for (int idx = tid; idx < HH * 16; idx += 256) {
        int pos = idx >> 4, c4 = (idx & 15) * 4;
        cpa16(qBase + (pos * QK_STRIDE + c4) * 4,
              g_q + (size_t)((b * HH + pos) * WW + w) * DD + c4);
    }
    for (int idx = tid; idx < 32 * 16; idx += 256) {
        int row = idx >> 4, c4 = (idx & 15) * 4;
        cpa16(kBase + (row * QK_STRIDE + c4) * 4,
              g_k + (size_t)((b * HH + row) * WW + w) * DD + c4);
    }
    cpa_commit();

    // ---- scores in 3 key-passes of 32 keys; warps 2(M) x 4(N=8) ----
    const int sm0 = (warp & 1) * 48, sn0 = (warp >> 1) * 8;
    uint32_t qOff[3];
    #pragma unroll
    for (int mi = 0; mi < 3; ++mi)
        qOff[mi] = ((sm0 + mi * 16 + (lane & 15)) * QK_STRIDE + 4 * (lane >> 4)) * 4;
    const uint32_t kOff = ((sn0 + (lane & 7)) * QK_STRIDE + 4 * ((lane >> 3) & 1)) * 4;

    for (int p = 0; p < 3; ++p) {
        cpa_wait_all();
        __syncthreads();

        float acc[3][4] = {};
        #pragma unroll
        for (int ks = 0; ks < 8; ++ks) {
            const uint32_t kbB = ks * 32;
            uint32_t a[3][4], b2[2];
            ldsm4(a[0], qBase + qOff[0] + kbB);
            ldsm4(a[1], qBase + qOff[1] + kbB);
            ldsm4(a[2], qBase + qOff[2] + kbB);
            ldsm2(b2,  kBase + kOff + kbB);
            #pragma unroll
            for (int mi = 0; mi < 3; ++mi)
                mma_tf32(acc[mi], a[mi], b2);
        }
        __syncthreads();   // all warps done reading Ks

        if (p < 2) {
            for (int idx = tid; idx < 32 * 16; idx += 256) {
                int row = idx >> 4, c4 = (idx & 15) * 4;
                cpa16(kBase + (row * QK_STRIDE + c4) * 4,
                      g_k + (size_t)((b * HH + (p + 1) * 32 + row) * WW + w) * DD + c4);
            }
            cpa_commit();
        }

        // write scores with diagonal mask
        #pragma unroll
        for (int mi = 0; mi < 3; ++mi) {
            const int r0 = sm0 + mi * 16 + g8, r1 = r0 + 8;
            const int c0 = p * 32 + sn0 + 2 * t4, c1 = c0 + 1;
            Ps[r0 * PS_STRIDE + c0] = (r0 == c0) ? -1e30f : acc[mi][0];
            Ps[r0 * PS_STRIDE + c1] = (r0 == c1) ? -1e30f : acc[mi][1];
            Ps[r1 * PS_STRIDE + c0] = (r1 == c0) ? -1e30f : acc[mi][2];
            Ps[r1 * PS_STRIDE + c1] = (r1 == c1) ? -1e30f : acc[mi][3];
        }
    }

    // issue V chunk 0 (Qs dead after last pass's post-compute barrier)
    for (int idx = tid; idx < HH * 16; idx += 256) {
        int gg = idx >> 4, c4 = (idx & 15) * 4;
        cpa16(vBase + (gg * VCH_STRIDE + c4) * 4,
              g_v + (size_t)((b * HH + gg) * WW + w) * CC + c4);
    }
    cpa_commit();
    __syncthreads();   // scores visible

    // ---- softmax ----
    for (int h = warp; h < HH; h += 8) {
        float m = -3.4e38f;
        for (int g = lane; g < HH; g += 32) m = fmaxf(m, Ps[h * PS_STRIDE + g]);
        #pragma unroll
        for (int o = 16; o; o >>= 1) m = fmaxf(m, __shfl_xor_sync(0xffffffffu, m, o));
        float l = 0.f;
        for (int g = lane; g < HH; g += 32) {
            uint32_t u = f2tf32(__expf(Ps[h * PS_STRIDE + g] - m));
            Psu[h * PS_STRIDE + g] = u;
            l += __uint_as_float(u);
        }
        #pragma unroll
        for (int o = 16; o; o >>= 1) l += __shfl_xor_sync(0xffffffffu, l, o);
        if (lane == 0) {
            int n = (b * HH + h) * WW + w;
            g_mv[n] = m;
            g_lv[n] = l;
        }
    }

    // ---- acc_v = P @ V, 8 chunks of 64 channels, single buffer ----
    const int pm0 = (warp & 1) * 48, pn0 = (warp >> 1) * 16;
    uint32_t pOff[3];
    #pragma unroll
    for (int mi = 0; mi < 3; ++mi)
        pOff[mi] = ((pm0 + mi * 16 + (lane & 15)) * PS_STRIDE + 4 * (lane >> 4)) * 4;

    for (int c = 0; c < NCHUNK; ++c) {
        cpa_wait_all();
        __syncthreads();

        float acc[3][2][4] = {};
        #pragma unroll
        for (int ks = 0; ks < 12; ++ks) {
            const int kb = ks * 8;
            const uint32_t kbB = ks * 32;
            uint32_t a[3][4], bf[2][2];
            ldsm4(a[0], pBase + pOff[0] + kbB);
            ldsm4(a[1], pBase + pOff[1] + kbB);
            ldsm4(a[2], pBase + pOff[2] + kbB);
            #pragma unroll
            for (int ni = 0; ni < 2; ++ni) {
                const int n = pn0 + ni * 8 + g8;
                bf[ni][0] = Vsu[(kb + t4    ) * VCH_STRIDE + n];
                bf[ni][1] = Vsu[(kb + t4 + 4) * VCH_STRIDE + n];
            }
            #pragma unroll
            for (int mi = 0; mi < 3; ++mi)
                #pragma unroll
                for (int ni = 0; ni < 2; ++ni)
                    mma_tf32(acc[mi][ni], a[mi], bf[ni]);
        }
        __syncthreads();   // all warps done reading V

        if (c + 1 < NCHUNK) {
            for (int idx = tid; idx < HH * 16; idx += 256) {
                int gg = idx >> 4, c4 = (idx & 15) * 4;
                cpa16(vBase + (gg * VCH_STRIDE + c4) * 4,
                      g_v + (size_t)((b * HH + gg) * WW + w) * CC + (c + 1) * 64 + c4);
            }
            cpa_commit();
        }

        #pragma unroll
        for (int mi = 0; mi < 3; ++mi) {
            const int rA = pm0 + mi * 16 + g8;
            const size_t nA = (size_t)((b * HH + rA    ) * WW + w) * CC;
            const size_t nB = (size_t)((b * HH + rA + 8) * WW + w) * CC;
            #pragma unroll
            for (int ni = 0; ni < 2; ++ni) {
                const int col = c * 64 + pn0 + ni * 8 + 2 * t4;
                float2 o0 = { acc[mi][ni][0], acc[mi][ni][1] };
                float2 o1 = { acc[mi][ni][2], acc[mi][ni][3] };
                *(float2*)(g_accv + nA + col) = o0;
                *(float2*)(g_accv + nB + col) = o1;
            }
        }
    }
}

// ---------------- Kernel 3: row attention pass + combine (per (b,h)) --------
__global__ __launch_bounds__(256, 3) void row_attn(
    const float* __restrict__ x, const float* __restrict__ gammap,
    float* __restrict__ out)
{
    extern __shared__ float sm[];
    uint32_t* Qs  = (uint32_t*)sm;
    uint32_t* Ks  = (uint32_t*)(sm + SM_KS);
    float*    Ps  = sm + SM_PS;
    uint32_t* Psu = (uint32_t*)Ps;
    uint32_t* Vsu = (uint32_t*)sm;

    const int tid = threadIdx.x;
    const int lane = tid & 31;
    const int warp = tid >> 5;
    const int g8 = lane >> 2, t4 = lane & 3;
    const int b = blockIdx.x / HH;
    const int h = blockIdx.x % HH;
    const int nbase = (b * HH + h) * WW;

    const uint32_t qBase = s2u(Qs), kBase = s2u(Ks), pBase = s2u(Psu), vBase = s2u(Vsu);

    for (int idx = tid; idx < WW * 16; idx += 256) {
        int pos = idx >> 4, c4 = (idx & 15) * 4;
        cpa16(qBase + (pos * QK_STRIDE + c4) * 4, g_q + (size_t)(nbase + pos) * DD + c4);
    }
    for (int idx = tid; idx < 32 * 16; idx += 256) {
        int row = idx >> 4, c4 = (idx & 15) * 4;
        cpa16(kBase + (row * QK_STRIDE + c4) * 4, g_k + (size_t)(nbase + row) * DD + c4);
    }
    cpa_commit();
    // column-pass stats into Ps padding (cols 98/99)
    if (tid < WW) {
        Ps[tid * PS_STRIDE + 98] = g_mv[nbase + tid];
        Ps[tid * PS_STRIDE + 99] = g_lv[nbase + tid];
    }

    const int sm0 = (warp & 1) * 48, sn0 = (warp >> 1) * 8;
    uint32_t qOff[3];
    #pragma unroll
    for (int mi = 0; mi < 3; ++mi)
        qOff[mi] = ((sm0 + mi * 16 + (lane & 15)) * QK_STRIDE + 4 * (lane >> 4)) * 4;
    const uint32_t kOff = ((sn0 + (lane & 7)) * QK_STRIDE + 4 * ((lane >> 3) & 1)) * 4;

    for (int p = 0; p < 3; ++p) {
        cpa_wait_all();
        __syncthreads();

        float acc[3][4] = {};
        #pragma unroll
        for (int ks = 0; ks < 8; ++ks) {
            const uint32_t kbB = ks * 32;
            uint32_t a[3][4], b2[2];
            ldsm4(a[0], qBase + qOff[0] + kbB);
            ldsm4(a[1], qBase + qOff[1] + kbB);
            ldsm4(a[2], qBase + qOff[2] + kbB);
            ldsm2(b2,  kBase + kOff + kbB);
            #pragma unroll
            for (int mi = 0; mi < 3; ++mi)
                mma_tf32(acc[mi], a[mi], b2);
        }
        __syncthreads();

        if (p < 2) {
            for (int idx = tid; idx < 32 * 16; idx += 256) {
                int row = idx >> 4, c4 = (idx & 15) * 4;
                cpa16(kBase + (row * QK_STRIDE + c4) * 4,
                      g_k + (size_t)(nbase + (p + 1) * 32 + row) * DD + c4);
            }
            cpa_commit();
        }

        #pragma unroll
        for (int mi = 0; mi < 3; ++mi) {
            const int r0 = sm0 + mi * 16 + g8, r1 = r0 + 8;
            const int c0 = p * 32 + sn0 + 2 * t4;
            *(float2*)&Ps[r0 * PS_STRIDE + c0] = *(float2*)&acc[mi][0];
            *(float2*)&Ps[r1 * PS_STRIDE + c0] = *(float2*)&acc[mi][2];
        }
    }

    // issue V chunk 0
    for (int idx = tid; idx < WW * 16; idx += 256) {
        int u0 = idx >> 4, c4 = (idx & 15) * 4;
        cpa16(vBase + (u0 * VCH_STRIDE + c4) * 4,
              g_v + (size_t)(nbase + u0) * CC + c4);
    }
    cpa_commit();
    __syncthreads();

    // softmax, stats into Ps padding cols 96/97
    for (int wq = warp; wq < WW; wq += 8) {
        float m = -3.4e38f;
        for (int g = lane; g < WW; g += 32) m = fmaxf(m, Ps[wq * PS_STRIDE + g]);
        #pragma unroll
        for (int o = 16; o; o >>= 1) m = fmaxf(m, __shfl_xor_sync(0xffffffffu, m, o));
        float l = 0.f;
        for (int g = lane; g < WW; g += 32) {
            uint32_t u = f2tf32(__expf(Ps[wq * PS_STRIDE + g] - m));
            Psu[wq * PS_STRIDE + g] = u;
            l += __uint_as_float(u);
        }
        #pragma unroll
        for (int o = 16; o; o >>= 1) l += __shfl_xor_sync(0xffffffffu, l, o);
        if (lane == 0) { Ps[wq * PS_STRIDE + 96] = m; Ps[wq * PS_STRIDE + 97] = l; }
    }
    __syncthreads();

    // exact combine factors -> cols 98/99
    if (tid < WW) {
        float mh = Ps[tid * PS_STRIDE + 96], lh = Ps[tid * PS_STRIDE + 97];
        float mv = Ps[tid * PS_STRIDE + 98], lv = Ps[tid * PS_STRIDE + 99];
        float M  = fmaxf(mh, mv);
        float ev = __expf(mv - M), eh = __expf(mh - M);
        float inv = 1.f / (ev * lv + eh * lh);
        Ps[tid * PS_STRIDE + 98] = ev * inv;
        Ps[tid * PS_STRIDE + 99] = eh * inv;
    }
    __syncthreads();

    const float gamma = *gammap;
    const int pm0 = (warp & 1) * 48, pn0 = (warp >> 1) * 16;
    uint32_t pOff[3];
    #pragma unroll
    for (int mi = 0; mi < 3; ++mi)
        pOff[mi] = ((pm0 + mi * 16 + (lane & 15)) * PS_STRIDE + 4 * (lane >> 4)) * 4;

    for (int c = 0; c < NCHUNK; ++c) {
        cpa_wait_all();
        __syncthreads();

        float acc[3][2][4] = {};
        #pragma unroll
        for (int ks = 0; ks < 12; ++ks) {
            const int kb = ks * 8;
            const uint32_t kbB = ks * 32;
            uint32_t a[3][4], bf[2][2];
            ldsm4(a[0], pBase + pOff[0] + kbB);
            ldsm4(a[1], pBase + pOff[1] + kbB);
            ldsm4(a[2], pBase + pOff[2] + kbB);
            #pragma unroll
            for (int ni = 0; ni < 2; ++ni) {
                const int n = pn0 + ni * 8 + g8;
                bf[ni][0] = Vsu[(kb + t4    ) * VCH_STRIDE + n];
                bf[ni][1] = Vsu[(kb + t4 + 4) * VCH_STRIDE + n];
            }
            #pragma unroll
            for (int mi = 0; mi < 3; ++mi)
                #pragma unroll
                for (int ni = 0; ni < 2; ++ni)
                    mma_tf32(acc[mi][ni], a[mi], bf[ni]);
        }
        __syncthreads();

        if (c + 1 < NCHUNK) {
            for (int idx = tid; idx < WW * 16; idx += 256) {
                int u0 = idx >> 4, c4 = (idx & 15) * 4;
                cpa16(vBase + (u0 * VCH_STRIDE + c4) * 4,
                      g_v + (size_t)(nbase + u0) * CC + (c + 1) * 64 + c4);
            }
            cpa_commit();
        }

        #pragma unroll
        for (int mi = 0; mi < 3; ++mi) {
            const int rA = pm0 + mi * 16 + g8;
            const int rB = rA + 8;
            const float fvA = Ps[rA * PS_STRIDE + 98], fhA = Ps[rA * PS_STRIDE + 99];
            const float fvB = Ps[rB * PS_STRIDE + 98], fhB = Ps[rB * PS_STRIDE + 99];
            const size_t oA = (size_t)(nbase + rA) * CC;
            const size_t oB = (size_t)(nbase + rB) * CC;
            #pragma unroll
            for (int ni = 0; ni < 2; ++ni) {
                const int col = c * 64 + pn0 + ni * 8 + 2 * t4;
                float2 avA = *(const float2*)(g_accv + oA + col);
                float2 xvA = *(const float2*)(x + oA + col);
                float2 avB = *(const float2*)(g_accv + oB + col);
                float2 xvB = *(const float2*)(x + oB + col);
                float2 o0, o1;
                o0.x = xvA.x + gamma * (fvA * avA.x + fhA * acc[mi][ni][0]);
                o0.y = xvA.y + gamma * (fvA * avA.y + fhA * acc[mi][ni][1]);
                o1.x = xvB.x + gamma * (fvB * avB.x + fhB * acc[mi][ni][2]);
                o1.y = xvB.y + gamma * (fvB * avB.y + fhB * acc[mi][ni][3]);
                *(float2*)(out + oA + col) = o0;
                *(float2*)(out + oB + col) = o1;
            }
        }
    }
}

// ---------------- launch ----------------------------------------------------
extern "C" void kernel_launch(void* const* d_in, const int* in_sizes, int n_in,
                              void* d_out, int out_size)
{
    const float* x  = (const float*)d_in[0];
    const float* Wq = (const float*)d_in[1];
    const float* bq = (const float*)d_in[2];
    const float* Wk = (const float*)d_in[3];
    const float* bk = (const float*)d_in[4];
    const float* Wv = (const float*)d_in[5];
    const float* bv = (const float*)d_in[6];
    const float* gm = (const float*)d_in[7];
    float* out = (float*)d_out;

    cudaFuncSetAttribute(qkv_gemm, cudaFuncAttributeMaxDynamicSharedMemorySize, QKV_SMEM_BYTES);
    cudaFuncSetAttribute(col_attn, cudaFuncAttributeMaxDynamicSharedMemorySize, SMEM_BYTES);
    cudaFuncSetAttribute(row_attn, cudaFuncAttributeMaxDynamicSharedMemorySize, SMEM_BYTES);

    cvt_w<<<1280, 256>>>(Wq, Wk, Wv);
    dim3 gA(5, 576);
    qkv_gemm<<<gA, 256, QKV_SMEM_BYTES>>>(x, bq, bk, bv);
    col_attn<<<768, 256, SMEM_BYTES>>>();
    row_attn<<<768, 256, SMEM_BYTES>>>(x, gm, out);
}

// round 12
// speedup vs baseline: 1.0705x; 1.0705x over previous
#include <cuda_runtime.h>
#include <cuda_bf16.h>
#include <cstdint>

#define HH 96
#define WW 96
#define CC 512
#define DD 64
#define N_POS 73728   // 8*96*96

// ---------------- scratch (device globals: no allocations allowed) ----------
__device__ float g_q[N_POS * DD];
__device__ float g_k[N_POS * DD];
__device__ float g_v[N_POS * CC];
__device__ __nv_bfloat16 g_accv[N_POS * CC];   // bf16 column-pass accumulator
__device__ float g_mv[N_POS];
__device__ float g_lv[N_POS];
__device__ float g_wt[640 * 512];   // W pre-converted to tf32 (rna), n-major [n][k]

// ---------------- helpers ----------------------------------------------------
__device__ __forceinline__ uint32_t f2tf32(float f) {
    uint32_t u;
    asm("cvt.rna.tf32.f32 %0, %1;" : "=r"(u) : "f"(f));
    return u;
}

__device__ __forceinline__ void mma_tf32(float* c, const uint32_t* a, const uint32_t* b) {
    asm volatile(
        "mma.sync.aligned.m16n8k8.row.col.f32.tf32.tf32.f32 "
        "{%0,%1,%2,%3}, {%4,%5,%6,%7}, {%8,%9}, {%0,%1,%2,%3};\n"
        : "+f"(c[0]), "+f"(c[1]), "+f"(c[2]), "+f"(c[3])
        : "r"(a[0]), "r"(a[1]), "r"(a[2]), "r"(a[3]),
          "r"(b[0]), "r"(b[1]));
}

__device__ __forceinline__ uint32_t s2u(const void* p) {
    return (uint32_t)__cvta_generic_to_shared(p);
}

__device__ __forceinline__ void ldsm4(uint32_t* r, uint32_t addr) {
    asm volatile("ldmatrix.sync.aligned.m8n8.x4.shared.b16 {%0,%1,%2,%3}, [%4];"
        : "=r"(r[0]), "=r"(r[1]), "=r"(r[2]), "=r"(r[3]) : "r"(addr));
}

__device__ __forceinline__ void ldsm2(uint32_t* r, uint32_t addr) {
    asm volatile("ldmatrix.sync.aligned.m8n8.x2.shared.b16 {%0,%1}, [%2];"
        : "=r"(r[0]), "=r"(r[1]) : "r"(addr));
}

__device__ __forceinline__ void cpa16(uint32_t dst, const void* src) {
    asm volatile("cp.async.cg.shared.global [%0], [%1], 16;"
                 :: "r"(dst), "l"(src) : "memory");
}
__device__ __forceinline__ void cpa_commit() {
    asm volatile("cp.async.commit_group;" ::: "memory");
}
__device__ __forceinline__ void cpa_wait0() {
    asm volatile("cp.async.wait_group 0;" ::: "memory");
}
__device__ __forceinline__ void cpa_wait1() {
    asm volatile("cp.async.wait_group 1;" ::: "memory");
}
__device__ __forceinline__ void cpa_wait_all() {
    asm volatile("cp.async.wait_all;" ::: "memory");
}

// ---------------- Kernel 0: convert W to tf32, n-major ----------------------
__global__ __launch_bounds__(256) void cvt_w(
    const float* __restrict__ Wq, const float* __restrict__ Wk,
    const float* __restrict__ Wv)
{
    int i = blockIdx.x * 256 + threadIdx.x;      // < 640*512
    int n = i >> 9, k = i & 511;
    float v;
    if (n < 64)       v = Wq[k * 64 + n];
    else if (n < 128) v = Wk[k * 64 + (n - 64)];
    else              v = Wv[k * 512 + (n - 128)];
    g_wt[i] = __uint_as_float(f2tf32(v));
}

// ---------------- Kernel 1: fused QKV projection GEMM (tf32 tensor) ---------
// Grid: (5, 576). ct 0 -> q|k, ct 1..4 -> v cols. 128x128 tile, 3-stage async.
#define QKV_SMEM_BYTES (3 * 9216 * 4)

__global__ __launch_bounds__(256, 2) void qkv_gemm(
    const float* __restrict__ x,
    const float* __restrict__ bq, const float* __restrict__ bk,
    const float* __restrict__ bv)
{
    extern __shared__ uint32_t smQ[];

    const int ct = blockIdx.x;
    const int rowBase = blockIdx.y * 128;
    const int ctBase = ct * 128;

    const int tid  = threadIdx.x;
    const int lane = tid & 31;
    const int warp = tid >> 5;
    const int wm   = warp >> 1;
    const int wn   = warp & 1;
    const int g8   = lane >> 2;
    const int t4   = lane & 3;

    const uint32_t smBase = s2u(smQ);
    uint32_t aOff[2], bOff[4];
    #pragma unroll
    for (int mi = 0; mi < 2; ++mi)
        aOff[mi] = ((wm * 32 + mi * 16 + (lane & 15)) * 36 + 4 * (lane >> 4)) * 4;
    #pragma unroll
    for (int g = 0; g < 4; ++g)
        bOff[g] = (4608 + (wn * 64 + g * 16 + ((lane & 16) >> 1) + (lane & 7)) * 36
                   + 4 * ((lane >> 3) & 1)) * 4;

    float acc[2][8][4] = {};

    auto issue_chunk = [&](int c, int s) {
        const uint32_t aDst = smBase + (s * 9216) * 4;
        const uint32_t bDst = smBase + (s * 9216 + 4608) * 4;
        const int k0 = c * 32;
        #pragma unroll
        for (int i = 0; i < 4; ++i) {
            int idx = tid + i * 256;
            int row = idx >> 3, seg = idx & 7;
            cpa16(aDst + (row * 36 + seg * 4) * 4,
                  x + (size_t)(rowBase + row) * CC + k0 + seg * 4);
        }
        #pragma unroll
        for (int i = 0; i < 4; ++i) {
            int idx = tid + i * 256;
            int row = idx >> 3, seg = idx & 7;
            cpa16(bDst + (row * 36 + seg * 4) * 4,
                  g_wt + (size_t)(ctBase + row) * 512 + k0 + seg * 4);
        }
        cpa_commit();
    };

    issue_chunk(0, 0);
    issue_chunk(1, 1);

    for (int c = 0; c < 16; ++c) {
        const int s = c % 3;
        cpa_wait1();
        __syncthreads();

        if (c + 2 < 16) issue_chunk(c + 2, (c + 2) % 3);

        const uint32_t aStage = smBase + (s * 9216) * 4;
        #pragma unroll
        for (int kk = 0; kk < 4; ++kk) {
            const uint32_t kbB = kk * 32;
            uint32_t a[2][4], bf[4][4];
            ldsm4(a[0], aStage + aOff[0] + kbB);
            ldsm4(a[1], aStage + aOff[1] + kbB);
            ldsm4(bf[0], aStage + bOff[0] + kbB);
            ldsm4(bf[1], aStage + bOff[1] + kbB);
            ldsm4(bf[2], aStage + bOff[2] + kbB);
            ldsm4(bf[3], aStage + bOff[3] + kbB);
            #pragma unroll
            for (int mi = 0; mi < 2; ++mi)
                #pragma unroll
                for (int g = 0; g < 4; ++g) {
                    mma_tf32(acc[mi][g * 2    ], a[mi], bf[g]);
                    mma_tf32(acc[mi][g * 2 + 1], a[mi], bf[g] + 2);
                }
        }
    }

    float* dstBase; const float* biasBase; int ldw;
    if (ct == 0) {
        if (wn == 0) { dstBase = g_q; biasBase = bq; ldw = 64; }
        else         { dstBase = g_k; biasBase = bk; ldw = 64; }
    } else {
        dstBase = g_v + (ct - 1) * 128 + wn * 64;
        biasBase = bv + (ct - 1) * 128 + wn * 64;
        ldw = CC;
    }

    #pragma unroll
    for (int ni = 0; ni < 8; ++ni) {
        const int colL = ni * 8 + 2 * t4;
        const float b0 = biasBase[colL], b1 = biasBase[colL + 1];
        #pragma unroll
        for (int mi = 0; mi < 2; ++mi) {
            const int r0 = rowBase + wm * 32 + mi * 16 + g8;
            float2 o0 = { __uint_as_float(f2tf32(acc[mi][ni][0] + b0)),
                          __uint_as_float(f2tf32(acc[mi][ni][1] + b1)) };
            float2 o1 = { __uint_as_float(f2tf32(acc[mi][ni][2] + b0)),
                          __uint_as_float(f2tf32(acc[mi][ni][3] + b1)) };
            *(float2*)(dstBase + (size_t)r0 * ldw + colL) = o0;
            *(float2*)(dstBase + (size_t)(r0 + 8) * ldw + colL) = o1;
        }
    }
}

// ---------------- shared-memory layout for attention kernels ----------------
#define QK_STRIDE 68
#define PS_STRIDE 100
#define VCH_STRIDE 68
#define SM_KS   6528
#define SM_PS   13056
#define SM_MS   22656
#define SM_LS   22752
#define SM_FV   22848
#define SM_FH   22944
#define SMEM_FLOATS 23040
#define SMEM_BYTES  (SMEM_FLOATS * 4)
#define NCHUNK 8   // 8 chunks of 64 channels

// ---------------- Kernel 2: column attention pass (per (b,w)) ---------------
__global__ __launch_bounds__(256, 2) void col_attn()
{
    extern __shared__ float sm[];
    uint32_t* Qs  = (uint32_t*)sm;
    uint32_t* Ks  = (uint32_t*)(sm + SM_KS);
    float*    Ps  = sm + SM_PS;
    uint32_t* Psu = (uint32_t*)Ps;
    uint32_t* Vsu = (uint32_t*)sm;   // two 96x68 buffers overlay Qs|Ks

    const int tid = threadIdx.x;
    const int lane = tid & 31;
    const int warp = tid >> 5;
    const int g8 = lane >> 2, t4 = lane & 3;
    const int b = blockIdx.x / WW;
    const int w = blockIdx.x % WW;

    const uint32_t qBase = s2u(Qs), kBase = s2u(Ks), pBase = s2u(Psu), vBase = s2u(Vsu);

    for (int idx = tid; idx < HH * 16; idx += 256) {
        int pos = idx >> 4, c4 = (idx & 15) * 4;
        size_t off = (size_t)((b * HH + pos) * WW + w) * DD + c4;
        uint32_t d = (pos * QK_STRIDE + c4) * 4;
        cpa16(qBase + d, g_q + off);
        cpa16(kBase + d, g_k + off);
    }
    cpa_commit();
    cpa_wait_all();
    __syncthreads();

    {
        const int sm0 = (warp & 1) * 48, sn0 = (warp >> 1) * 24;
        uint32_t qOff[3];
        #pragma unroll
        for (int mi = 0; mi < 3; ++mi)
            qOff[mi] = ((sm0 + mi * 16 + (lane & 15)) * QK_STRIDE + 4 * (lane >> 4)) * 4;
        const uint32_t kOff01 = ((sn0 + ((lane & 16) >> 1) + (lane & 7)) * QK_STRIDE
                                 + 4 * ((lane >> 3) & 1)) * 4;
        const uint32_t kOff2  = ((sn0 + 16 + (lane & 7)) * QK_STRIDE
                                 + 4 * ((lane >> 3) & 1)) * 4;

        float acc[3][3][4] = {};
        #pragma unroll
        for (int ks = 0; ks < 8; ++ks) {
            const uint32_t kbB = ks * 32;
            uint32_t a[3][4], b01[4], b2[2];
            ldsm4(a[0], qBase + qOff[0] + kbB);
            ldsm4(a[1], qBase + qOff[1] + kbB);
            ldsm4(a[2], qBase + qOff[2] + kbB);
            ldsm4(b01, kBase + kOff01 + kbB);
            ldsm2(b2,  kBase + kOff2  + kbB);
            #pragma unroll
            for (int mi = 0; mi < 3; ++mi) {
                mma_tf32(acc[mi][0], a[mi], b01);
                mma_tf32(acc[mi][1], a[mi], b01 + 2);
                mma_tf32(acc[mi][2], a[mi], b2);
            }
        }

        #pragma unroll
        for (int mi = 0; mi < 3; ++mi) {
            const int r0 = sm0 + mi * 16 + g8, r1 = r0 + 8;
            #pragma unroll
            for (int ni = 0; ni < 3; ++ni) {
                const int c0 = sn0 + ni * 8 + 2 * t4, c1 = c0 + 1;
                Ps[r0 * PS_STRIDE + c0] = (r0 == c0) ? -1e30f : acc[mi][ni][0];
                Ps[r0 * PS_STRIDE + c1] = (r0 == c1) ? -1e30f : acc[mi][ni][1];
                Ps[r1 * PS_STRIDE + c0] = (r1 == c0) ? -1e30f : acc[mi][ni][2];
                Ps[r1 * PS_STRIDE + c1] = (r1 == c1) ? -1e30f : acc[mi][ni][3];
            }
        }
    }
    __syncthreads();   // Qs/Ks now dead

    {
        const uint32_t dst = vBase;
        for (int idx = tid; idx < HH * 16; idx += 256) {
            int gg = idx >> 4, c4 = (idx & 15) * 4;
            cpa16(dst + (gg * VCH_STRIDE + c4) * 4,
                  g_v + (size_t)((b * HH + gg) * WW + w) * CC + c4);
        }
        cpa_commit();
    }

    for (int h = warp; h < HH; h += 8) {
        float m = -3.4e38f;
        for (int g = lane; g < HH; g += 32) m = fmaxf(m, Ps[h * PS_STRIDE + g]);
        #pragma unroll
        for (int o = 16; o; o >>= 1) m = fmaxf(m, __shfl_xor_sync(0xffffffffu, m, o));
        float l = 0.f;
        for (int g = lane; g < HH; g += 32) {
            uint32_t u = f2tf32(__expf(Ps[h * PS_STRIDE + g] - m));
            Psu[h * PS_STRIDE + g] = u;
            l += __uint_as_float(u);
        }
        #pragma unroll
        for (int o = 16; o; o >>= 1) l += __shfl_xor_sync(0xffffffffu, l, o);
        if (lane == 0) {
            int n = (b * HH + h) * WW + w;
            g_mv[n] = m;
            g_lv[n] = l;
        }
    }

    const int pm0 = (warp & 1) * 48, pn0 = (warp >> 1) * 16;
    uint32_t pOff[3];
    #pragma unroll
    for (int mi = 0; mi < 3; ++mi)
        pOff[mi] = ((pm0 + mi * 16 + (lane & 15)) * PS_STRIDE + 4 * (lane >> 4)) * 4;

    for (int c = 0; c < NCHUNK; ++c) {
        if (c + 1 < NCHUNK) {
            const uint32_t dst = vBase + ((c + 1) & 1) * 6528 * 4;
            for (int idx = tid; idx < HH * 16; idx += 256) {
                int gg = idx >> 4, c4 = (idx & 15) * 4;
                cpa16(dst + (gg * VCH_STRIDE + c4) * 4,
                      g_v + (size_t)((b * HH + gg) * WW + w) * CC + (c + 1) * 64 + c4);
            }
            cpa_commit();
            cpa_wait1();
        } else {
            cpa_wait0();
        }
        __syncthreads();

        const uint32_t* Vb = Vsu + (c & 1) * 6528;
        float acc[3][2][4] = {};
        #pragma unroll
        for (int ks = 0; ks < 12; ++ks) {
            const int kb = ks * 8;
            const uint32_t kbB = ks * 32;
            uint32_t a[3][4], bf[2][2];
            ldsm4(a[0], pBase + pOff[0] + kbB);
            ldsm4(a[1], pBase + pOff[1] + kbB);
            ldsm4(a[2], pBase + pOff[2] + kbB);
            #pragma unroll
            for (int ni = 0; ni < 2; ++ni) {
                const int n = pn0 + ni * 8 + g8;
                bf[ni][0] = Vb[(kb + t4    ) * VCH_STRIDE + n];
                bf[ni][1] = Vb[(kb + t4 + 4) * VCH_STRIDE + n];
            }
            #pragma unroll
            for (int mi = 0; mi < 3; ++mi)
                #pragma unroll
                for (int ni = 0; ni < 2; ++ni)
                    mma_tf32(acc[mi][ni], a[mi], bf[ni]);
        }

        #pragma unroll
        for (int mi = 0; mi < 3; ++mi) {
            const int rA = pm0 + mi * 16 + g8;
            const size_t nA = (size_t)((b * HH + rA    ) * WW + w) * CC;
            const size_t nB = (size_t)((b * HH + rA + 8) * WW + w) * CC;
            #pragma unroll
            for (int ni = 0; ni < 2; ++ni) {
                const int col = c * 64 + pn0 + ni * 8 + 2 * t4;
                float2 o0 = { acc[mi][ni][0], acc[mi][ni][1] };
                float2 o1 = { acc[mi][ni][2], acc[mi][ni][3] };
                *(__nv_bfloat162*)(g_accv + nA + col) = __float22bfloat162_rn(o0);
                *(__nv_bfloat162*)(g_accv + nB + col) = __float22bfloat162_rn(o1);
            }
        }
        __syncthreads();
    }
}

// ---------------- Kernel 3: row attention pass + combine (per (b,h)) --------
__global__ __launch_bounds__(256, 2) void row_attn(
    const float* __restrict__ x, const float* __restrict__ gammap,
    float* __restrict__ out)
{
    extern __shared__ float sm[];
    uint32_t* Qs  = (uint32_t*)sm;
    uint32_t* Ks  = (uint32_t*)(sm + SM_KS);
    float*    Ps  = sm + SM_PS;
    uint32_t* Psu = (uint32_t*)Ps;
    uint32_t* Vsu = (uint32_t*)sm;
    float* ms = sm + SM_MS;
    float* ls = sm + SM_LS;
    float* fv = sm + SM_FV;
    float* fh = sm + SM_FH;

    const int tid = threadIdx.x;
    const int lane = tid & 31;
    const int warp = tid >> 5;
    const int g8 = lane >> 2, t4 = lane & 3;
    const int b = blockIdx.x / HH;
    const int h = blockIdx.x % HH;
    const int nbase = (b * HH + h) * WW;

    const uint32_t qBase = s2u(Qs), kBase = s2u(Ks), pBase = s2u(Psu), vBase = s2u(Vsu);

    for (int idx = tid; idx < WW * 16; idx += 256) {
        int pos = idx >> 4, c4 = (idx & 15) * 4;
        size_t off = (size_t)(nbase + pos) * DD + c4;
        uint32_t d = (pos * QK_STRIDE + c4) * 4;
        cpa16(qBase + d, g_q + off);
        cpa16(kBase + d, g_k + off);
    }
    if (tid < WW) {
        fv[tid] = g_mv[nbase + tid];
        fh[tid] = g_lv[nbase + tid];
    }
    cpa_commit();
    cpa_wait_all();
    __syncthreads();

    {
        const int sm0 = (warp & 1) * 48, sn0 = (warp >> 1) * 24;
        uint32_t qOff[3];
        #pragma unroll
        for (int mi = 0; mi < 3; ++mi)
            qOff[mi] = ((sm0 + mi * 16 + (lane & 15)) * QK_STRIDE + 4 * (lane >> 4)) * 4;
        const uint32_t kOff01 = ((sn0 + ((lane & 16) >> 1) + (lane & 7)) * QK_STRIDE
                                 + 4 * ((lane >> 3) & 1)) * 4;
        const uint32_t kOff2  = ((sn0 + 16 + (lane & 7)) * QK_STRIDE
                                 + 4 * ((lane >> 3) & 1)) * 4;

        float acc[3][3][4] = {};
        #pragma unroll
        for (int ks = 0; ks < 8; ++ks) {
            const uint32_t kbB = ks * 32;
            uint32_t a[3][4], b01[4], b2[2];
            ldsm4(a[0], qBase + qOff[0] + kbB);
            ldsm4(a[1], qBase + qOff[1] + kbB);
            ldsm4(a[2], qBase + qOff[2] + kbB);
            ldsm4(b01, kBase + kOff01 + kbB);
            ldsm2(b2,  kBase + kOff2  + kbB);
            #pragma unroll
            for (int mi = 0; mi < 3; ++mi) {
                mma_tf32(acc[mi][0], a[mi], b01);
                mma_tf32(acc[mi][1], a[mi], b01 + 2);
                mma_tf32(acc[mi][2], a[mi], b2);
            }
        }

        #pragma unroll
        for (int mi = 0; mi < 3; ++mi) {
            const int r0 = sm0 + mi * 16 + g8, r1 = r0 + 8;
            #pragma unroll
            for (int ni = 0; ni < 3; ++ni) {
                const int c0 = sn0 + ni * 8 + 2 * t4;
                *(float2*)&Ps[r0 * PS_STRIDE + c0] = *(float2*)&acc[mi][ni][0];
                *(float2*)&Ps[r1 * PS_STRIDE + c0] = *(float2*)&acc[mi][ni][2];
            }
        }
    }
    __syncthreads();   // Qs/Ks dead

    {
        for (int idx = tid; idx < WW * 16; idx += 256) {
            int u0 = idx >> 4, c4 = (idx & 15) * 4;
            cpa16(vBase + (u0 * VCH_STRIDE + c4) * 4,
                  g_v + (size_t)(nbase + u0) * CC + c4);
        }
        cpa_commit();
    }

    for (int wq = warp; wq < WW; wq += 8) {
        float m = -3.4e38f;
        for (int g = lane; g < WW; g += 32) m = fmaxf(m, Ps[wq * PS_STRIDE + g]);
        #pragma unroll
        for (int o = 16; o; o >>= 1) m = fmaxf(m, __shfl_xor_sync(0xffffffffu, m, o));
        float l = 0.f;
        for (int g = lane; g < WW; g += 32) {
            uint32_t u = f2tf32(__expf(Ps[wq * PS_STRIDE + g] - m));
            Psu[wq * PS_STRIDE + g] = u;
            l += __uint_as_float(u);
        }
        #pragma unroll
        for (int o = 16; o; o >>= 1) l += __shfl_xor_sync(0xffffffffu, l, o);
        if (lane == 0) { ms[wq] = m; ls[wq] = l; }
    }
    __syncthreads();

    if (tid < WW) {
        float mh = ms[tid], lh = ls[tid];
        float mv = fv[tid], lv = fh[tid];
        float M  = fmaxf(mh, mv);
        float ev = __expf(mv - M), eh = __expf(mh - M);
        float inv = 1.f / (ev * lv + eh * lh);
        fv[tid] = ev * inv;
        fh[tid] = eh * inv;
    }

    const float gamma = *gammap;
    const int pm0 = (warp & 1) * 48, pn0 = (warp >> 1) * 16;
    uint32_t pOff[3];
    #pragma unroll
    for (int mi = 0; mi < 3; ++mi)
        pOff[mi] = ((pm0 + mi * 16 + (lane & 15)) * PS_STRIDE + 4 * (lane >> 4)) * 4;

    for (int c = 0; c < NCHUNK; ++c) {
        if (c + 1 < NCHUNK) {
            const uint32_t dst = vBase + ((c + 1) & 1) * 6528 * 4;
            for (int idx = tid; idx < WW * 16; idx += 256) {
                int u0 = idx >> 4, c4 = (idx & 15) * 4;
                cpa16(dst + (u0 * VCH_STRIDE + c4) * 4,
                      g_v + (size_t)(nbase + u0) * CC + (c + 1) * 64 + c4);
            }
            cpa_commit();
            cpa_wait1();
        } else {
            cpa_wait0();
        }
        __syncthreads();

        // prefetch epilogue operands (accv bf16, x fp32) into registers
        __nv_bfloat162 pav[3][2][2];
        float2 pxv[3][2][2];
        #pragma unroll
        for (int mi = 0; mi < 3; ++mi) {
            const int rA = pm0 + mi * 16 + g8;
            const size_t oA = (size_t)(nbase + rA) * CC;
            const size_t oB = (size_t)(nbase + rA + 8) * CC;
            #pragma unroll
            for (int ni = 0; ni < 2; ++ni) {
                const int col = c * 64 + pn0 + ni * 8 + 2 * t4;
                pav[mi][ni][0] = *(const __nv_bfloat162*)(g_accv + oA + col);
                pxv[mi][ni][0] = *(const float2*)(x + oA + col);
                pav[mi][ni][1] = *(const __nv_bfloat162*)(g_accv + oB + col);
                pxv[mi][ni][1] = *(const float2*)(x + oB + col);
            }
        }

        const uint32_t* Vb = Vsu + (c & 1) * 6528;
        float acc[3][2][4] = {};
        #pragma unroll
        for (int ks = 0; ks < 12; ++ks) {
            const int kb = ks * 8;
            const uint32_t kbB = ks * 32;
            uint32_t a[3][4], bf[2][2];
            ldsm4(a[0], pBase + pOff[0] + kbB);
            ldsm4(a[1], pBase + pOff[1] + kbB);
            ldsm4(a[2], pBase + pOff[2] + kbB);
            #pragma unroll
            for (int ni = 0; ni < 2; ++ni) {
                const int n = pn0 + ni * 8 + g8;
                bf[ni][0] = Vb[(kb + t4    ) * VCH_STRIDE + n];
                bf[ni][1] = Vb[(kb + t4 + 4) * VCH_STRIDE + n];
            }
            #pragma unroll
            for (int mi = 0; mi < 3; ++mi)
                #pragma unroll
                for (int ni = 0; ni < 2; ++ni)
                    mma_tf32(acc[mi][ni], a[mi], bf[ni]);
        }

        #pragma unroll
        for (int mi = 0; mi < 3; ++mi) {
            const int rA = pm0 + mi * 16 + g8;
            const int rB = rA + 8;
            const float fvA = fv[rA], fhA = fh[rA];
            const float fvB = fv[rB], fhB = fh[rB];
            const size_t oA = (size_t)(nbase + rA) * CC;
            const size_t oB = (size_t)(nbase + rB) * CC;
            #pragma unroll
            for (int ni = 0; ni < 2; ++ni) {
                const int col = c * 64 + pn0 + ni * 8 + 2 * t4;
                float2 avA = __bfloat1622float2(pav[mi][ni][0]);
                float2 avB = __bfloat1622float2(pav[mi][ni][1]);
                float2 o0, o1;
                o0.x = pxv[mi][ni][0].x + gamma * (fvA * avA.x + fhA * acc[mi][ni][0]);
                o0.y = pxv[mi][ni][0].y + gamma * (fvA * avA.y + fhA * acc[mi][ni][1]);
                o1.x = pxv[mi][ni][1].x + gamma * (fvB * avB.x + fhB * acc[mi][ni][2]);
                o1.y = pxv[mi][ni][1].y + gamma * (fvB * avB.y + fhB * acc[mi][ni][3]);
                *(float2*)(out + oA + col) = o0;
                *(float2*)(out + oB + col) = o1;
            }
        }
        __syncthreads();
    }
}

// ---------------- launch ----------------------------------------------------
extern "C" void kernel_launch(void* const* d_in, const int* in_sizes, int n_in,
                              void* d_out, int out_size)
{
    const float* x  = (const float*)d_in[0];
    const float* Wq = (const float*)d_in[1];
    const float* bq = (const float*)d_in[2];
    const float* Wk = (const float*)d_in[3];
    const float* bk = (const float*)d_in[4];
    const float* Wv = (const float*)d_in[5];
    const float* bv = (const float*)d_in[6];
    const float* gm = (const float*)d_in[7];
    float* out = (float*)d_out;

    cudaFuncSetAttribute(qkv_gemm, cudaFuncAttributeMaxDynamicSharedMemorySize, QKV_SMEM_BYTES);
    cudaFuncSetAttribute(col_attn, cudaFuncAttributeMaxDynamicSharedMemorySize, SMEM_BYTES);
    cudaFuncSetAttribute(row_attn, cudaFuncAttributeMaxDynamicSharedMemorySize, SMEM_BYTES);

    cvt_w<<<1280, 256>>>(Wq, Wk, Wv);
    dim3 gA(5, 576);
    qkv_gemm<<<gA, 256, QKV_SMEM_BYTES>>>(x, bq, bk, bv);
    col_attn<<<768, 256, SMEM_BYTES>>>();
    row_attn<<<768, 256, SMEM_BYTES>>>(x, gm, out);
}

// round 13
// speedup vs baseline: 1.1038x; 1.0310x over previous
#include <cuda_runtime.h>
#include <cuda_bf16.h>
#include <cstdint>

#define HH 96
#define WW 96
#define CC 512
#define DD 64
#define N_POS 73728   // 8*96*96

// ---------------- scratch (device globals: no allocations allowed) ----------
__device__ float g_q[N_POS * DD];
__device__ float g_k[N_POS * DD];
__device__ float g_v[N_POS * CC];
__device__ __nv_bfloat16 g_accv[N_POS * CC];   // bf16 column-pass accumulator
__device__ float g_mv[N_POS];
__device__ float g_lv[N_POS];
__device__ float g_wt[640 * 512];   // W pre-converted to tf32 (rna), n-major [n][k]

// ---------------- helpers ----------------------------------------------------
__device__ __forceinline__ uint32_t f2tf32(float f) {
    uint32_t u;
    asm("cvt.rna.tf32.f32 %0, %1;" : "=r"(u) : "f"(f));
    return u;
}

__device__ __forceinline__ void mma_tf32(float* c, const uint32_t* a, const uint32_t* b) {
    asm volatile(
        "mma.sync.aligned.m16n8k8.row.col.f32.tf32.tf32.f32 "
        "{%0,%1,%2,%3}, {%4,%5,%6,%7}, {%8,%9}, {%0,%1,%2,%3};\n"
        : "+f"(c[0]), "+f"(c[1]), "+f"(c[2]), "+f"(c[3])
        : "r"(a[0]), "r"(a[1]), "r"(a[2]), "r"(a[3]),
          "r"(b[0]), "r"(b[1]));
}

__device__ __forceinline__ uint32_t s2u(const void* p) {
    return (uint32_t)__cvta_generic_to_shared(p);
}

__device__ __forceinline__ void ldsm4(uint32_t* r, uint32_t addr) {
    asm volatile("ldmatrix.sync.aligned.m8n8.x4.shared.b16 {%0,%1,%2,%3}, [%4];"
        : "=r"(r[0]), "=r"(r[1]), "=r"(r[2]), "=r"(r[3]) : "r"(addr));
}

__device__ __forceinline__ void ldsm2(uint32_t* r, uint32_t addr) {
    asm volatile("ldmatrix.sync.aligned.m8n8.x2.shared.b16 {%0,%1}, [%2];"
        : "=r"(r[0]), "=r"(r[1]) : "r"(addr));
}

__device__ __forceinline__ void cpa16(uint32_t dst, const void* src) {
    asm volatile("cp.async.cg.shared.global [%0], [%1], 16;"
                 :: "r"(dst), "l"(src) : "memory");
}
__device__ __forceinline__ void cpa_commit() {
    asm volatile("cp.async.commit_group;" ::: "memory");
}
__device__ __forceinline__ void cpa_wait0() {
    asm volatile("cp.async.wait_group 0;" ::: "memory");
}
__device__ __forceinline__ void cpa_wait1() {
    asm volatile("cp.async.wait_group 1;" ::: "memory");
}
__device__ __forceinline__ void cpa_wait2() {
    asm volatile("cp.async.wait_group 2;" ::: "memory");
}
__device__ __forceinline__ void cpa_wait_all() {
    asm volatile("cp.async.wait_all;" ::: "memory");
}

// ---------------- Kernel 0: convert W to tf32, n-major ----------------------
__global__ __launch_bounds__(256) void cvt_w(
    const float* __restrict__ Wq, const float* __restrict__ Wk,
    const float* __restrict__ Wv)
{
    int i = blockIdx.x * 256 + threadIdx.x;      // < 640*512
    int n = i >> 9, k = i & 511;
    float v;
    if (n < 64)       v = Wq[k * 64 + n];
    else if (n < 128) v = Wk[k * 64 + (n - 64)];
    else              v = Wv[k * 512 + (n - 128)];
    g_wt[i] = __uint_as_float(f2tf32(v));
}

// ---------------- Kernel 1: fused QKV projection GEMM (tf32 tensor) ---------
#define QKV_SMEM_BYTES (3 * 9216 * 4)

__global__ __launch_bounds__(256, 2) void qkv_gemm(
    const float* __restrict__ x,
    const float* __restrict__ bq, const float* __restrict__ bk,
    const float* __restrict__ bv)
{
    extern __shared__ uint32_t smQ[];

    const int ct = blockIdx.x;
    const int rowBase = blockIdx.y * 128;
    const int ctBase = ct * 128;

    const int tid  = threadIdx.x;
    const int lane = tid & 31;
    const int warp = tid >> 5;
    const int wm   = warp >> 1;
    const int wn   = warp & 1;
    const int g8   = lane >> 2;
    const int t4   = lane & 3;

    const uint32_t smBase = s2u(smQ);
    uint32_t aOff[2], bOff[4];
    #pragma unroll
    for (int mi = 0; mi < 2; ++mi)
        aOff[mi] = ((wm * 32 + mi * 16 + (lane & 15)) * 36 + 4 * (lane >> 4)) * 4;
    #pragma unroll
    for (int g = 0; g < 4; ++g)
        bOff[g] = (4608 + (wn * 64 + g * 16 + ((lane & 16) >> 1) + (lane & 7)) * 36
                   + 4 * ((lane >> 3) & 1)) * 4;

    float acc[2][8][4] = {};

    auto issue_chunk = [&](int c, int s) {
        const uint32_t aDst = smBase + (s * 9216) * 4;
        const uint32_t bDst = smBase + (s * 9216 + 4608) * 4;
        const int k0 = c * 32;
        #pragma unroll
        for (int i = 0; i < 4; ++i) {
            int idx = tid + i * 256;
            int row = idx >> 3, seg = idx & 7;
            cpa16(aDst + (row * 36 + seg * 4) * 4,
                  x + (size_t)(rowBase + row) * CC + k0 + seg * 4);
        }
        #pragma unroll
        for (int i = 0; i < 4; ++i) {
            int idx = tid + i * 256;
            int row = idx >> 3, seg = idx & 7;
            cpa16(bDst + (row * 36 + seg * 4) * 4,
                  g_wt + (size_t)(ctBase + row) * 512 + k0 + seg * 4);
        }
        cpa_commit();
    };

    issue_chunk(0, 0);
    issue_chunk(1, 1);

    for (int c = 0; c < 16; ++c) {
        const int s = c % 3;
        cpa_wait1();
        __syncthreads();

        if (c + 2 < 16) issue_chunk(c + 2, (c + 2) % 3);

        const uint32_t aStage = smBase + (s * 9216) * 4;
        #pragma unroll
        for (int kk = 0; kk < 4; ++kk) {
            const uint32_t kbB = kk * 32;
            uint32_t a[2][4], bf[4][4];
            ldsm4(a[0], aStage + aOff[0] + kbB);
            ldsm4(a[1], aStage + aOff[1] + kbB);
            ldsm4(bf[0], aStage + bOff[0] + kbB);
            ldsm4(bf[1], aStage + bOff[1] + kbB);
            ldsm4(bf[2], aStage + bOff[2] + kbB);
            ldsm4(bf[3], aStage + bOff[3] + kbB);
            #pragma unroll
            for (int mi = 0; mi < 2; ++mi)
                #pragma unroll
                for (int g = 0; g < 4; ++g) {
                    mma_tf32(acc[mi][g * 2    ], a[mi], bf[g]);
                    mma_tf32(acc[mi][g * 2 + 1], a[mi], bf[g] + 2);
                }
        }
    }

    float* dstBase; const float* biasBase; int ldw;
    if (ct == 0) {
        if (wn == 0) { dstBase = g_q; biasBase = bq; ldw = 64; }
        else         { dstBase = g_k; biasBase = bk; ldw = 64; }
    } else {
        dstBase = g_v + (ct - 1) * 128 + wn * 64;
        biasBase = bv + (ct - 1) * 128 + wn * 64;
        ldw = CC;
    }

    #pragma unroll
    for (int ni = 0; ni < 8; ++ni) {
        const int colL = ni * 8 + 2 * t4;
        const float b0 = biasBase[colL], b1 = biasBase[colL + 1];
        #pragma unroll
        for (int mi = 0; mi < 2; ++mi) {
            const int r0 = rowBase + wm * 32 + mi * 16 + g8;
            float2 o0 = { __uint_as_float(f2tf32(acc[mi][ni][0] + b0)),
                          __uint_as_float(f2tf32(acc[mi][ni][1] + b1)) };
            float2 o1 = { __uint_as_float(f2tf32(acc[mi][ni][2] + b0)),
                          __uint_as_float(f2tf32(acc[mi][ni][3] + b1)) };
            *(float2*)(dstBase + (size_t)r0 * ldw + colL) = o0;
            *(float2*)(dstBase + (size_t)(r0 + 8) * ldw + colL) = o1;
        }
    }
}

// ---------------- shared-memory layout for attention kernels ----------------
// words:
// [0 .. 6528)      Qs (96x68)   -- overlaid by V buf0
// [6528 .. 13056)  Ks (96x68)   -- overlaid by V buf1
// [13056 .. 22656) Ps (96x100)
// [22656 .. 23040) stats: ms, ls, fv, fh
// [23040 .. 26496) accv stage: 96 rows x 36 words (72 bf16, 64 used)
#define QK_STRIDE 68
#define PS_STRIDE 100
#define VCH_STRIDE 68
#define ST_STRIDE 36          // words per stage row (72 bf16)
#define SM_KS   6528
#define SM_PS   13056
#define SM_MS   22656
#define SM_LS   22752
#define SM_FV   22848
#define SM_FH   22944
#define SM_STAGE 23040
#define SMEM_FLOATS 26496
#define SMEM_BYTES  (SMEM_FLOATS * 4)
#define NCHUNK 8   // 8 chunks of 64 channels

// ---------------- Kernel 2: column attention pass (per (b,w)) ---------------
__global__ __launch_bounds__(256, 2) void col_attn()
{
    extern __shared__ float sm[];
    uint32_t* Qs  = (uint32_t*)sm;
    uint32_t* Ks  = (uint32_t*)(sm + SM_KS);
    float*    Ps  = sm + SM_PS;
    uint32_t* Psu = (uint32_t*)Ps;
    uint32_t* Vsu = (uint32_t*)sm;
    __nv_bfloat16* stageB = (__nv_bfloat16*)(sm + SM_STAGE);

    const int tid = threadIdx.x;
    const int lane = tid & 31;
    const int warp = tid >> 5;
    const int g8 = lane >> 2, t4 = lane & 3;
    const int b = blockIdx.x / WW;
    const int w = blockIdx.x % WW;

    const uint32_t qBase = s2u(Qs), kBase = s2u(Ks), pBase = s2u(Psu), vBase = s2u(Vsu);

    for (int idx = tid; idx < HH * 16; idx += 256) {
        int pos = idx >> 4, c4 = (idx & 15) * 4;
        size_t off = (size_t)((b * HH + pos) * WW + w) * DD + c4;
        uint32_t d = (pos * QK_STRIDE + c4) * 4;
        cpa16(qBase + d, g_q + off);
        cpa16(kBase + d, g_k + off);
    }
    cpa_commit();
    cpa_wait_all();
    __syncthreads();

    // ---- scores S = Q @ K^T (tf32 MMA + ldmatrix), warps 2(M) x 4(N) ----
    {
        const int sm0 = (warp & 1) * 48, sn0 = (warp >> 1) * 24;
        uint32_t qOff[3];
        #pragma unroll
        for (int mi = 0; mi < 3; ++mi)
            qOff[mi] = ((sm0 + mi * 16 + (lane & 15)) * QK_STRIDE + 4 * (lane >> 4)) * 4;
        const uint32_t kOff01 = ((sn0 + ((lane & 16) >> 1) + (lane & 7)) * QK_STRIDE
                                 + 4 * ((lane >> 3) & 1)) * 4;
        const uint32_t kOff2  = ((sn0 + 16 + (lane & 7)) * QK_STRIDE
                                 + 4 * ((lane >> 3) & 1)) * 4;

        float acc[3][3][4] = {};
        #pragma unroll
        for (int ks = 0; ks < 8; ++ks) {
            const uint32_t kbB = ks * 32;
            uint32_t a[3][4], b01[4], b2[2];
            ldsm4(a[0], qBase + qOff[0] + kbB);
            ldsm4(a[1], qBase + qOff[1] + kbB);
            ldsm4(a[2], qBase + qOff[2] + kbB);
            ldsm4(b01, kBase + kOff01 + kbB);
            ldsm2(b2,  kBase + kOff2  + kbB);
            #pragma unroll
            for (int mi = 0; mi < 3; ++mi) {
                mma_tf32(acc[mi][0], a[mi], b01);
                mma_tf32(acc[mi][1], a[mi], b01 + 2);
                mma_tf32(acc[mi][2], a[mi], b2);
            }
        }

        #pragma unroll
        for (int mi = 0; mi < 3; ++mi) {
            const int r0 = sm0 + mi * 16 + g8, r1 = r0 + 8;
            #pragma unroll
            for (int ni = 0; ni < 3; ++ni) {
                const int c0 = sn0 + ni * 8 + 2 * t4, c1 = c0 + 1;
                Ps[r0 * PS_STRIDE + c0] = (r0 == c0) ? -1e30f : acc[mi][ni][0];
                Ps[r0 * PS_STRIDE + c1] = (r0 == c1) ? -1e30f : acc[mi][ni][1];
                Ps[r1 * PS_STRIDE + c0] = (r1 == c0) ? -1e30f : acc[mi][ni][2];
                Ps[r1 * PS_STRIDE + c1] = (r1 == c1) ? -1e30f : acc[mi][ni][3];
            }
        }
    }
    __syncthreads();   // Qs/Ks now dead

    // issue V chunk 0
    for (int idx = tid; idx < HH * 16; idx += 256) {
        int gg = idx >> 4, c4 = (idx & 15) * 4;
        cpa16(vBase + (gg * VCH_STRIDE + c4) * 4,
              g_v + (size_t)((b * HH + gg) * WW + w) * CC + c4);
    }
    cpa_commit();

    // ---- softmax ----
    for (int h = warp; h < HH; h += 8) {
        float m = -3.4e38f;
        for (int g = lane; g < HH; g += 32) m = fmaxf(m, Ps[h * PS_STRIDE + g]);
        #pragma unroll
        for (int o = 16; o; o >>= 1) m = fmaxf(m, __shfl_xor_sync(0xffffffffu, m, o));
        float l = 0.f;
        for (int g = lane; g < HH; g += 32) {
            uint32_t u = f2tf32(__expf(Ps[h * PS_STRIDE + g] - m));
            Psu[h * PS_STRIDE + g] = u;
            l += __uint_as_float(u);
        }
        #pragma unroll
        for (int o = 16; o; o >>= 1) l += __shfl_xor_sync(0xffffffffu, l, o);
        if (lane == 0) {
            int n = (b * HH + h) * WW + w;
            g_mv[n] = m;
            g_lv[n] = l;
        }
    }

    // ---- acc_v = P @ V: smem stage + coalesced bf16 store ----
    const int pm0 = (warp & 1) * 48, pn0 = (warp >> 1) * 16;
    uint32_t pOff[3];
    #pragma unroll
    for (int mi = 0; mi < 3; ++mi)
        pOff[mi] = ((pm0 + mi * 16 + (lane & 15)) * PS_STRIDE + 4 * (lane >> 4)) * 4;

    for (int c = 0; c < NCHUNK; ++c) {
        if (c + 1 < NCHUNK) {
            const uint32_t dst = vBase + ((c + 1) & 1) * 6528 * 4;
            for (int idx = tid; idx < HH * 16; idx += 256) {
                int gg = idx >> 4, c4 = (idx & 15) * 4;
                cpa16(dst + (gg * VCH_STRIDE + c4) * 4,
                      g_v + (size_t)((b * HH + gg) * WW + w) * CC + (c + 1) * 64 + c4);
            }
            cpa_commit();
            cpa_wait1();
        } else {
            cpa_wait0();
        }
        __syncthreads();   // V(c) ready; stage free (prev copy done)

        const uint32_t* Vb = Vsu + (c & 1) * 6528;
        float acc[3][2][4] = {};
        #pragma unroll
        for (int ks = 0; ks < 12; ++ks) {
            const int kb = ks * 8;
            const uint32_t kbB = ks * 32;
            uint32_t a[3][4], bf[2][2];
            ldsm4(a[0], pBase + pOff[0] + kbB);
            ldsm4(a[1], pBase + pOff[1] + kbB);
            ldsm4(a[2], pBase + pOff[2] + kbB);
            #pragma unroll
            for (int ni = 0; ni < 2; ++ni) {
                const int n = pn0 + ni * 8 + g8;
                bf[ni][0] = Vb[(kb + t4    ) * VCH_STRIDE + n];
                bf[ni][1] = Vb[(kb + t4 + 4) * VCH_STRIDE + n];
            }
            #pragma unroll
            for (int mi = 0; mi < 3; ++mi)
                #pragma unroll
                for (int ni = 0; ni < 2; ++ni)
                    mma_tf32(acc[mi][ni], a[mi], bf[ni]);
        }

        // fragments -> bf16 stage
        #pragma unroll
        for (int mi = 0; mi < 3; ++mi) {
            const int rA = pm0 + mi * 16 + g8;
            #pragma unroll
            for (int ni = 0; ni < 2; ++ni) {
                const int colL = pn0 + ni * 8 + 2 * t4;
                float2 o0 = { acc[mi][ni][0], acc[mi][ni][1] };
                float2 o1 = { acc[mi][ni][2], acc[mi][ni][3] };
                *(__nv_bfloat162*)(stageB + rA * 72 + colL) = __float22bfloat162_rn(o0);
                *(__nv_bfloat162*)(stageB + (rA + 8) * 72 + colL) = __float22bfloat162_rn(o1);
            }
        }
        __syncthreads();   // stage complete

        // coalesced store: 96 rows x 128B
        for (int t = tid; t < HH * 8; t += 256) {
            int row = t >> 3, seg = t & 7;
            uint4 vv = *(uint4*)(sm + SM_STAGE + row * ST_STRIDE + seg * 4);
            *(uint4*)(g_accv + (size_t)((b * HH + row) * WW + w) * CC + c * 64 + seg * 8) = vv;
        }
    }
}

// ---------------- Kernel 3: row attention pass + combine (per (b,h)) --------
__global__ __launch_bounds__(256, 2) void row_attn(
    const float* __restrict__ x, const float* __restrict__ gammap,
    float* __restrict__ out)
{
    extern __shared__ float sm[];
    uint32_t* Qs  = (uint32_t*)sm;
    uint32_t* Ks  = (uint32_t*)(sm + SM_KS);
    float*    Ps  = sm + SM_PS;
    uint32_t* Psu = (uint32_t*)Ps;
    uint32_t* Vsu = (uint32_t*)sm;
    float* ms = sm + SM_MS;
    float* ls = sm + SM_LS;
    float* fv = sm + SM_FV;
    float* fh = sm + SM_FH;
    __nv_bfloat16* stageB = (__nv_bfloat16*)(sm + SM_STAGE);

    const int tid = threadIdx.x;
    const int lane = tid & 31;
    const int warp = tid >> 5;
    const int g8 = lane >> 2, t4 = lane & 3;
    const int b = blockIdx.x / HH;
    const int h = blockIdx.x % HH;
    const int nbase = (b * HH + h) * WW;

    const uint32_t qBase = s2u(Qs), kBase = s2u(Ks), pBase = s2u(Psu), vBase = s2u(Vsu);
    const uint32_t stBase = s2u(stageB);

    for (int idx = tid; idx < WW * 16; idx += 256) {
        int pos = idx >> 4, c4 = (idx & 15) * 4;
        size_t off = (size_t)(nbase + pos) * DD + c4;
        uint32_t d = (pos * QK_STRIDE + c4) * 4;
        cpa16(qBase + d, g_q + off);
        cpa16(kBase + d, g_k + off);
    }
    if (tid < WW) {
        fv[tid] = g_mv[nbase + tid];
        fh[tid] = g_lv[nbase + tid];
    }
    cpa_commit();
    cpa_wait_all();
    __syncthreads();

    // scores (no mask)
    {
        const int sm0 = (warp & 1) * 48, sn0 = (warp >> 1) * 24;
        uint32_t qOff[3];
        #pragma unroll
        for (int mi = 0; mi < 3; ++mi)
            qOff[mi] = ((sm0 + mi * 16 + (lane & 15)) * QK_STRIDE + 4 * (lane >> 4)) * 4;
        const uint32_t kOff01 = ((sn0 + ((lane & 16) >> 1) + (lane & 7)) * QK_STRIDE
                                 + 4 * ((lane >> 3) & 1)) * 4;
        const uint32_t kOff2  = ((sn0 + 16 + (lane & 7)) * QK_STRIDE
                                 + 4 * ((lane >> 3) & 1)) * 4;

        float acc[3][3][4] = {};
        #pragma unroll
        for (int ks = 0; ks < 8; ++ks) {
            const uint32_t kbB = ks * 32;
            uint32_t a[3][4], b01[4], b2[2];
            ldsm4(a[0], qBase + qOff[0] + kbB);
            ldsm4(a[1], qBase + qOff[1] + kbB);
            ldsm4(a[2], qBase + qOff[2] + kbB);
            ldsm4(b01, kBase + kOff01 + kbB);
            ldsm2(b2,  kBase + kOff2  + kbB);
            #pragma unroll
            for (int mi = 0; mi < 3; ++mi) {
                mma_tf32(acc[mi][0], a[mi], b01);
                mma_tf32(acc[mi][1], a[mi], b01 + 2);
                mma_tf32(acc[mi][2], a[mi], b2);
            }
        }

        #pragma unroll
        for (int mi = 0; mi < 3; ++mi) {
            const int r0 = sm0 + mi * 16 + g8, r1 = r0 + 8;
            #pragma unroll
            for (int ni = 0; ni < 3; ++ni) {
                const int c0 = sn0 + ni * 8 + 2 * t4;
                *(float2*)&Ps[r0 * PS_STRIDE + c0] = *(float2*)&acc[mi][ni][0];
                *(float2*)&Ps[r1 * PS_STRIDE + c0] = *(float2*)&acc[mi][ni][2];
            }
        }
    }
    __syncthreads();   // Qs/Ks dead

    // issue V chunk 0 (G0), accv chunk 0 (G1)
    for (int idx = tid; idx < WW * 16; idx += 256) {
        int u0 = idx >> 4, c4 = (idx & 15) * 4;
        cpa16(vBase + (u0 * VCH_STRIDE + c4) * 4,
              g_v + (size_t)(nbase + u0) * CC + c4);
    }
    cpa_commit();
    for (int t = tid; t < WW * 8; t += 256) {
        int row = t >> 3, seg = t & 7;
        cpa16(stBase + (row * ST_STRIDE + seg * 4) * 4,
              g_accv + (size_t)(nbase + row) * CC + seg * 8);
    }
    cpa_commit();

    // softmax
    for (int wq = warp; wq < WW; wq += 8) {
        float m = -3.4e38f;
        for (int g = lane; g < WW; g += 32) m = fmaxf(m, Ps[wq * PS_STRIDE + g]);
        #pragma unroll
        for (int o = 16; o; o >>= 1) m = fmaxf(m, __shfl_xor_sync(0xffffffffu, m, o));
        float l = 0.f;
        for (int g = lane; g < WW; g += 32) {
            uint32_t u = f2tf32(__expf(Ps[wq * PS_STRIDE + g] - m));
            Psu[wq * PS_STRIDE + g] = u;
            l += __uint_as_float(u);
        }
        #pragma unroll
        for (int o = 16; o; o >>= 1) l += __shfl_xor_sync(0xffffffffu, l, o);
        if (lane == 0) { ms[wq] = m; ls[wq] = l; }
    }
    __syncthreads();

    if (tid < WW) {
        float mh = ms[tid], lh = ls[tid];
        float mv = fv[tid], lv = fh[tid];
        float M  = fmaxf(mh, mv);
        float ev = __expf(mv - M), eh = __expf(mh - M);
        float inv = 1.f / (ev * lv + eh * lh);
        fv[tid] = ev * inv;
        fh[tid] = eh * inv;
    }

    const float gamma = *gammap;
    const int pm0 = (warp & 1) * 48, pn0 = (warp >> 1) * 16;
    uint32_t pOff[3];
    #pragma unroll
    for (int mi = 0; mi < 3; ++mi)
        pOff[mi] = ((pm0 + mi * 16 + (lane & 15)) * PS_STRIDE + 4 * (lane >> 4)) * 4;

    // group bookkeeping: at iter c entry, pending = [V(c), accv(c)]
    for (int c = 0; c < NCHUNK; ++c) {
        if (c + 1 < NCHUNK) {
            const uint32_t dst = vBase + ((c + 1) & 1) * 6528 * 4;
            for (int idx = tid; idx < WW * 16; idx += 256) {
                int u0 = idx >> 4, c4 = (idx & 15) * 4;
                cpa16(dst + (u0 * VCH_STRIDE + c4) * 4,
                      g_v + (size_t)(nbase + u0) * CC + (c + 1) * 64 + c4);
            }
            cpa_commit();
            cpa_wait2();    // V(c) done; [accv(c), V(c+1)] may be pending
        } else {
            cpa_wait1();    // V(7) done; [accv(7)] may be pending
        }
        __syncthreads();

        const uint32_t* Vb = Vsu + (c & 1) * 6528;
        float acc[3][2][4] = {};
        #pragma unroll
        for (int ks = 0; ks < 12; ++ks) {
            const int kb = ks * 8;
            const uint32_t kbB = ks * 32;
            uint32_t a[3][4], bf[2][2];
            ldsm4(a[0], pBase + pOff[0] + kbB);
            ldsm4(a[1], pBase + pOff[1] + kbB);
            ldsm4(a[2], pBase + pOff[2] + kbB);
            #pragma unroll
            for (int ni = 0; ni < 2; ++ni) {
                const int n = pn0 + ni * 8 + g8;
                bf[ni][0] = Vb[(kb + t4    ) * VCH_STRIDE + n];
                bf[ni][1] = Vb[(kb + t4 + 4) * VCH_STRIDE + n];
            }
            #pragma unroll
            for (int mi = 0; mi < 3; ++mi)
                #pragma unroll
                for (int ni = 0; ni < 2; ++ni)
                    mma_tf32(acc[mi][ni], a[mi], bf[ni]);
        }

        if (c + 1 < NCHUNK) cpa_wait1();   // accv(c) done; V(c+1) may be pending
        else                cpa_wait0();
        __syncthreads();

        #pragma unroll
        for (int mi = 0; mi < 3; ++mi) {
            const int rA = pm0 + mi * 16 + g8;
            const int rB = rA + 8;
            const float fvA = fv[rA], fhA = fh[rA];
            const float fvB = fv[rB], fhB = fh[rB];
            const size_t oA = (size_t)(nbase + rA) * CC;
            const size_t oB = (size_t)(nbase + rB) * CC;
            #pragma unroll
            for (int ni = 0; ni < 2; ++ni) {
                const int colL = pn0 + ni * 8 + 2 * t4;
                const int col = c * 64 + colL;
                float2 avA = __bfloat1622float2(*(__nv_bfloat162*)(stageB + rA * 72 + colL));
                float2 avB = __bfloat1622float2(*(__nv_bfloat162*)(stageB + rB * 72 + colL));
                float2 xvA = *(const float2*)(x + oA + col);
                float2 xvB = *(const float2*)(x + oB + col);
                float2 o0, o1;
                o0.x = xvA.x + gamma * (fvA * avA.x + fhA * acc[mi][ni][0]);
                o0.y = xvA.y + gamma * (fvA * avA.y + fhA * acc[mi][ni][1]);
                o1.x = xvB.x + gamma * (fvB * avB.x + fhB * acc[mi][ni][2]);
                o1.y = xvB.y + gamma * (fvB * avB.y + fhB * acc[mi][ni][3]);
                *(float2*)(out + oA + col) = o0;
                *(float2*)(out + oB + col) = o1;
            }
        }
        __syncthreads();   // all threads done reading accv stage

        if (c + 1 < NCHUNK) {
            for (int t = tid; t < WW * 8; t += 256) {
                int row = t >> 3, seg = t & 7;
                cpa16(stBase + (row * ST_STRIDE + seg * 4) * 4,
                      g_accv + (size_t)(nbase + row) * CC + (c + 1) * 64 + seg * 8);
            }
            cpa_commit();
        }
    }
}

// ---------------- launch ----------------------------------------------------
extern "C" void kernel_launch(void* const* d_in, const int* in_sizes, int n_in,
                              void* d_out, int out_size)
{
    const float* x  = (const float*)d_in[0];
    const float* Wq = (const float*)d_in[1];
    const float* bq = (const float*)d_in[2];
    const float* Wk = (const float*)d_in[3];
    const float* bk = (const float*)d_in[4];
    const float* Wv = (const float*)d_in[5];
    const float* bv = (const float*)d_in[6];
    const float* gm = (const float*)d_in[7];
    float* out = (float*)d_out;

    cudaFuncSetAttribute(qkv_gemm, cudaFuncAttributeMaxDynamicSharedMemorySize, QKV_SMEM_BYTES);
    cudaFuncSetAttribute(col_attn, cudaFuncAttributeMaxDynamicSharedMemorySize, SMEM_BYTES);
    cudaFuncSetAttribute(row_attn, cudaFuncAttributeMaxDynamicSharedMemorySize, SMEM_BYTES);

    cvt_w<<<1280, 256>>>(Wq, Wk, Wv);
    dim3 gA(5, 576);
    qkv_gemm<<<gA, 256, QKV_SMEM_BYTES>>>(x, bq, bk, bv);
    col_attn<<<768, 256, SMEM_BYTES>>>();
    row_attn<<<768, 256, SMEM_BYTES>>>(x, gm, out);
}

// round 14
// speedup vs baseline: 1.2491x; 1.1316x over previous
#include <cuda_runtime.h>
#include <cuda_bf16.h>
#include <cuda_fp16.h>
#include <cstdint>

#define HH 96
#define WW 96
#define CC 512
#define DD 64
#define N_POS 73728   // 8*96*96

// ---------------- scratch (device globals: no allocations allowed) ----------
__device__ float g_q[N_POS * DD];
__device__ float g_k[N_POS * DD];
__device__ __half g_vh[N_POS * CC];            // fp16 V (10-bit mantissa == tf32)
__device__ __nv_bfloat16 g_accv[N_POS * CC];   // bf16 column-pass accumulator
__device__ float g_mv[N_POS];
__device__ float g_lv[N_POS];
__device__ float g_wt[640 * 512];   // W pre-converted to tf32 (rna), n-major [n][k]

// ---------------- helpers ----------------------------------------------------
__device__ __forceinline__ uint32_t f2tf32(float f) {
    uint32_t u;
    asm("cvt.rna.tf32.f32 %0, %1;" : "=r"(u) : "f"(f));
    return u;
}

__device__ __forceinline__ void mma_tf32(float* c, const uint32_t* a, const uint32_t* b) {
    asm volatile(
        "mma.sync.aligned.m16n8k8.row.col.f32.tf32.tf32.f32 "
        "{%0,%1,%2,%3}, {%4,%5,%6,%7}, {%8,%9}, {%0,%1,%2,%3};\n"
        : "+f"(c[0]), "+f"(c[1]), "+f"(c[2]), "+f"(c[3])
        : "r"(a[0]), "r"(a[1]), "r"(a[2]), "r"(a[3]),
          "r"(b[0]), "r"(b[1]));
}

__device__ __forceinline__ void mma_f16(float* c, const uint32_t* a, const uint32_t* b) {
    asm volatile(
        "mma.sync.aligned.m16n8k16.row.col.f32.f16.f16.f32 "
        "{%0,%1,%2,%3}, {%4,%5,%6,%7}, {%8,%9}, {%0,%1,%2,%3};\n"
        : "+f"(c[0]), "+f"(c[1]), "+f"(c[2]), "+f"(c[3])
        : "r"(a[0]), "r"(a[1]), "r"(a[2]), "r"(a[3]),
          "r"(b[0]), "r"(b[1]));
}

__device__ __forceinline__ uint32_t s2u(const void* p) {
    return (uint32_t)__cvta_generic_to_shared(p);
}

__device__ __forceinline__ void ldsm4(uint32_t* r, uint32_t addr) {
    asm volatile("ldmatrix.sync.aligned.m8n8.x4.shared.b16 {%0,%1,%2,%3}, [%4];"
        : "=r"(r[0]), "=r"(r[1]), "=r"(r[2]), "=r"(r[3]) : "r"(addr));
}

__device__ __forceinline__ void ldsm4t(uint32_t* r, uint32_t addr) {
    asm volatile("ldmatrix.sync.aligned.m8n8.x4.trans.shared.b16 {%0,%1,%2,%3}, [%4];"
        : "=r"(r[0]), "=r"(r[1]), "=r"(r[2]), "=r"(r[3]) : "r"(addr));
}

__device__ __forceinline__ void ldsm2(uint32_t* r, uint32_t addr) {
    asm volatile("ldmatrix.sync.aligned.m8n8.x2.shared.b16 {%0,%1}, [%2];"
        : "=r"(r[0]), "=r"(r[1]) : "r"(addr));
}

__device__ __forceinline__ void cpa16(uint32_t dst, const void* src) {
    asm volatile("cp.async.cg.shared.global [%0], [%1], 16;"
                 :: "r"(dst), "l"(src) : "memory");
}
__device__ __forceinline__ void cpa_commit() {
    asm volatile("cp.async.commit_group;" ::: "memory");
}
__device__ __forceinline__ void cpa_wait0() {
    asm volatile("cp.async.wait_group 0;" ::: "memory");
}
__device__ __forceinline__ void cpa_wait1() {
    asm volatile("cp.async.wait_group 1;" ::: "memory");
}
__device__ __forceinline__ void cpa_wait2() {
    asm volatile("cp.async.wait_group 2;" ::: "memory");
}
__device__ __forceinline__ void cpa_wait_all() {
    asm volatile("cp.async.wait_all;" ::: "memory");
}

// ---------------- Kernel 0: convert W to tf32, n-major ----------------------
__global__ __launch_bounds__(256) void cvt_w(
    const float* __restrict__ Wq, const float* __restrict__ Wk,
    const float* __restrict__ Wv)
{
    int i = blockIdx.x * 256 + threadIdx.x;      // < 640*512
    int n = i >> 9, k = i & 511;
    float v;
    if (n < 64)       v = Wq[k * 64 + n];
    else if (n < 128) v = Wk[k * 64 + (n - 64)];
    else              v = Wv[k * 512 + (n - 128)];
    g_wt[i] = __uint_as_float(f2tf32(v));
}

// ---------------- Kernel 1: fused QKV projection GEMM (tf32 tensor) ---------
#define QKV_SMEM_BYTES (3 * 9216 * 4)

__global__ __launch_bounds__(256, 2) void qkv_gemm(
    const float* __restrict__ x,
    const float* __restrict__ bq, const float* __restrict__ bk,
    const float* __restrict__ bv)
{
    extern __shared__ uint32_t smQ[];

    const int ct = blockIdx.x;
    const int rowBase = blockIdx.y * 128;
    const int ctBase = ct * 128;

    const int tid  = threadIdx.x;
    const int lane = tid & 31;
    const int warp = tid >> 5;
    const int wm   = warp >> 1;
    const int wn   = warp & 1;
    const int g8   = lane >> 2;
    const int t4   = lane & 3;

    const uint32_t smBase = s2u(smQ);
    uint32_t aOff[2], bOff[4];
    #pragma unroll
    for (int mi = 0; mi < 2; ++mi)
        aOff[mi] = ((wm * 32 + mi * 16 + (lane & 15)) * 36 + 4 * (lane >> 4)) * 4;
    #pragma unroll
    for (int g = 0; g < 4; ++g)
        bOff[g] = (4608 + (wn * 64 + g * 16 + ((lane & 16) >> 1) + (lane & 7)) * 36
                   + 4 * ((lane >> 3) & 1)) * 4;

    float acc[2][8][4] = {};

    auto issue_chunk = [&](int c, int s) {
        const uint32_t aDst = smBase + (s * 9216) * 4;
        const uint32_t bDst = smBase + (s * 9216 + 4608) * 4;
        const int k0 = c * 32;
        #pragma unroll
        for (int i = 0; i < 4; ++i) {
            int idx = tid + i * 256;
            int row = idx >> 3, seg = idx & 7;
            cpa16(aDst + (row * 36 + seg * 4) * 4,
                  x + (size_t)(rowBase + row) * CC + k0 + seg * 4);
        }
        #pragma unroll
        for (int i = 0; i < 4; ++i) {
            int idx = tid + i * 256;
            int row = idx >> 3, seg = idx & 7;
            cpa16(bDst + (row * 36 + seg * 4) * 4,
                  g_wt + (size_t)(ctBase + row) * 512 + k0 + seg * 4);
        }
        cpa_commit();
    };

    issue_chunk(0, 0);
    issue_chunk(1, 1);

    for (int c = 0; c < 16; ++c) {
        const int s = c % 3;
        cpa_wait1();
        __syncthreads();

        if (c + 2 < 16) issue_chunk(c + 2, (c + 2) % 3);

        const uint32_t aStage = smBase + (s * 9216) * 4;
        #pragma unroll
        for (int kk = 0; kk < 4; ++kk) {
            const uint32_t kbB = kk * 32;
            uint32_t a[2][4], bf[4][4];
            ldsm4(a[0], aStage + aOff[0] + kbB);
            ldsm4(a[1], aStage + aOff[1] + kbB);
            ldsm4(bf[0], aStage + bOff[0] + kbB);
            ldsm4(bf[1], aStage + bOff[1] + kbB);
            ldsm4(bf[2], aStage + bOff[2] + kbB);
            ldsm4(bf[3], aStage + bOff[3] + kbB);
            #pragma unroll
            for (int mi = 0; mi < 2; ++mi)
                #pragma unroll
                for (int g = 0; g < 4; ++g) {
                    mma_tf32(acc[mi][g * 2    ], a[mi], bf[g]);
                    mma_tf32(acc[mi][g * 2 + 1], a[mi], bf[g] + 2);
                }
        }
    }

    if (ct == 0) {
        float* dstBase; const float* biasBase;
        if (wn == 0) { dstBase = g_q; biasBase = bq; }
        else         { dstBase = g_k; biasBase = bk; }
        #pragma unroll
        for (int ni = 0; ni < 8; ++ni) {
            const int colL = ni * 8 + 2 * t4;
            const float b0 = biasBase[colL], b1 = biasBase[colL + 1];
            #pragma unroll
            for (int mi = 0; mi < 2; ++mi) {
                const int r0 = rowBase + wm * 32 + mi * 16 + g8;
                float2 o0 = { __uint_as_float(f2tf32(acc[mi][ni][0] + b0)),
                              __uint_as_float(f2tf32(acc[mi][ni][1] + b1)) };
                float2 o1 = { __uint_as_float(f2tf32(acc[mi][ni][2] + b0)),
                              __uint_as_float(f2tf32(acc[mi][ni][3] + b1)) };
                *(float2*)(dstBase + (size_t)r0 * 64 + colL) = o0;
                *(float2*)(dstBase + (size_t)(r0 + 8) * 64 + colL) = o1;
            }
        }
    } else {
        __half* dstBase = g_vh + (ct - 1) * 128 + wn * 64;
        const float* biasBase = bv + (ct - 1) * 128 + wn * 64;
        #pragma unroll
        for (int ni = 0; ni < 8; ++ni) {
            const int colL = ni * 8 + 2 * t4;
            const float b0 = biasBase[colL], b1 = biasBase[colL + 1];
            #pragma unroll
            for (int mi = 0; mi < 2; ++mi) {
                const int r0 = rowBase + wm * 32 + mi * 16 + g8;
                __half2 o0 = __floats2half2_rn(acc[mi][ni][0] + b0, acc[mi][ni][1] + b1);
                __half2 o1 = __floats2half2_rn(acc[mi][ni][2] + b0, acc[mi][ni][3] + b1);
                *(__half2*)(dstBase + (size_t)r0 * CC + colL) = o0;
                *(__half2*)(dstBase + (size_t)(r0 + 8) * CC + colL) = o1;
            }
        }
    }
}

// ---------------- shared-memory layout for attention kernels ----------------
// words:
// [0 .. 13056)     Qs (96x68) | Ks (96x68) during scores; after:
//                  Vh0 @0 (96x72 halfs = 3456 w), Vh1 @3456, Pf16 @6912 (96x104 halfs)
// [13056 .. 22656) Ps (96x100) fp32 scores
// [22656 .. 23040) stats: ms, ls, fv, fh
// [23040 .. 26496) accv stage: 96 x 36 words (72 bf16, 64 used)
#define QK_STRIDE 68
#define PS_STRIDE 100
#define PF_STRIDE 104     // halfs
#define VH_STRIDE 72      // halfs
#define SM_KS   6528
#define SM_VH1  3456
#define SM_PF   6912
#define SM_PS   13056
#define SM_MS   22656
#define SM_LS   22752
#define SM_FV   22848
#define SM_FH   22944
#define SM_STAGE 23040
#define ST_STRIDE 36
#define SMEM_FLOATS 26496
#define SMEM_BYTES  (SMEM_FLOATS * 4)
#define NCHUNK 8   // 8 chunks of 64 channels

// ---------------- Kernel 2: column attention pass (per (b,w)) ---------------
__global__ __launch_bounds__(256, 2) void col_attn()
{
    extern __shared__ float sm[];
    uint32_t* Qs  = (uint32_t*)sm;
    uint32_t* Ks  = (uint32_t*)(sm + SM_KS);
    float*    Ps  = sm + SM_PS;
    __half*   Pf  = (__half*)(sm + SM_PF);
    __nv_bfloat16* stageB = (__nv_bfloat16*)(sm + SM_STAGE);

    const int tid = threadIdx.x;
    const int lane = tid & 31;
    const int warp = tid >> 5;
    const int g8 = lane >> 2, t4 = lane & 3;
    const int b = blockIdx.x / WW;
    const int w = blockIdx.x % WW;

    const uint32_t qBase = s2u(Qs), kBase = s2u(Ks);
    const uint32_t pfBase = s2u(Pf);
    const uint32_t vhBase0 = s2u(sm);
    const uint32_t vhBase1 = s2u(sm + SM_VH1);

    for (int idx = tid; idx < HH * 16; idx += 256) {
        int pos = idx >> 4, c4 = (idx & 15) * 4;
        size_t off = (size_t)((b * HH + pos) * WW + w) * DD + c4;
        uint32_t d = (pos * QK_STRIDE + c4) * 4;
        cpa16(qBase + d, g_q + off);
        cpa16(kBase + d, g_k + off);
    }
    cpa_commit();
    cpa_wait_all();
    __syncthreads();

    // ---- scores S = Q @ K^T (tf32 MMA), warps 2(M) x 4(N) ----
    {
        const int sm0 = (warp & 1) * 48, sn0 = (warp >> 1) * 24;
        uint32_t qOff[3];
        #pragma unroll
        for (int mi = 0; mi < 3; ++mi)
            qOff[mi] = ((sm0 + mi * 16 + (lane & 15)) * QK_STRIDE + 4 * (lane >> 4)) * 4;
        const uint32_t kOff01 = ((sn0 + ((lane & 16) >> 1) + (lane & 7)) * QK_STRIDE
                                 + 4 * ((lane >> 3) & 1)) * 4;
        const uint32_t kOff2  = ((sn0 + 16 + (lane & 7)) * QK_STRIDE
                                 + 4 * ((lane >> 3) & 1)) * 4;

        float acc[3][3][4] = {};
        #pragma unroll
        for (int ks = 0; ks < 8; ++ks) {
            const uint32_t kbB = ks * 32;
            uint32_t a[3][4], b01[4], b2[2];
            ldsm4(a[0], qBase + qOff[0] + kbB);
            ldsm4(a[1], qBase + qOff[1] + kbB);
            ldsm4(a[2], qBase + qOff[2] + kbB);
            ldsm4(b01, kBase + kOff01 + kbB);
            ldsm2(b2,  kBase + kOff2  + kbB);
            #pragma unroll
            for (int mi = 0; mi < 3; ++mi) {
                mma_tf32(acc[mi][0], a[mi], b01);
                mma_tf32(acc[mi][1], a[mi], b01 + 2);
                mma_tf32(acc[mi][2], a[mi], b2);
            }
        }

        #pragma unroll
        for (int mi = 0; mi < 3; ++mi) {
            const int r0 = sm0 + mi * 16 + g8, r1 = r0 + 8;
            #pragma unroll
            for (int ni = 0; ni < 3; ++ni) {
                const int c0 = sn0 + ni * 8 + 2 * t4, c1 = c0 + 1;
                Ps[r0 * PS_STRIDE + c0] = (r0 == c0) ? -1e30f : acc[mi][ni][0];
                Ps[r0 * PS_STRIDE + c1] = (r0 == c1) ? -1e30f : acc[mi][ni][1];
                Ps[r1 * PS_STRIDE + c0] = (r1 == c0) ? -1e30f : acc[mi][ni][2];
                Ps[r1 * PS_STRIDE + c1] = (r1 == c1) ? -1e30f : acc[mi][ni][3];
            }
        }
    }
    __syncthreads();   // Qs/Ks now dead

    // issue V chunk 0 (fp16) into Vh0
    for (int idx = tid; idx < HH * 8; idx += 256) {
        int gg = idx >> 3, seg = idx & 7;
        cpa16(vhBase0 + (gg * VH_STRIDE + seg * 8) * 2,
              g_vh + (size_t)((b * HH + gg) * WW + w) * CC + seg * 8);
    }
    cpa_commit();

    // ---- softmax: stats + write P as fp16 ----
    for (int h = warp; h < HH; h += 8) {
        float m = -3.4e38f;
        for (int g = lane; g < HH; g += 32) m = fmaxf(m, Ps[h * PS_STRIDE + g]);
        #pragma unroll
        for (int o = 16; o; o >>= 1) m = fmaxf(m, __shfl_xor_sync(0xffffffffu, m, o));
        float l = 0.f;
        for (int g = lane; g < HH; g += 32) {
            __half hp = __float2half_rn(__expf(Ps[h * PS_STRIDE + g] - m));
            Pf[h * PF_STRIDE + g] = hp;
            l += __half2float(hp);
        }
        #pragma unroll
        for (int o = 16; o; o >>= 1) l += __shfl_xor_sync(0xffffffffu, l, o);
        if (lane == 0) {
            int n = (b * HH + h) * WW + w;
            g_mv[n] = m;
            g_lv[n] = l;
        }
    }

    // ---- acc_v = P @ V (fp16 MMA m16n8k16), 8 chunks of 64 channels ----
    const int pm0 = (warp & 1) * 48, pn0 = (warp >> 1) * 16;
    uint32_t pOff[3];
    #pragma unroll
    for (int mi = 0; mi < 3; ++mi)
        pOff[mi] = ((pm0 + mi * 16 + (lane & 15)) * PF_STRIDE + ((lane >> 4) << 3)) * 2;
    const uint32_t vOff = (((lane & 15) * VH_STRIDE) + pn0 + ((lane >> 4) << 3)) * 2;

    for (int c = 0; c < NCHUNK; ++c) {
        if (c + 1 < NCHUNK) {
            const uint32_t dst = (((c + 1) & 1) ? vhBase1 : vhBase0);
            for (int idx = tid; idx < HH * 8; idx += 256) {
                int gg = idx >> 3, seg = idx & 7;
                cpa16(dst + (gg * VH_STRIDE + seg * 8) * 2,
                      g_vh + (size_t)((b * HH + gg) * WW + w) * CC + (c + 1) * 64 + seg * 8);
            }
            cpa_commit();
            cpa_wait1();
        } else {
            cpa_wait0();
        }
        __syncthreads();

        const uint32_t vb = ((c & 1) ? vhBase1 : vhBase0);
        float acc[3][2][4] = {};
        #pragma unroll
        for (int ks = 0; ks < 6; ++ks) {
            uint32_t a[3][4], bf[4];
            ldsm4(a[0], pfBase + pOff[0] + ks * 32);
            ldsm4(a[1], pfBase + pOff[1] + ks * 32);
            ldsm4(a[2], pfBase + pOff[2] + ks * 32);
            ldsm4t(bf, vb + vOff + ks * (16 * VH_STRIDE * 2));
            #pragma unroll
            for (int mi = 0; mi < 3; ++mi) {
                mma_f16(acc[mi][0], a[mi], bf);
                mma_f16(acc[mi][1], a[mi], bf + 2);
            }
        }

        // fragments -> bf16 stage
        #pragma unroll
        for (int mi = 0; mi < 3; ++mi) {
            const int rA = pm0 + mi * 16 + g8;
            #pragma unroll
            for (int ni = 0; ni < 2; ++ni) {
                const int colL = pn0 + ni * 8 + 2 * t4;
                float2 o0 = { acc[mi][ni][0], acc[mi][ni][1] };
                float2 o1 = { acc[mi][ni][2], acc[mi][ni][3] };
                *(__nv_bfloat162*)(stageB + rA * 72 + colL) = __float22bfloat162_rn(o0);
                *(__nv_bfloat162*)(stageB + (rA + 8) * 72 + colL) = __float22bfloat162_rn(o1);
            }
        }
        __syncthreads();

        // coalesced store: 96 rows x 128B
        for (int t = tid; t < HH * 8; t += 256) {
            int row = t >> 3, seg = t & 7;
            uint4 vv = *(uint4*)(sm + SM_STAGE + row * ST_STRIDE + seg * 4);
            *(uint4*)(g_accv + (size_t)((b * HH + row) * WW + w) * CC + c * 64 + seg * 8) = vv;
        }
    }
}

// ---------------- Kernel 3: row attention pass + combine (per (b,h)) --------
__global__ __launch_bounds__(256, 2) void row_attn(
    const float* __restrict__ x, const float* __restrict__ gammap,
    float* __restrict__ out)
{
    extern __shared__ float sm[];
    uint32_t* Qs  = (uint32_t*)sm;
    uint32_t* Ks  = (uint32_t*)(sm + SM_KS);
    float*    Ps  = sm + SM_PS;
    __half*   Pf  = (__half*)(sm + SM_PF);
    float* ms = sm + SM_MS;
    float* ls = sm + SM_LS;
    float* fv = sm + SM_FV;
    float* fh = sm + SM_FH;
    __nv_bfloat16* stageB = (__nv_bfloat16*)(sm + SM_STAGE);

    const int tid = threadIdx.x;
    const int lane = tid & 31;
    const int warp = tid >> 5;
    const int g8 = lane >> 2, t4 = lane & 3;
    const int b = blockIdx.x / HH;
    const int h = blockIdx.x % HH;
    const int nbase = (b * HH + h) * WW;

    const uint32_t qBase = s2u(Qs), kBase = s2u(Ks);
    const uint32_t pfBase = s2u(Pf);
    const uint32_t vhBase0 = s2u(sm);
    const uint32_t vhBase1 = s2u(sm + SM_VH1);
    const uint32_t stBase = s2u(stageB);

    for (int idx = tid; idx < WW * 16; idx += 256) {
        int pos = idx >> 4, c4 = (idx & 15) * 4;
        size_t off = (size_t)(nbase + pos) * DD + c4;
        uint32_t d = (pos * QK_STRIDE + c4) * 4;
        cpa16(qBase + d, g_q + off);
        cpa16(kBase + d, g_k + off);
    }
    if (tid < WW) {
        fv[tid] = g_mv[nbase + tid];
        fh[tid] = g_lv[nbase + tid];
    }
    cpa_commit();
    cpa_wait_all();
    __syncthreads();

    // scores (no mask)
    {
        const int sm0 = (warp & 1) * 48, sn0 = (warp >> 1) * 24;
        uint32_t qOff[3];
        #pragma unroll
        for (int mi = 0; mi < 3; ++mi)
            qOff[mi] = ((sm0 + mi * 16 + (lane & 15)) * QK_STRIDE + 4 * (lane >> 4)) * 4;
        const uint32_t kOff01 = ((sn0 + ((lane & 16) >> 1) + (lane & 7)) * QK_STRIDE
                                 + 4 * ((lane >> 3) & 1)) * 4;
        const uint32_t kOff2  = ((sn0 + 16 + (lane & 7)) * QK_STRIDE
                                 + 4 * ((lane >> 3) & 1)) * 4;

        float acc[3][3][4] = {};
        #pragma unroll
        for (int ks = 0; ks < 8; ++ks) {
            const uint32_t kbB = ks * 32;
            uint32_t a[3][4], b01[4], b2[2];
            ldsm4(a[0], qBase + qOff[0] + kbB);
            ldsm4(a[1], qBase + qOff[1] + kbB);
            ldsm4(a[2], qBase + qOff[2] + kbB);
            ldsm4(b01, kBase + kOff01 + kbB);
            ldsm2(b2,  kBase + kOff2  + kbB);
            #pragma unroll
            for (int mi = 0; mi < 3; ++mi) {
                mma_tf32(acc[mi][0], a[mi], b01);
                mma_tf32(acc[mi][1], a[mi], b01 + 2);
                mma_tf32(acc[mi][2], a[mi], b2);
            }
        }

        #pragma unroll
        for (int mi = 0; mi < 3; ++mi) {
            const int r0 = sm0 + mi * 16 + g8, r1 = r0 + 8;
            #pragma unroll
            for (int ni = 0; ni < 3; ++ni) {
                const int c0 = sn0 + ni * 8 + 2 * t4;
                *(float2*)&Ps[r0 * PS_STRIDE + c0] = *(float2*)&acc[mi][ni][0];
                *(float2*)&Ps[r1 * PS_STRIDE + c0] = *(float2*)&acc[mi][ni][2];
            }
        }
    }
    __syncthreads();   // Qs/Ks dead

    // issue V chunk 0 (G0), accv chunk 0 (G1)
    for (int idx = tid; idx < WW * 8; idx += 256) {
        int u0 = idx >> 3, seg = idx & 7;
        cpa16(vhBase0 + (u0 * VH_STRIDE + seg * 8) * 2,
              g_vh + (size_t)(nbase + u0) * CC + seg * 8);
    }
    cpa_commit();
    for (int t = tid; t < WW * 8; t += 256) {
        int row = t >> 3, seg = t & 7;
        cpa16(stBase + (row * ST_STRIDE + seg * 4) * 4,
              g_accv + (size_t)(nbase + row) * CC + seg * 8);
    }
    cpa_commit();

    // softmax -> fp16 P
    for (int wq = warp; wq < WW; wq += 8) {
        float m = -3.4e38f;
        for (int g = lane; g < WW; g += 32) m = fmaxf(m, Ps[wq * PS_STRIDE + g]);
        #pragma unroll
        for (int o = 16; o; o >>= 1) m = fmaxf(m, __shfl_xor_sync(0xffffffffu, m, o));
        float l = 0.f;
        for (int g = lane; g < WW; g += 32) {
            __half hp = __float2half_rn(__expf(Ps[wq * PS_STRIDE + g] - m));
            Pf[wq * PF_STRIDE + g] = hp;
            l += __half2float(hp);
        }
        #pragma unroll
        for (int o = 16; o; o >>= 1) l += __shfl_xor_sync(0xffffffffu, l, o);
        if (lane == 0) { ms[wq] = m; ls[wq] = l; }
    }
    __syncthreads();

    if (tid < WW) {
        float mh = ms[tid], lh = ls[tid];
        float mv = fv[tid], lv = fh[tid];
        float M  = fmaxf(mh, mv);
        float ev = __expf(mv - M), eh = __expf(mh - M);
        float inv = 1.f / (ev * lv + eh * lh);
        fv[tid] = ev * inv;
        fh[tid] = eh * inv;
    }

    const float gamma = *gammap;
    const int pm0 = (warp & 1) * 48, pn0 = (warp >> 1) * 16;
    uint32_t pOff[3];
    #pragma unroll
    for (int mi = 0; mi < 3; ++mi)
        pOff[mi] = ((pm0 + mi * 16 + (lane & 15)) * PF_STRIDE + ((lane >> 4) << 3)) * 2;
    const uint32_t vOff = (((lane & 15) * VH_STRIDE) + pn0 + ((lane >> 4) << 3)) * 2;

    // group bookkeeping: at iter c entry, pending = [V(c), accv(c)]
    for (int c = 0; c < NCHUNK; ++c) {
        if (c + 1 < NCHUNK) {
            const uint32_t dst = (((c + 1) & 1) ? vhBase1 : vhBase0);
            for (int idx = tid; idx < WW * 8; idx += 256) {
                int u0 = idx >> 3, seg = idx & 7;
                cpa16(dst + (u0 * VH_STRIDE + seg * 8) * 2,
                      g_vh + (size_t)(nbase + u0) * CC + (c + 1) * 64 + seg * 8);
            }
            cpa_commit();
            cpa_wait2();    // V(c) done; [accv(c), V(c+1)] may be pending
        } else {
            cpa_wait1();    // V(7) done; [accv(7)] may be pending
        }
        __syncthreads();

        const uint32_t vb = ((c & 1) ? vhBase1 : vhBase0);
        float acc[3][2][4] = {};
        #pragma unroll
        for (int ks = 0; ks < 6; ++ks) {
            uint32_t a[3][4], bf[4];
            ldsm4(a[0], pfBase + pOff[0] + ks * 32);
            ldsm4(a[1], pfBase + pOff[1] + ks * 32);
            ldsm4(a[2], pfBase + pOff[2] + ks * 32);
            ldsm4t(bf, vb + vOff + ks * (16 * VH_STRIDE * 2));
            #pragma unroll
            for (int mi = 0; mi < 3; ++mi) {
                mma_f16(acc[mi][0], a[mi], bf);
                mma_f16(acc[mi][1], a[mi], bf + 2);
            }
        }

        if (c + 1 < NCHUNK) cpa_wait1();   // accv(c) done; V(c+1) may be pending
        else                cpa_wait0();
        __syncthreads();

        #pragma unroll
        for (int mi = 0; mi < 3; ++mi) {
            const int rA = pm0 + mi * 16 + g8;
            const int rB = rA + 8;
            const float fvA = fv[rA], fhA = fh[rA];
            const float fvB = fv[rB], fhB = fh[rB];
            const size_t oA = (size_t)(nbase + rA) * CC;
            const size_t oB = (size_t)(nbase + rB) * CC;
            #pragma unroll
            for (int ni = 0; ni < 2; ++ni) {
                const int colL = pn0 + ni * 8 + 2 * t4;
                const int col = c * 64 + colL;
                float2 avA = __bfloat1622float2(*(__nv_bfloat162*)(stageB + rA * 72 + colL));
                float2 avB = __bfloat1622float2(*(__nv_bfloat162*)(stageB + rB * 72 + colL));
                float2 xvA = *(const float2*)(x + oA + col);
                float2 xvB = *(const float2*)(x + oB + col);
                float2 o0, o1;
                o0.x = xvA.x + gamma * (fvA * avA.x + fhA * acc[mi][ni][0]);
                o0.y = xvA.y + gamma * (fvA * avA.y + fhA * acc[mi][ni][1]);
                o1.x = xvB.x + gamma * (fvB * avB.x + fhB * acc[mi][ni][2]);
                o1.y = xvB.y + gamma * (fvB * avB.y + fhB * acc[mi][ni][3]);
                *(float2*)(out + oA + col) = o0;
                *(float2*)(out + oB + col) = o1;
            }
        }
        __syncthreads();   // all threads done reading accv stage

        if (c + 1 < NCHUNK) {
            for (int t = tid; t < WW * 8; t += 256) {
                int row = t >> 3, seg = t & 7;
                cpa16(stBase + (row * ST_STRIDE + seg * 4) * 4,
                      g_accv + (size_t)(nbase + row) * CC + (c + 1) * 64 + seg * 8);
            }
            cpa_commit();
        }
    }
}

// ---------------- launch ----------------------------------------------------
extern "C" void kernel_launch(void* const* d_in, const int* in_sizes, int n_in,
                              void* d_out, int out_size)
{
    const float* x  = (const float*)d_in[0];
    const float* Wq = (const float*)d_in[1];
    const float* bq = (const float*)d_in[2];
    const float* Wk = (const float*)d_in[3];
    const float* bk = (const float*)d_in[4];
    const float* Wv = (const float*)d_in[5];
    const float* bv = (const float*)d_in[6];
    const float* gm = (const float*)d_in[7];
    float* out = (float*)d_out;

    cudaFuncSetAttribute(qkv_gemm, cudaFuncAttributeMaxDynamicSharedMemorySize, QKV_SMEM_BYTES);
    cudaFuncSetAttribute(col_attn, cudaFuncAttributeMaxDynamicSharedMemorySize, SMEM_BYTES);
    cudaFuncSetAttribute(row_attn, cudaFuncAttributeMaxDynamicSharedMemorySize, SMEM_BYTES);

    cvt_w<<<1280, 256>>>(Wq, Wk, Wv);
    dim3 gA(5, 576);
    qkv_gemm<<<gA, 256, QKV_SMEM_BYTES>>>(x, bq, bk, bv);
    col_attn<<<768, 256, SMEM_BYTES>>>();
    row_attn<<<768, 256, SMEM_BYTES>>>(x, gm, out);
}

// round 15
// speedup vs baseline: 1.2697x; 1.0165x over previous
#include <cuda_runtime.h>
#include <cuda_bf16.h>
#include <cuda_fp16.h>
#include <cstdint>

#define HH 96
#define WW 96
#define CC 512
#define DD 64
#define N_POS 73728   // 8*96*96

// ---------------- scratch (device globals: no allocations allowed) ----------
__device__ __half g_q[N_POS * DD];             // fp16 q (10-bit mantissa == tf32)
__device__ __half g_k[N_POS * DD];             // fp16 k
__device__ __half g_vh[N_POS * CC];            // fp16 V
__device__ __nv_bfloat16 g_accv[N_POS * CC];   // bf16 column-pass accumulator
__device__ float g_mv[N_POS];
__device__ float g_lv[N_POS];
__device__ float g_wt[640 * 512];   // W pre-converted to tf32 (rna), n-major [n][k]

// ---------------- helpers ----------------------------------------------------
__device__ __forceinline__ uint32_t f2tf32(float f) {
    uint32_t u;
    asm("cvt.rna.tf32.f32 %0, %1;" : "=r"(u) : "f"(f));
    return u;
}

__device__ __forceinline__ void mma_tf32(float* c, const uint32_t* a, const uint32_t* b) {
    asm volatile(
        "mma.sync.aligned.m16n8k8.row.col.f32.tf32.tf32.f32 "
        "{%0,%1,%2,%3}, {%4,%5,%6,%7}, {%8,%9}, {%0,%1,%2,%3};\n"
        : "+f"(c[0]), "+f"(c[1]), "+f"(c[2]), "+f"(c[3])
        : "r"(a[0]), "r"(a[1]), "r"(a[2]), "r"(a[3]),
          "r"(b[0]), "r"(b[1]));
}

__device__ __forceinline__ void mma_f16(float* c, const uint32_t* a, const uint32_t* b) {
    asm volatile(
        "mma.sync.aligned.m16n8k16.row.col.f32.f16.f16.f32 "
        "{%0,%1,%2,%3}, {%4,%5,%6,%7}, {%8,%9}, {%0,%1,%2,%3};\n"
        : "+f"(c[0]), "+f"(c[1]), "+f"(c[2]), "+f"(c[3])
        : "r"(a[0]), "r"(a[1]), "r"(a[2]), "r"(a[3]),
          "r"(b[0]), "r"(b[1]));
}

__device__ __forceinline__ uint32_t s2u(const void* p) {
    return (uint32_t)__cvta_generic_to_shared(p);
}

__device__ __forceinline__ void ldsm4(uint32_t* r, uint32_t addr) {
    asm volatile("ldmatrix.sync.aligned.m8n8.x4.shared.b16 {%0,%1,%2,%3}, [%4];"
        : "=r"(r[0]), "=r"(r[1]), "=r"(r[2]), "=r"(r[3]) : "r"(addr));
}

__device__ __forceinline__ void ldsm4t(uint32_t* r, uint32_t addr) {
    asm volatile("ldmatrix.sync.aligned.m8n8.x4.trans.shared.b16 {%0,%1,%2,%3}, [%4];"
        : "=r"(r[0]), "=r"(r[1]), "=r"(r[2]), "=r"(r[3]) : "r"(addr));
}

__device__ __forceinline__ void ldsm2(uint32_t* r, uint32_t addr) {
    asm volatile("ldmatrix.sync.aligned.m8n8.x2.shared.b16 {%0,%1}, [%2];"
        : "=r"(r[0]), "=r"(r[1]) : "r"(addr));
}

__device__ __forceinline__ void cpa16(uint32_t dst, const void* src) {
    asm volatile("cp.async.cg.shared.global [%0], [%1], 16;"
                 :: "r"(dst), "l"(src) : "memory");
}
__device__ __forceinline__ void cpa_commit() {
    asm volatile("cp.async.commit_group;" ::: "memory");
}
__device__ __forceinline__ void cpa_wait0() {
    asm volatile("cp.async.wait_group 0;" ::: "memory");
}
__device__ __forceinline__ void cpa_wait1() {
    asm volatile("cp.async.wait_group 1;" ::: "memory");
}
__device__ __forceinline__ void cpa_wait2() {
    asm volatile("cp.async.wait_group 2;" ::: "memory");
}
__device__ __forceinline__ void cpa_wait_all() {
    asm volatile("cp.async.wait_all;" ::: "memory");
}

// ---------------- Kernel 0: convert W to tf32, n-major ----------------------
__global__ __launch_bounds__(256) void cvt_w(
    const float* __restrict__ Wq, const float* __restrict__ Wk,
    const float* __restrict__ Wv)
{
    int i = blockIdx.x * 256 + threadIdx.x;      // < 640*512
    int n = i >> 9, k = i & 511;
    float v;
    if (n < 64)       v = Wq[k * 64 + n];
    else if (n < 128) v = Wk[k * 64 + (n - 64)];
    else              v = Wv[k * 512 + (n - 128)];
    g_wt[i] = __uint_as_float(f2tf32(v));
}

// ---------------- Kernel 1: fused QKV projection GEMM (tf32 tensor) ---------
#define QKV_SMEM_BYTES (3 * 9216 * 4)

__global__ __launch_bounds__(256, 2) void qkv_gemm(
    const float* __restrict__ x,
    const float* __restrict__ bq, const float* __restrict__ bk,
    const float* __restrict__ bv)
{
    extern __shared__ uint32_t smQ[];

    const int ct = blockIdx.x;
    const int rowBase = blockIdx.y * 128;
    const int ctBase = ct * 128;

    const int tid  = threadIdx.x;
    const int lane = tid & 31;
    const int warp = tid >> 5;
    const int wm   = warp >> 1;
    const int wn   = warp & 1;
    const int g8   = lane >> 2;
    const int t4   = lane & 3;

    const uint32_t smBase = s2u(smQ);
    uint32_t aOff[2], bOff[4];
    #pragma unroll
    for (int mi = 0; mi < 2; ++mi)
        aOff[mi] = ((wm * 32 + mi * 16 + (lane & 15)) * 36 + 4 * (lane >> 4)) * 4;
    #pragma unroll
    for (int g = 0; g < 4; ++g)
        bOff[g] = (4608 + (wn * 64 + g * 16 + ((lane & 16) >> 1) + (lane & 7)) * 36
                   + 4 * ((lane >> 3) & 1)) * 4;

    float acc[2][8][4] = {};

    auto issue_chunk = [&](int c, int s) {
        const uint32_t aDst = smBase + (s * 9216) * 4;
        const uint32_t bDst = smBase + (s * 9216 + 4608) * 4;
        const int k0 = c * 32;
        #pragma unroll
        for (int i = 0; i < 4; ++i) {
            int idx = tid + i * 256;
            int row = idx >> 3, seg = idx & 7;
            cpa16(aDst + (row * 36 + seg * 4) * 4,
                  x + (size_t)(rowBase + row) * CC + k0 + seg * 4);
        }
        #pragma unroll
        for (int i = 0; i < 4; ++i) {
            int idx = tid + i * 256;
            int row = idx >> 3, seg = idx & 7;
            cpa16(bDst + (row * 36 + seg * 4) * 4,
                  g_wt + (size_t)(ctBase + row) * 512 + k0 + seg * 4);
        }
        cpa_commit();
    };

    issue_chunk(0, 0);
    issue_chunk(1, 1);

    for (int c = 0; c < 16; ++c) {
        const int s = c % 3;
        cpa_wait1();
        __syncthreads();

        if (c + 2 < 16) issue_chunk(c + 2, (c + 2) % 3);

        const uint32_t aStage = smBase + (s * 9216) * 4;
        #pragma unroll
        for (int kk = 0; kk < 4; ++kk) {
            const uint32_t kbB = kk * 32;
            uint32_t a[2][4], bf[4][4];
            ldsm4(a[0], aStage + aOff[0] + kbB);
            ldsm4(a[1], aStage + aOff[1] + kbB);
            ldsm4(bf[0], aStage + bOff[0] + kbB);
            ldsm4(bf[1], aStage + bOff[1] + kbB);
            ldsm4(bf[2], aStage + bOff[2] + kbB);
            ldsm4(bf[3], aStage + bOff[3] + kbB);
            #pragma unroll
            for (int mi = 0; mi < 2; ++mi)
                #pragma unroll
                for (int g = 0; g < 4; ++g) {
                    mma_tf32(acc[mi][g * 2    ], a[mi], bf[g]);
                    mma_tf32(acc[mi][g * 2 + 1], a[mi], bf[g] + 2);
                }
        }
    }

    if (ct == 0) {
        __half* dstBase; const float* biasBase;
        if (wn == 0) { dstBase = g_q; biasBase = bq; }
        else         { dstBase = g_k; biasBase = bk; }
        #pragma unroll
        for (int ni = 0; ni < 8; ++ni) {
            const int colL = ni * 8 + 2 * t4;
            const float b0 = biasBase[colL], b1 = biasBase[colL + 1];
            #pragma unroll
            for (int mi = 0; mi < 2; ++mi) {
                const int r0 = rowBase + wm * 32 + mi * 16 + g8;
                __half2 o0 = __floats2half2_rn(acc[mi][ni][0] + b0, acc[mi][ni][1] + b1);
                __half2 o1 = __floats2half2_rn(acc[mi][ni][2] + b0, acc[mi][ni][3] + b1);
                *(__half2*)(dstBase + (size_t)r0 * 64 + colL) = o0;
                *(__half2*)(dstBase + (size_t)(r0 + 8) * 64 + colL) = o1;
            }
        }
    } else {
        __half* dstBase = g_vh + (ct - 1) * 128 + wn * 64;
        const float* biasBase = bv + (ct - 1) * 128 + wn * 64;
        #pragma unroll
        for (int ni = 0; ni < 8; ++ni) {
            const int colL = ni * 8 + 2 * t4;
            const float b0 = biasBase[colL], b1 = biasBase[colL + 1];
            #pragma unroll
            for (int mi = 0; mi < 2; ++mi) {
                const int r0 = rowBase + wm * 32 + mi * 16 + g8;
                __half2 o0 = __floats2half2_rn(acc[mi][ni][0] + b0, acc[mi][ni][1] + b1);
                __half2 o1 = __floats2half2_rn(acc[mi][ni][2] + b0, acc[mi][ni][3] + b1);
                *(__half2*)(dstBase + (size_t)r0 * CC + colL) = o0;
                *(__half2*)(dstBase + (size_t)(r0 + 8) * CC + colL) = o1;
            }
        }
    }
}

// ---------------- shared-memory layout for attention kernels ----------------
// words:
// [0 .. 3456)      Qs (96x72 halfs)  -- overlaid by V buf0 after scores
// [3456 .. 6912)   Ks (96x72 halfs)  -- overlaid by V buf1
// [6912 .. 11904)  Pf16 (96x104 halfs)
// [11904 .. 21504) Ps (96x100 fp32 scores)
// [21504 .. 21888) stats: ms, ls, fv, fh
// [21888 .. 25344) accv stage: 96 x 36 words (72 bf16, 64 used)
#define QKH_STRIDE 72     // halfs
#define PS_STRIDE 100
#define PF_STRIDE 104     // halfs
#define VH_STRIDE 72      // halfs
#define SM_KSH  3456
#define SM_VH1  3456
#define SM_PF   6912
#define SM_PS   11904
#define SM_MS   21504
#define SM_LS   21600
#define SM_FV   21696
#define SM_FH   21792
#define SM_STAGE 21888
#define ST_STRIDE 36
#define SMEM_FLOATS 25344
#define SMEM_BYTES  (SMEM_FLOATS * 4)
#define NCHUNK 8   // 8 chunks of 64 channels

// ---------------- Kernel 2: column attention pass (per (b,w)) ---------------
__global__ __launch_bounds__(256, 2) void col_attn()
{
    extern __shared__ float sm[];
    float*    Ps  = sm + SM_PS;
    __half*   Pf  = (__half*)(sm + SM_PF);
    __nv_bfloat16* stageB = (__nv_bfloat16*)(sm + SM_STAGE);

    const int tid = threadIdx.x;
    const int lane = tid & 31;
    const int warp = tid >> 5;
    const int g8 = lane >> 2, t4 = lane & 3;
    const int b = blockIdx.x / WW;
    const int w = blockIdx.x % WW;

    const uint32_t qBase = s2u(sm);
    const uint32_t kBase = s2u(sm + SM_KSH);
    const uint32_t pfBase = s2u(Pf);
    const uint32_t vhBase0 = qBase;
    const uint32_t vhBase1 = kBase;

    // fill Q,K fp16 (96 rows x 64 halfs each)
    for (int idx = tid; idx < HH * 8; idx += 256) {
        int pos = idx >> 3, seg = idx & 7;
        size_t off = (size_t)((b * HH + pos) * WW + w) * DD + seg * 8;
        uint32_t d = (pos * QKH_STRIDE + seg * 8) * 2;
        cpa16(qBase + d, g_q + off);
        cpa16(kBase + d, g_k + off);
    }
    cpa_commit();
    cpa_wait_all();
    __syncthreads();

    // ---- scores S = Q @ K^T (fp16 MMA m16n8k16), warps 2(M) x 4(N=24) ----
    {
        const int sm0 = (warp & 1) * 48, sn0 = (warp >> 1) * 24;
        uint32_t qOff[3];
        #pragma unroll
        for (int mi = 0; mi < 3; ++mi)
            qOff[mi] = ((sm0 + mi * 16 + (lane & 15)) * QKH_STRIDE + ((lane >> 4) << 3)) * 2;
        const uint32_t kOff01 = ((sn0 + ((lane & 16) >> 1) + (lane & 7)) * QKH_STRIDE
                                 + ((lane >> 3) & 1) * 8) * 2;
        const uint32_t kOff2  = ((sn0 + 16 + (lane & 7)) * QKH_STRIDE
                                 + ((lane >> 3) & 1) * 8) * 2;

        float acc[3][3][4] = {};
        #pragma unroll
        for (int ks = 0; ks < 4; ++ks) {
            const uint32_t kbB = ks * 32;   // 16 halfs
            uint32_t a[3][4], b01[4], b2[2];
            ldsm4(a[0], qBase + qOff[0] + kbB);
            ldsm4(a[1], qBase + qOff[1] + kbB);
            ldsm4(a[2], qBase + qOff[2] + kbB);
            ldsm4(b01, kBase + kOff01 + kbB);
            ldsm2(b2,  kBase + kOff2  + kbB);
            #pragma unroll
            for (int mi = 0; mi < 3; ++mi) {
                mma_f16(acc[mi][0], a[mi], b01);
                mma_f16(acc[mi][1], a[mi], b01 + 2);
                mma_f16(acc[mi][2], a[mi], b2);
            }
        }

        #pragma unroll
        for (int mi = 0; mi < 3; ++mi) {
            const int r0 = sm0 + mi * 16 + g8, r1 = r0 + 8;
            #pragma unroll
            for (int ni = 0; ni < 3; ++ni) {
                const int c0 = sn0 + ni * 8 + 2 * t4, c1 = c0 + 1;
                Ps[r0 * PS_STRIDE + c0] = (r0 == c0) ? -1e30f : acc[mi][ni][0];
                Ps[r0 * PS_STRIDE + c1] = (r0 == c1) ? -1e30f : acc[mi][ni][1];
                Ps[r1 * PS_STRIDE + c0] = (r1 == c0) ? -1e30f : acc[mi][ni][2];
                Ps[r1 * PS_STRIDE + c1] = (r1 == c1) ? -1e30f : acc[mi][ni][3];
            }
        }
    }
    __syncthreads();   // Qs/Ks now dead

    // issue V chunk 0 (fp16) into Vh0
    for (int idx = tid; idx < HH * 8; idx += 256) {
        int gg = idx >> 3, seg = idx & 7;
        cpa16(vhBase0 + (gg * VH_STRIDE + seg * 8) * 2,
              g_vh + (size_t)((b * HH + gg) * WW + w) * CC + seg * 8);
    }
    cpa_commit();

    // ---- softmax: stats + write P as fp16 ----
    for (int h = warp; h < HH; h += 8) {
        float m = -3.4e38f;
        for (int g = lane; g < HH; g += 32) m = fmaxf(m, Ps[h * PS_STRIDE + g]);
        #pragma unroll
        for (int o = 16; o; o >>= 1) m = fmaxf(m, __shfl_xor_sync(0xffffffffu, m, o));
        float l = 0.f;
        for (int g = lane; g < HH; g += 32) {
            __half hp = __float2half_rn(__expf(Ps[h * PS_STRIDE + g] - m));
            Pf[h * PF_STRIDE + g] = hp;
            l += __half2float(hp);
        }
        #pragma unroll
        for (int o = 16; o; o >>= 1) l += __shfl_xor_sync(0xffffffffu, l, o);
        if (lane == 0) {
            int n = (b * HH + h) * WW + w;
            g_mv[n] = m;
            g_lv[n] = l;
        }
    }

    // ---- acc_v = P @ V (fp16 MMA), 8 chunks of 64 channels ----
    const int pm0 = (warp & 1) * 48, pn0 = (warp >> 1) * 16;
    uint32_t pOff[3];
    #pragma unroll
    for (int mi = 0; mi < 3; ++mi)
        pOff[mi] = ((pm0 + mi * 16 + (lane & 15)) * PF_STRIDE + ((lane >> 4) << 3)) * 2;
    const uint32_t vOff = (((lane & 15) * VH_STRIDE) + pn0 + ((lane >> 4) << 3)) * 2;

    for (int c = 0; c < NCHUNK; ++c) {
        if (c + 1 < NCHUNK) {
            const uint32_t dst = (((c + 1) & 1) ? vhBase1 : vhBase0);
            for (int idx = tid; idx < HH * 8; idx += 256) {
                int gg = idx >> 3, seg = idx & 7;
                cpa16(dst + (gg * VH_STRIDE + seg * 8) * 2,
                      g_vh + (size_t)((b * HH + gg) * WW + w) * CC + (c + 1) * 64 + seg * 8);
            }
            cpa_commit();
            cpa_wait1();
        } else {
            cpa_wait0();
        }
        __syncthreads();

        const uint32_t vb = ((c & 1) ? vhBase1 : vhBase0);
        float acc[3][2][4] = {};
        #pragma unroll
        for (int ks = 0; ks < 6; ++ks) {
            uint32_t a[3][4], bf[4];
            ldsm4(a[0], pfBase + pOff[0] + ks * 32);
            ldsm4(a[1], pfBase + pOff[1] + ks * 32);
            ldsm4(a[2], pfBase + pOff[2] + ks * 32);
            ldsm4t(bf, vb + vOff + ks * (16 * VH_STRIDE * 2));
            #pragma unroll
            for (int mi = 0; mi < 3; ++mi) {
                mma_f16(acc[mi][0], a[mi], bf);
                mma_f16(acc[mi][1], a[mi], bf + 2);
            }
        }

        // fragments -> bf16 stage
        #pragma unroll
        for (int mi = 0; mi < 3; ++mi) {
            const int rA = pm0 + mi * 16 + g8;
            #pragma unroll
            for (int ni = 0; ni < 2; ++ni) {
                const int colL = pn0 + ni * 8 + 2 * t4;
                float2 o0 = { acc[mi][ni][0], acc[mi][ni][1] };
                float2 o1 = { acc[mi][ni][2], acc[mi][ni][3] };
                *(__nv_bfloat162*)(stageB + rA * 72 + colL) = __float22bfloat162_rn(o0);
                *(__nv_bfloat162*)(stageB + (rA + 8) * 72 + colL) = __float22bfloat162_rn(o1);
            }
        }
        __syncthreads();

        // coalesced store: 96 rows x 128B
        for (int t = tid; t < HH * 8; t += 256) {
            int row = t >> 3, seg = t & 7;
            uint4 vv = *(uint4*)(sm + SM_STAGE + row * ST_STRIDE + seg * 4);
            *(uint4*)(g_accv + (size_t)((b * HH + row) * WW + w) * CC + c * 64 + seg * 8) = vv;
        }
    }
}

// ---------------- Kernel 3: row attention pass + combine (per (b,h)) --------
__global__ __launch_bounds__(256, 2) void row_attn(
    const float* __restrict__ x, const float* __restrict__ gammap,
    float* __restrict__ out)
{
    extern __shared__ float sm[];
    float*    Ps  = sm + SM_PS;
    __half*   Pf  = (__half*)(sm + SM_PF);
    float* ms = sm + SM_MS;
    float* ls = sm + SM_LS;
    float* fv = sm + SM_FV;
    float* fh = sm + SM_FH;
    __nv_bfloat16* stageB = (__nv_bfloat16*)(sm + SM_STAGE);

    const int tid = threadIdx.x;
    const int lane = tid & 31;
    const int warp = tid >> 5;
    const int g8 = lane >> 2, t4 = lane & 3;
    const int b = blockIdx.x / HH;
    const int h = blockIdx.x % HH;
    const int nbase = (b * HH + h) * WW;

    const uint32_t qBase = s2u(sm);
    const uint32_t kBase = s2u(sm + SM_KSH);
    const uint32_t pfBase = s2u(Pf);
    const uint32_t vhBase0 = qBase;
    const uint32_t vhBase1 = kBase;
    const uint32_t stBase = s2u(stageB);

    for (int idx = tid; idx < WW * 8; idx += 256) {
        int pos = idx >> 3, seg = idx & 7;
        size_t off = (size_t)(nbase + pos) * DD + seg * 8;
        uint32_t d = (pos * QKH_STRIDE + seg * 8) * 2;
        cpa16(qBase + d, g_q + off);
        cpa16(kBase + d, g_k + off);
    }
    if (tid < WW) {
        fv[tid] = g_mv[nbase + tid];
        fh[tid] = g_lv[nbase + tid];
    }
    cpa_commit();
    cpa_wait_all();
    __syncthreads();

    // scores (no mask), fp16 MMA
    {
        const int sm0 = (warp & 1) * 48, sn0 = (warp >> 1) * 24;
        uint32_t qOff[3];
        #pragma unroll
        for (int mi = 0; mi < 3; ++mi)
            qOff[mi] = ((sm0 + mi * 16 + (lane & 15)) * QKH_STRIDE + ((lane >> 4) << 3)) * 2;
        const uint32_t kOff01 = ((sn0 + ((lane & 16) >> 1) + (lane & 7)) * QKH_STRIDE
                                 + ((lane >> 3) & 1) * 8) * 2;
        const uint32_t kOff2  = ((sn0 + 16 + (lane & 7)) * QKH_STRIDE
                                 + ((lane >> 3) & 1) * 8) * 2;

        float acc[3][3][4] = {};
        #pragma unroll
        for (int ks = 0; ks < 4; ++ks) {
            const uint32_t kbB = ks * 32;
            uint32_t a[3][4], b01[4], b2[2];
            ldsm4(a[0], qBase + qOff[0] + kbB);
            ldsm4(a[1], qBase + qOff[1] + kbB);
            ldsm4(a[2], qBase + qOff[2] + kbB);
            ldsm4(b01, kBase + kOff01 + kbB);
            ldsm2(b2,  kBase + kOff2  + kbB);
            #pragma unroll
            for (int mi = 0; mi < 3; ++mi) {
                mma_f16(acc[mi][0], a[mi], b01);
                mma_f16(acc[mi][1], a[mi], b01 + 2);
                mma_f16(acc[mi][2], a[mi], b2);
            }
        }

        #pragma unroll
        for (int mi = 0; mi < 3; ++mi) {
            const int r0 = sm0 + mi * 16 + g8, r1 = r0 + 8;
            #pragma unroll
            for (int ni = 0; ni < 3; ++ni) {
                const int c0 = sn0 + ni * 8 + 2 * t4;
                *(float2*)&Ps[r0 * PS_STRIDE + c0] = *(float2*)&acc[mi][ni][0];
                *(float2*)&Ps[r1 * PS_STRIDE + c0] = *(float2*)&acc[mi][ni][2];
            }
        }
    }
    __syncthreads();   // Qs/Ks dead

    // issue V chunk 0 (G0), accv chunk 0 (G1)
    for (int idx = tid; idx < WW * 8; idx += 256) {
        int u0 = idx >> 3, seg = idx & 7;
        cpa16(vhBase0 + (u0 * VH_STRIDE + seg * 8) * 2,
              g_vh + (size_t)(nbase + u0) * CC + seg * 8);
    }
    cpa_commit();
    for (int t = tid; t < WW * 8; t += 256) {
        int row = t >> 3, seg = t & 7;
        cpa16(stBase + (row * ST_STRIDE + seg * 4) * 4,
              g_accv + (size_t)(nbase + row) * CC + seg * 8);
    }
    cpa_commit();

    // softmax -> fp16 P
    for (int wq = warp; wq < WW; wq += 8) {
        float m = -3.4e38f;
        for (int g = lane; g < WW; g += 32) m = fmaxf(m, Ps[wq * PS_STRIDE + g]);
        #pragma unroll
        for (int o = 16; o; o >>= 1) m = fmaxf(m, __shfl_xor_sync(0xffffffffu, m, o));
        float l = 0.f;
        for (int g = lane; g < WW; g += 32) {
            __half hp = __float2half_rn(__expf(Ps[wq * PS_STRIDE + g] - m));
            Pf[wq * PF_STRIDE + g] = hp;
            l += __half2float(hp);
        }
        #pragma unroll
        for (int o = 16; o; o >>= 1) l += __shfl_xor_sync(0xffffffffu, l, o);
        if (lane == 0) { ms[wq] = m; ls[wq] = l; }
    }
    __syncthreads();

    if (tid < WW) {
        float mh = ms[tid], lh = ls[tid];
        float mv = fv[tid], lv = fh[tid];
        float M  = fmaxf(mh, mv);
        float ev = __expf(mv - M), eh = __expf(mh - M);
        float inv = 1.f / (ev * lv + eh * lh);
        fv[tid] = ev * inv;
        fh[tid] = eh * inv;
    }

    const float gamma = *gammap;
    const int pm0 = (warp & 1) * 48, pn0 = (warp >> 1) * 16;
    uint32_t pOff[3];
    #pragma unroll
    for (int mi = 0; mi < 3; ++mi)
        pOff[mi] = ((pm0 + mi * 16 + (lane & 15)) * PF_STRIDE + ((lane >> 4) << 3)) * 2;
    const uint32_t vOff = (((lane & 15) * VH_STRIDE) + pn0 + ((lane >> 4) << 3)) * 2;

    // group bookkeeping: at iter c entry, pending = [V(c), accv(c)]
    for (int c = 0; c < NCHUNK; ++c) {
        if (c + 1 < NCHUNK) {
            const uint32_t dst = (((c + 1) & 1) ? vhBase1 : vhBase0);
            for (int idx = tid; idx < WW * 8; idx += 256) {
                int u0 = idx >> 3, seg = idx & 7;
                cpa16(dst + (u0 * VH_STRIDE + seg * 8) * 2,
                      g_vh + (size_t)(nbase + u0) * CC + (c + 1) * 64 + seg * 8);
            }
            cpa_commit();
            cpa_wait2();    // V(c) done; [accv(c), V(c+1)] may be pending
        } else {
            cpa_wait1();    // V(7) done; [accv(7)] may be pending
        }
        __syncthreads();

        const uint32_t vb = ((c & 1) ? vhBase1 : vhBase0);
        float acc[3][2][4] = {};
        #pragma unroll
        for (int ks = 0; ks < 6; ++ks) {
            uint32_t a[3][4], bf[4];
            ldsm4(a[0], pfBase + pOff[0] + ks * 32);
            ldsm4(a[1], pfBase + pOff[1] + ks * 32);
            ldsm4(a[2], pfBase + pOff[2] + ks * 32);
            ldsm4t(bf, vb + vOff + ks * (16 * VH_STRIDE * 2));
            #pragma unroll
            for (int mi = 0; mi < 3; ++mi) {
                mma_f16(acc[mi][0], a[mi], bf);
                mma_f16(acc[mi][1], a[mi], bf + 2);
            }
        }

        if (c + 1 < NCHUNK) cpa_wait1();   // accv(c) done; V(c+1) may be pending
        else                cpa_wait0();
        __syncthreads();

        #pragma unroll
        for (int mi = 0; mi < 3; ++mi) {
            const int rA = pm0 + mi * 16 + g8;
            const int rB = rA + 8;
            const float fvA = fv[rA], fhA = fh[rA];
            const float fvB = fv[rB], fhB = fh[rB];
            const size_t oA = (size_t)(nbase + rA) * CC;
            const size_t oB = (size_t)(nbase + rB) * CC;
            #pragma unroll
            for (int ni = 0; ni < 2; ++ni) {
                const int colL = pn0 + ni * 8 + 2 * t4;
                const int col = c * 64 + colL;
                float2 avA = __bfloat1622float2(*(__nv_bfloat162*)(stageB + rA * 72 + colL));
                float2 avB = __bfloat1622float2(*(__nv_bfloat162*)(stageB + rB * 72 + colL));
                float2 xvA = *(const float2*)(x + oA + col);
                float2 xvB = *(const float2*)(x + oB + col);
                float2 o0, o1;
                o0.x = xvA.x + gamma * (fvA * avA.x + fhA * acc[mi][ni][0]);
                o0.y = xvA.y + gamma * (fvA * avA.y + fhA * acc[mi][ni][1]);
                o1.x = xvB.x + gamma * (fvB * avB.x + fhB * acc[mi][ni][2]);
                o1.y = xvB.y + gamma * (fvB * avB.y + fhB * acc[mi][ni][3]);
                *(float2*)(out + oA + col) = o0;
                *(float2*)(out + oB + col) = o1;
            }
        }
        __syncthreads();   // all threads done reading accv stage

        if (c + 1 < NCHUNK) {
            for (int t = tid; t < WW * 8; t += 256) {
                int row = t >> 3, seg = t & 7;
                cpa16(stBase + (row * ST_STRIDE + seg * 4) * 4,
                      g_accv + (size_t)(nbase + row) * CC + (c + 1) * 64 + seg * 8);
            }
            cpa_commit();
        }
    }
}

// ---------------- launch ----------------------------------------------------
extern "C" void kernel_launch(void* const* d_in, const int* in_sizes, int n_in,
                              void* d_out, int out_size)
{
    const float* x  = (const float*)d_in[0];
    const float* Wq = (const float*)d_in[1];
    const float* bq = (const float*)d_in[2];
    const float* Wk = (const float*)d_in[3];
    const float* bk = (const float*)d_in[4];
    const float* Wv = (const float*)d_in[5];
    const float* bv = (const float*)d_in[6];
    const float* gm = (const float*)d_in[7];
    float* out = (float*)d_out;

    cudaFuncSetAttribute(qkv_gemm, cudaFuncAttributeMaxDynamicSharedMemorySize, QKV_SMEM_BYTES);
    cudaFuncSetAttribute(col_attn, cudaFuncAttributeMaxDynamicSharedMemorySize, SMEM_BYTES);
    cudaFuncSetAttribute(row_attn, cudaFuncAttributeMaxDynamicSharedMemorySize, SMEM_BYTES);

    cvt_w<<<1280, 256>>>(Wq, Wk, Wv);
    dim3 gA(5, 576);
    qkv_gemm<<<gA, 256, QKV_SMEM_BYTES>>>(x, bq, bk, bv);
    col_attn<<<768, 256, SMEM_BYTES>>>();
    row_attn<<<768, 256, SMEM_BYTES>>>(x, gm, out);
}

// round 16
// speedup vs baseline: 1.5745x; 1.2401x over previous
#include <cuda_runtime.h>
#include <cuda_bf16.h>
#include <cuda_fp16.h>
#include <cstdint>

#define HH 96
#define WW 96
#define CC 512
#define DD 64
#define N_POS 73728   // 8*96*96

// ---------------- scratch (device globals: no allocations allowed) ----------
__device__ __half g_xh[N_POS * CC];            // fp16 x (rne; same grid as tf32)
__device__ __half g_q[N_POS * DD];             // fp16 q
__device__ __half g_k[N_POS * DD];             // fp16 k
__device__ __half g_vh[N_POS * CC];            // fp16 V
__device__ __nv_bfloat16 g_accv[N_POS * CC];   // bf16 column-pass accumulator
__device__ float g_mv[N_POS];
__device__ float g_lv[N_POS];
__device__ __half g_wth[640 * 512];            // W fp16, n-major [n][k]

// ---------------- helpers ----------------------------------------------------
__device__ __forceinline__ void mma_f16(float* c, const uint32_t* a, const uint32_t* b) {
    asm volatile(
        "mma.sync.aligned.m16n8k16.row.col.f32.f16.f16.f32 "
        "{%0,%1,%2,%3}, {%4,%5,%6,%7}, {%8,%9}, {%0,%1,%2,%3};\n"
        : "+f"(c[0]), "+f"(c[1]), "+f"(c[2]), "+f"(c[3])
        : "r"(a[0]), "r"(a[1]), "r"(a[2]), "r"(a[3]),
          "r"(b[0]), "r"(b[1]));
}

__device__ __forceinline__ uint32_t s2u(const void* p) {
    return (uint32_t)__cvta_generic_to_shared(p);
}

__device__ __forceinline__ void ldsm4(uint32_t* r, uint32_t addr) {
    asm volatile("ldmatrix.sync.aligned.m8n8.x4.shared.b16 {%0,%1,%2,%3}, [%4];"
        : "=r"(r[0]), "=r"(r[1]), "=r"(r[2]), "=r"(r[3]) : "r"(addr));
}

__device__ __forceinline__ void ldsm4t(uint32_t* r, uint32_t addr) {
    asm volatile("ldmatrix.sync.aligned.m8n8.x4.trans.shared.b16 {%0,%1,%2,%3}, [%4];"
        : "=r"(r[0]), "=r"(r[1]), "=r"(r[2]), "=r"(r[3]) : "r"(addr));
}

__device__ __forceinline__ void ldsm2(uint32_t* r, uint32_t addr) {
    asm volatile("ldmatrix.sync.aligned.m8n8.x2.shared.b16 {%0,%1}, [%2];"
        : "=r"(r[0]), "=r"(r[1]) : "r"(addr));
}

__device__ __forceinline__ void cpa16(uint32_t dst, const void* src) {
    asm volatile("cp.async.cg.shared.global [%0], [%1], 16;"
                 :: "r"(dst), "l"(src) : "memory");
}
__device__ __forceinline__ void cpa_commit() {
    asm volatile("cp.async.commit_group;" ::: "memory");
}
__device__ __forceinline__ void cpa_wait0() {
    asm volatile("cp.async.wait_group 0;" ::: "memory");
}
__device__ __forceinline__ void cpa_wait1() {
    asm volatile("cp.async.wait_group 1;" ::: "memory");
}
__device__ __forceinline__ void cpa_wait2() {
    asm volatile("cp.async.wait_group 2;" ::: "memory");
}
__device__ __forceinline__ void cpa_wait_all() {
    asm volatile("cp.async.wait_all;" ::: "memory");
}

// ---------------- Kernel 0a: convert x to fp16 -------------------------------
__global__ __launch_bounds__(256) void cvt_x(const float* __restrict__ x)
{
    size_t i4 = (size_t)blockIdx.x * 256 + threadIdx.x;   // < N_POS*CC/4
    float4 v = *(const float4*)(x + i4 * 4);
    __half2 h0 = __floats2half2_rn(v.x, v.y);
    __half2 h1 = __floats2half2_rn(v.z, v.w);
    *(__half2*)(g_xh + i4 * 4)     = h0;
    *(__half2*)(g_xh + i4 * 4 + 2) = h1;
}

// ---------------- Kernel 0b: convert W to fp16, n-major ----------------------
__global__ __launch_bounds__(256) void cvt_w(
    const float* __restrict__ Wq, const float* __restrict__ Wk,
    const float* __restrict__ Wv)
{
    int i = blockIdx.x * 256 + threadIdx.x;      // < 640*512
    int n = i >> 9, k = i & 511;
    float v;
    if (n < 64)       v = Wq[k * 64 + n];
    else if (n < 128) v = Wk[k * 64 + (n - 64)];
    else              v = Wv[k * 512 + (n - 128)];
    g_wth[i] = __float2half_rn(v);
}

// ---------------- Kernel 1: fused QKV projection GEMM (fp16 tensor) ---------
// Grid: (5, 576). ct 0 -> q|k, ct 1..4 -> v cols. 128x128 tile, K-chunk 32,
// 3-stage async pipeline. Stage: A [128][40] halfs @0, B [128][40] halfs @10240B.
#define QKV_SMEM_BYTES (3 * 20480)

__global__ __launch_bounds__(256, 2) void qkv_gemm(
    const float* __restrict__ bq, const float* __restrict__ bk,
    const float* __restrict__ bv)
{
    extern __shared__ uint32_t smQ[];

    const int ct = blockIdx.x;
    const int rowBase = blockIdx.y * 128;
    const int ctBase = ct * 128;

    const int tid  = threadIdx.x;
    const int lane = tid & 31;
    const int warp = tid >> 5;
    const int wm   = warp >> 1;
    const int wn   = warp & 1;
    const int g8   = lane >> 2;
    const int t4   = lane & 3;

    const uint32_t smBase = s2u(smQ);
    uint32_t aOff[2], bOff[4];
    #pragma unroll
    for (int mi = 0; mi < 2; ++mi)
        aOff[mi] = ((wm * 32 + mi * 16 + (lane & 15)) * 40 + ((lane >> 4) << 3)) * 2;
    #pragma unroll
    for (int g = 0; g < 4; ++g)
        bOff[g] = 10240 + ((wn * 64 + g * 16 + ((lane & 16) >> 1) + (lane & 7)) * 40
                   + ((lane >> 3) & 1) * 8) * 2;

    float acc[2][8][4] = {};

    auto issue_chunk = [&](int c, int s) {
        const uint32_t aDst = smBase + s * 20480;
        const uint32_t bDst = aDst + 10240;
        const int k0 = c * 32;
        #pragma unroll
        for (int i = 0; i < 2; ++i) {
            int idx = tid + i * 256;           // 0..511
            int row = idx >> 2, seg = idx & 3; // 4 segs of 8 halfs
            cpa16(aDst + (row * 40 + seg * 8) * 2,
                  g_xh + (size_t)(rowBase + row) * CC + k0 + seg * 8);
        }
        #pragma unroll
        for (int i = 0; i < 2; ++i) {
            int idx = tid + i * 256;
            int row = idx >> 2, seg = idx & 3;
            cpa16(bDst + (row * 40 + seg * 8) * 2,
                  g_wth + (size_t)(ctBase + row) * 512 + k0 + seg * 8);
        }
        cpa_commit();
    };

    issue_chunk(0, 0);
    issue_chunk(1, 1);

    for (int c = 0; c < 16; ++c) {
        const int s = c % 3;
        cpa_wait1();
        __syncthreads();

        if (c + 2 < 16) issue_chunk(c + 2, (c + 2) % 3);

        const uint32_t stg = smBase + s * 20480;
        #pragma unroll
        for (int ks = 0; ks < 2; ++ks) {
            const uint32_t kbB = ks * 32;    // 16 halfs
            uint32_t a[2][4], bf[4][4];
            ldsm4(a[0], stg + aOff[0] + kbB);
            ldsm4(a[1], stg + aOff[1] + kbB);
            ldsm4(bf[0], stg + bOff[0] + kbB);
            ldsm4(bf[1], stg + bOff[1] + kbB);
            ldsm4(bf[2], stg + bOff[2] + kbB);
            ldsm4(bf[3], stg + bOff[3] + kbB);
            #pragma unroll
            for (int mi = 0; mi < 2; ++mi)
                #pragma unroll
                for (int g = 0; g < 4; ++g) {
                    mma_f16(acc[mi][g * 2    ], a[mi], bf[g]);
                    mma_f16(acc[mi][g * 2 + 1], a[mi], bf[g] + 2);
                }
        }
    }

    if (ct == 0) {
        __half* dstBase; const float* biasBase;
        if (wn == 0) { dstBase = g_q; biasBase = bq; }
        else         { dstBase = g_k; biasBase = bk; }
        #pragma unroll
        for (int ni = 0; ni < 8; ++ni) {
            const int colL = ni * 8 + 2 * t4;
            const float b0 = biasBase[colL], b1 = biasBase[colL + 1];
            #pragma unroll
            for (int mi = 0; mi < 2; ++mi) {
                const int r0 = rowBase + wm * 32 + mi * 16 + g8;
                __half2 o0 = __floats2half2_rn(acc[mi][ni][0] + b0, acc[mi][ni][1] + b1);
                __half2 o1 = __floats2half2_rn(acc[mi][ni][2] + b0, acc[mi][ni][3] + b1);
                *(__half2*)(dstBase + (size_t)r0 * 64 + colL) = o0;
                *(__half2*)(dstBase + (size_t)(r0 + 8) * 64 + colL) = o1;
            }
        }
    } else {
        __half* dstBase = g_vh + (ct - 1) * 128 + wn * 64;
        const float* biasBase = bv + (ct - 1) * 128 + wn * 64;
        #pragma unroll
        for (int ni = 0; ni < 8; ++ni) {
            const int colL = ni * 8 + 2 * t4;
            const float b0 = biasBase[colL], b1 = biasBase[colL + 1];
            #pragma unroll
            for (int mi = 0; mi < 2; ++mi) {
                const int r0 = rowBase + wm * 32 + mi * 16 + g8;
                __half2 o0 = __floats2half2_rn(acc[mi][ni][0] + b0, acc[mi][ni][1] + b1);
                __half2 o1 = __floats2half2_rn(acc[mi][ni][2] + b0, acc[mi][ni][3] + b1);
                *(__half2*)(dstBase + (size_t)r0 * CC + colL) = o0;
                *(__half2*)(dstBase + (size_t)(r0 + 8) * CC + colL) = o1;
            }
        }
    }
}

// ---------------- shared-memory layout for attention kernels ----------------
// words:
// [0 .. 3456)      Qs (96x72 halfs)  -- overlaid by V buf0 after scores
// [3456 .. 6912)   Ks (96x72 halfs)  -- overlaid by V buf1
// [6912 .. 11904)  Pf16 (96x104 halfs)
// [11904 .. 21504) Ps (96x100 fp32 scores)
// [21504 .. 21888) stats: ms, ls, fv, fh
// [21888 .. 25344) accv stage: 96 x 36 words (72 bf16, 64 used)
#define QKH_STRIDE 72     // halfs
#define PS_STRIDE 100
#define PF_STRIDE 104     // halfs
#define VH_STRIDE 72      // halfs
#define SM_KSH  3456
#define SM_VH1  3456
#define SM_PF   6912
#define SM_PS   11904
#define SM_MS   21504
#define SM_LS   21600
#define SM_FV   21696
#define SM_FH   21792
#define SM_STAGE 21888
#define ST_STRIDE 36
#define SMEM_FLOATS 25344
#define SMEM_BYTES  (SMEM_FLOATS * 4)
#define NCHUNK 8   // 8 chunks of 64 channels

// ---------------- Kernel 2: column attention pass (per (b,w)) ---------------
__global__ __launch_bounds__(256, 2) void col_attn()
{
    extern __shared__ float sm[];
    float*    Ps  = sm + SM_PS;
    __half*   Pf  = (__half*)(sm + SM_PF);
    __nv_bfloat16* stageB = (__nv_bfloat16*)(sm + SM_STAGE);

    const int tid = threadIdx.x;
    const int lane = tid & 31;
    const int warp = tid >> 5;
    const int g8 = lane >> 2, t4 = lane & 3;
    const int b = blockIdx.x / WW;
    const int w = blockIdx.x % WW;

    const uint32_t qBase = s2u(sm);
    const uint32_t kBase = s2u(sm + SM_KSH);
    const uint32_t pfBase = s2u(Pf);
    const uint32_t vhBase0 = qBase;
    const uint32_t vhBase1 = kBase;

    // fill Q,K fp16 (96 rows x 64 halfs each)
    for (int idx = tid; idx < HH * 8; idx += 256) {
        int pos = idx >> 3, seg = idx & 7;
        size_t off = (size_t)((b * HH + pos) * WW + w) * DD + seg * 8;
        uint32_t d = (pos * QKH_STRIDE + seg * 8) * 2;
        cpa16(qBase + d, g_q + off);
        cpa16(kBase + d, g_k + off);
    }
    cpa_commit();
    cpa_wait_all();
    __syncthreads();

    // ---- scores S = Q @ K^T (fp16 MMA m16n8k16), warps 2(M) x 4(N=24) ----
    {
        const int sm0 = (warp & 1) * 48, sn0 = (warp >> 1) * 24;
        uint32_t qOff[3];
        #pragma unroll
        for (int mi = 0; mi < 3; ++mi)
            qOff[mi] = ((sm0 + mi * 16 + (lane & 15)) * QKH_STRIDE + ((lane >> 4) << 3)) * 2;
        const uint32_t kOff01 = ((sn0 + ((lane & 16) >> 1) + (lane & 7)) * QKH_STRIDE
                                 + ((lane >> 3) & 1) * 8) * 2;
        const uint32_t kOff2  = ((sn0 + 16 + (lane & 7)) * QKH_STRIDE
                                 + ((lane >> 3) & 1) * 8) * 2;

        float acc[3][3][4] = {};
        #pragma unroll
        for (int ks = 0; ks < 4; ++ks) {
            const uint32_t kbB = ks * 32;   // 16 halfs
            uint32_t a[3][4], b01[4], b2[2];
            ldsm4(a[0], qBase + qOff[0] + kbB);
            ldsm4(a[1], qBase + qOff[1] + kbB);
            ldsm4(a[2], qBase + qOff[2] + kbB);
            ldsm4(b01, kBase + kOff01 + kbB);
            ldsm2(b2,  kBase + kOff2  + kbB);
            #pragma unroll
            for (int mi = 0; mi < 3; ++mi) {
                mma_f16(acc[mi][0], a[mi], b01);
                mma_f16(acc[mi][1], a[mi], b01 + 2);
                mma_f16(acc[mi][2], a[mi], b2);
            }
        }

        #pragma unroll
        for (int mi = 0; mi < 3; ++mi) {
            const int r0 = sm0 + mi * 16 + g8, r1 = r0 + 8;
            #pragma unroll
            for (int ni = 0; ni < 3; ++ni) {
                const int c0 = sn0 + ni * 8 + 2 * t4, c1 = c0 + 1;
                Ps[r0 * PS_STRIDE + c0] = (r0 == c0) ? -1e30f : acc[mi][ni][0];
                Ps[r0 * PS_STRIDE + c1] = (r0 == c1) ? -1e30f : acc[mi][ni][1];
                Ps[r1 * PS_STRIDE + c0] = (r1 == c0) ? -1e30f : acc[mi][ni][2];
                Ps[r1 * PS_STRIDE + c1] = (r1 == c1) ? -1e30f : acc[mi][ni][3];
            }
        }
    }
    __syncthreads();   // Qs/Ks now dead

    // issue V chunk 0 (fp16) into Vh0
    for (int idx = tid; idx < HH * 8; idx += 256) {
        int gg = idx >> 3, seg = idx & 7;
        cpa16(vhBase0 + (gg * VH_STRIDE + seg * 8) * 2,
              g_vh + (size_t)((b * HH + gg) * WW + w) * CC + seg * 8);
    }
    cpa_commit();

    // ---- softmax: stats + write P as fp16 ----
    for (int h = warp; h < HH; h += 8) {
        float m = -3.4e38f;
        for (int g = lane; g < HH; g += 32) m = fmaxf(m, Ps[h * PS_STRIDE + g]);
        #pragma unroll
        for (int o = 16; o; o >>= 1) m = fmaxf(m, __shfl_xor_sync(0xffffffffu, m, o));
        float l = 0.f;
        for (int g = lane; g < HH; g += 32) {
            __half hp = __float2half_rn(__expf(Ps[h * PS_STRIDE + g] - m));
            Pf[h * PF_STRIDE + g] = hp;
            l += __half2float(hp);
        }
        #pragma unroll
        for (int o = 16; o; o >>= 1) l += __shfl_xor_sync(0xffffffffu, l, o);
        if (lane == 0) {
            int n = (b * HH + h) * WW + w;
            g_mv[n] = m;
            g_lv[n] = l;
        }
    }

    // ---- acc_v = P @ V (fp16 MMA), 8 chunks of 64 channels ----
    const int pm0 = (warp & 1) * 48, pn0 = (warp >> 1) * 16;
    uint32_t pOff[3];
    #pragma unroll
    for (int mi = 0; mi < 3; ++mi)
        pOff[mi] = ((pm0 + mi * 16 + (lane & 15)) * PF_STRIDE + ((lane >> 4) << 3)) * 2;
    const uint32_t vOff = (((lane & 15) * VH_STRIDE) + pn0 + ((lane >> 4) << 3)) * 2;

    for (int c = 0; c < NCHUNK; ++c) {
        if (c + 1 < NCHUNK) {
            const uint32_t dst = (((c + 1) & 1) ? vhBase1 : vhBase0);
            for (int idx = tid; idx < HH * 8; idx += 256) {
                int gg = idx >> 3, seg = idx & 7;
                cpa16(dst + (gg * VH_STRIDE + seg * 8) * 2,
                      g_vh + (size_t)((b * HH + gg) * WW + w) * CC + (c + 1) * 64 + seg * 8);
            }
            cpa_commit();
            cpa_wait1();
        } else {
            cpa_wait0();
        }
        __syncthreads();

        const uint32_t vb = ((c & 1) ? vhBase1 : vhBase0);
        float acc[3][2][4] = {};
        #pragma unroll
        for (int ks = 0; ks < 6; ++ks) {
            uint32_t a[3][4], bf[4];
            ldsm4(a[0], pfBase + pOff[0] + ks * 32);
            ldsm4(a[1], pfBase + pOff[1] + ks * 32);
            ldsm4(a[2], pfBase + pOff[2] + ks * 32);
            ldsm4t(bf, vb + vOff + ks * (16 * VH_STRIDE * 2));
            #pragma unroll
            for (int mi = 0; mi < 3; ++mi) {
                mma_f16(acc[mi][0], a[mi], bf);
                mma_f16(acc[mi][1], a[mi], bf + 2);
            }
        }

        // fragments -> bf16 stage
        #pragma unroll
        for (int mi = 0; mi < 3; ++mi) {
            const int rA = pm0 + mi * 16 + g8;
            #pragma unroll
            for (int ni = 0; ni < 2; ++ni) {
                const int colL = pn0 + ni * 8 + 2 * t4;
                float2 o0 = { acc[mi][ni][0], acc[mi][ni][1] };
                float2 o1 = { acc[mi][ni][2], acc[mi][ni][3] };
                *(__nv_bfloat162*)(stageB + rA * 72 + colL) = __float22bfloat162_rn(o0);
                *(__nv_bfloat162*)(stageB + (rA + 8) * 72 + colL) = __float22bfloat162_rn(o1);
            }
        }
        __syncthreads();

        // coalesced store: 96 rows x 128B
        for (int t = tid; t < HH * 8; t += 256) {
            int row = t >> 3, seg = t & 7;
            uint4 vv = *(uint4*)(sm + SM_STAGE + row * ST_STRIDE + seg * 4);
            *(uint4*)(g_accv + (size_t)((b * HH + row) * WW + w) * CC + c * 64 + seg * 8) = vv;
        }
    }
}

// ---------------- Kernel 3: row attention pass + combine (per (b,h)) --------
__global__ __launch_bounds__(256, 2) void row_attn(
    const float* __restrict__ x, const float* __restrict__ gammap,
    float* __restrict__ out)
{
    extern __shared__ float sm[];
    float*    Ps  = sm + SM_PS;
    __half*   Pf  = (__half*)(sm + SM_PF);
    float* ms = sm + SM_MS;
    float* ls = sm + SM_LS;
    float* fv = sm + SM_FV;
    float* fh = sm + SM_FH;
    __nv_bfloat16* stageB = (__nv_bfloat16*)(sm + SM_STAGE);

    const int tid = threadIdx.x;
    const int lane = tid & 31;
    const int warp = tid >> 5;
    const int g8 = lane >> 2, t4 = lane & 3;
    const int b = blockIdx.x / HH;
    const int h = blockIdx.x % HH;
    const int nbase = (b * HH + h) * WW;

    const uint32_t qBase = s2u(sm);
    const uint32_t kBase = s2u(sm + SM_KSH);
    const uint32_t pfBase = s2u(Pf);
    const uint32_t vhBase0 = qBase;
    const uint32_t vhBase1 = kBase;
    const uint32_t stBase = s2u(stageB);

    for (int idx = tid; idx < WW * 8; idx += 256) {
        int pos = idx >> 3, seg = idx & 7;
        size_t off = (size_t)(nbase + pos) * DD + seg * 8;
        uint32_t d = (pos * QKH_STRIDE + seg * 8) * 2;
        cpa16(qBase + d, g_q + off);
        cpa16(kBase + d, g_k + off);
    }
    if (tid < WW) {
        fv[tid] = g_mv[nbase + tid];
        fh[tid] = g_lv[nbase + tid];
    }
    cpa_commit();
    cpa_wait_all();
    __syncthreads();

    // scores (no mask), fp16 MMA
    {
        const int sm0 = (warp & 1) * 48, sn0 = (warp >> 1) * 24;
        uint32_t qOff[3];
        #pragma unroll
        for (int mi = 0; mi < 3; ++mi)
            qOff[mi] = ((sm0 + mi * 16 + (lane & 15)) * QKH_STRIDE + ((lane >> 4) << 3)) * 2;
        const uint32_t kOff01 = ((sn0 + ((lane & 16) >> 1) + (lane & 7)) * QKH_STRIDE
                                 + ((lane >> 3) & 1) * 8) * 2;
        const uint32_t kOff2  = ((sn0 + 16 + (lane & 7)) * QKH_STRIDE
                                 + ((lane >> 3) & 1) * 8) * 2;

        float acc[3][3][4] = {};
        #pragma unroll
        for (int ks = 0; ks < 4; ++ks) {
            const uint32_t kbB = ks * 32;
            uint32_t a[3][4], b01[4], b2[2];
            ldsm4(a[0], qBase + qOff[0] + kbB);
            ldsm4(a[1], qBase + qOff[1] + kbB);
            ldsm4(a[2], qBase + qOff[2] + kbB);
            ldsm4(b01, kBase + kOff01 + kbB);
            ldsm2(b2,  kBase + kOff2  + kbB);
            #pragma unroll
            for (int mi = 0; mi < 3; ++mi) {
                mma_f16(acc[mi][0], a[mi], b01);
                mma_f16(acc[mi][1], a[mi], b01 + 2);
                mma_f16(acc[mi][2], a[mi], b2);
            }
        }

        #pragma unroll
        for (int mi = 0; mi < 3; ++mi) {
            const int r0 = sm0 + mi * 16 + g8, r1 = r0 + 8;
            #pragma unroll
            for (int ni = 0; ni < 3; ++ni) {
                const int c0 = sn0 + ni * 8 + 2 * t4;
                *(float2*)&Ps[r0 * PS_STRIDE + c0] = *(float2*)&acc[mi][ni][0];
                *(float2*)&Ps[r1 * PS_STRIDE + c0] = *(float2*)&acc[mi][ni][2];
            }
        }
    }
    __syncthreads();   // Qs/Ks dead

    // issue V chunk 0 (G0), accv chunk 0 (G1)
    for (int idx = tid; idx < WW * 8; idx += 256) {
        int u0 = idx >> 3, seg = idx & 7;
        cpa16(vhBase0 + (u0 * VH_STRIDE + seg * 8) * 2,
              g_vh + (size_t)(nbase + u0) * CC + seg * 8);
    }
    cpa_commit();
    for (int t = tid; t < WW * 8; t += 256) {
        int row = t >> 3, seg = t & 7;
        cpa16(stBase + (row * ST_STRIDE + seg * 4) * 4,
              g_accv + (size_t)(nbase + row) * CC + seg * 8);
    }
    cpa_commit();

    // softmax -> fp16 P
    for (int wq = warp; wq < WW; wq += 8) {
        float m = -3.4e38f;
        for (int g = lane; g < WW; g += 32) m = fmaxf(m, Ps[wq * PS_STRIDE + g]);
        #pragma unroll
        for (int o = 16; o; o >>= 1) m = fmaxf(m, __shfl_xor_sync(0xffffffffu, m, o));
        float l = 0.f;
        for (int g = lane; g < WW; g += 32) {
            __half hp = __float2half_rn(__expf(Ps[wq * PS_STRIDE + g] - m));
            Pf[wq * PF_STRIDE + g] = hp;
            l += __half2float(hp);
        }
        #pragma unroll
        for (int o = 16; o; o >>= 1) l += __shfl_xor_sync(0xffffffffu, l, o);
        if (lane == 0) { ms[wq] = m; ls[wq] = l; }
    }
    __syncthreads();

    if (tid < WW) {
        float mh = ms[tid], lh = ls[tid];
        float mv = fv[tid], lv = fh[tid];
        float M  = fmaxf(mh, mv);
        float ev = __expf(mv - M), eh = __expf(mh - M);
        float inv = 1.f / (ev * lv + eh * lh);
        fv[tid] = ev * inv;
        fh[tid] = eh * inv;
    }

    const float gamma = *gammap;
    const int pm0 = (warp & 1) * 48, pn0 = (warp >> 1) * 16;
    uint32_t pOff[3];
    #pragma unroll
    for (int mi = 0; mi < 3; ++mi)
        pOff[mi] = ((pm0 + mi * 16 + (lane & 15)) * PF_STRIDE + ((lane >> 4) << 3)) * 2;
    const uint32_t vOff = (((lane & 15) * VH_STRIDE) + pn0 + ((lane >> 4) << 3)) * 2;

    // group bookkeeping: at iter c entry, pending = [V(c), accv(c)]
    for (int c = 0; c < NCHUNK; ++c) {
        if (c + 1 < NCHUNK) {
            const uint32_t dst = (((c + 1) & 1) ? vhBase1 : vhBase0);
            for (int idx = tid; idx < WW * 8; idx += 256) {
                int u0 = idx >> 3, seg = idx & 7;
                cpa16(dst + (u0 * VH_STRIDE + seg * 8) * 2,
                      g_vh + (size_t)(nbase + u0) * CC + (c + 1) * 64 + seg * 8);
            }
            cpa_commit();
            cpa_wait2();    // V(c) done; [accv(c), V(c+1)] may be pending
        } else {
            cpa_wait1();    // V(7) done; [accv(7)] may be pending
        }
        __syncthreads();

        const uint32_t vb = ((c & 1) ? vhBase1 : vhBase0);
        float acc[3][2][4] = {};
        #pragma unroll
        for (int ks = 0; ks < 6; ++ks) {
            uint32_t a[3][4], bf[4];
            ldsm4(a[0], pfBase + pOff[0] + ks * 32);
            ldsm4(a[1], pfBase + pOff[1] + ks * 32);
            ldsm4(a[2], pfBase + pOff[2] + ks * 32);
            ldsm4t(bf, vb + vOff + ks * (16 * VH_STRIDE * 2));
            #pragma unroll
            for (int mi = 0; mi < 3; ++mi) {
                mma_f16(acc[mi][0], a[mi], bf);
                mma_f16(acc[mi][1], a[mi], bf + 2);
            }
        }

        if (c + 1 < NCHUNK) cpa_wait1();   // accv(c) done; V(c+1) may be pending
        else                cpa_wait0();
        __syncthreads();

        #pragma unroll
        for (int mi = 0; mi < 3; ++mi) {
            const int rA = pm0 + mi * 16 + g8;
            const int rB = rA + 8;
            const float fvA = fv[rA], fhA = fh[rA];
            const float fvB = fv[rB], fhB = fh[rB];
            const size_t oA = (size_t)(nbase + rA) * CC;
            const size_t oB = (size_t)(nbase + rB) * CC;
            #pragma unroll
            for (int ni = 0; ni < 2; ++ni) {
                const int colL = pn0 + ni * 8 + 2 * t4;
                const int col = c * 64 + colL;
                float2 avA = __bfloat1622float2(*(__nv_bfloat162*)(stageB + rA * 72 + colL));
                float2 avB = __bfloat1622float2(*(__nv_bfloat162*)(stageB + rB * 72 + colL));
                float2 xvA = *(const float2*)(x + oA + col);
                float2 xvB = *(const float2*)(x + oB + col);
                float2 o0, o1;
                o0.x = xvA.x + gamma * (fvA * avA.x + fhA * acc[mi][ni][0]);
                o0.y = xvA.y + gamma * (fvA * avA.y + fhA * acc[mi][ni][1]);
                o1.x = xvB.x + gamma * (fvB * avB.x + fhB * acc[mi][ni][2]);
                o1.y = xvB.y + gamma * (fvB * avB.y + fhB * acc[mi][ni][3]);
                *(float2*)(out + oA + col) = o0;
                *(float2*)(out + oB + col) = o1;
            }
        }
        __syncthreads();   // all threads done reading accv stage

        if (c + 1 < NCHUNK) {
            for (int t = tid; t < WW * 8; t += 256) {
                int row = t >> 3, seg = t & 7;
                cpa16(stBase + (row * ST_STRIDE + seg * 4) * 4,
                      g_accv + (size_t)(nbase + row) * CC + (c + 1) * 64 + seg * 8);
            }
            cpa_commit();
        }
    }
}

// ---------------- launch ----------------------------------------------------
extern "C" void kernel_launch(void* const* d_in, const int* in_sizes, int n_in,
                              void* d_out, int out_size)
{
    const float* x  = (const float*)d_in[0];
    const float* Wq = (const float*)d_in[1];
    const float* bq = (const float*)d_in[2];
    const float* Wk = (const float*)d_in[3];
    const float* bk = (const float*)d_in[4];
    const float* Wv = (const float*)d_in[5];
    const float* bv = (const float*)d_in[6];
    const float* gm = (const float*)d_in[7];
    float* out = (float*)d_out;

    cudaFuncSetAttribute(qkv_gemm, cudaFuncAttributeMaxDynamicSharedMemorySize, QKV_SMEM_BYTES);
    cudaFuncSetAttribute(col_attn, cudaFuncAttributeMaxDynamicSharedMemorySize, SMEM_BYTES);
    cudaFuncSetAttribute(row_attn, cudaFuncAttributeMaxDynamicSharedMemorySize, SMEM_BYTES);

    cvt_x<<<36864, 256>>>(x);
    cvt_w<<<1280, 256>>>(Wq, Wk, Wv);
    dim3 gA(5, 576);
    qkv_gemm<<<gA, 256, QKV_SMEM_BYTES>>>(bq, bk, bv);
    col_attn<<<768, 256, SMEM_BYTES>>>();
    row_attn<<<768, 256, SMEM_BYTES>>>(x, gm, out);
}

// round 17
// speedup vs baseline: 1.7486x; 1.1106x over previous
#include <cuda_runtime.h>
#include <cuda_bf16.h>
#include <cuda_fp16.h>
#include <cstdint>

#define HH 96
#define WW 96
#define CC 512
#define DD 64
#define N_POS 73728   // 8*96*96

// ---------------- scratch (device globals: no allocations allowed) ----------
__device__ __half g_xh[N_POS * CC];            // fp16 x (rne)
__device__ __half g_q[N_POS * DD];             // fp16 q
__device__ __half g_k[N_POS * DD];             // fp16 k
__device__ __half g_vh[N_POS * CC];            // fp16 V
__device__ __nv_bfloat16 g_accv[N_POS * CC];   // bf16 column-pass accumulator
__device__ float g_mv[N_POS];
__device__ float g_lv[N_POS];
__device__ __half g_wth[640 * 512];            // W fp16, n-major [n][k]

// ---------------- helpers ----------------------------------------------------
__device__ __forceinline__ void mma_f16(float* c, const uint32_t* a, const uint32_t* b) {
    asm volatile(
        "mma.sync.aligned.m16n8k16.row.col.f32.f16.f16.f32 "
        "{%0,%1,%2,%3}, {%4,%5,%6,%7}, {%8,%9}, {%0,%1,%2,%3};\n"
        : "+f"(c[0]), "+f"(c[1]), "+f"(c[2]), "+f"(c[3])
        : "r"(a[0]), "r"(a[1]), "r"(a[2]), "r"(a[3]),
          "r"(b[0]), "r"(b[1]));
}

__device__ __forceinline__ uint32_t s2u(const void* p) {
    return (uint32_t)__cvta_generic_to_shared(p);
}

__device__ __forceinline__ void ldsm4(uint32_t* r, uint32_t addr) {
    asm volatile("ldmatrix.sync.aligned.m8n8.x4.shared.b16 {%0,%1,%2,%3}, [%4];"
        : "=r"(r[0]), "=r"(r[1]), "=r"(r[2]), "=r"(r[3]) : "r"(addr));
}

__device__ __forceinline__ void ldsm4t(uint32_t* r, uint32_t addr) {
    asm volatile("ldmatrix.sync.aligned.m8n8.x4.trans.shared.b16 {%0,%1,%2,%3}, [%4];"
        : "=r"(r[0]), "=r"(r[1]), "=r"(r[2]), "=r"(r[3]) : "r"(addr));
}

__device__ __forceinline__ void ldsm2(uint32_t* r, uint32_t addr) {
    asm volatile("ldmatrix.sync.aligned.m8n8.x2.shared.b16 {%0,%1}, [%2];"
        : "=r"(r[0]), "=r"(r[1]) : "r"(addr));
}

__device__ __forceinline__ void cpa16(uint32_t dst, const void* src) {
    asm volatile("cp.async.cg.shared.global [%0], [%1], 16;"
                 :: "r"(dst), "l"(src) : "memory");
}
__device__ __forceinline__ void cpa_commit() {
    asm volatile("cp.async.commit_group;" ::: "memory");
}
__device__ __forceinline__ void cpa_wait0() {
    asm volatile("cp.async.wait_group 0;" ::: "memory");
}
__device__ __forceinline__ void cpa_wait1() {
    asm volatile("cp.async.wait_group 1;" ::: "memory");
}
__device__ __forceinline__ void cpa_wait2() {
    asm volatile("cp.async.wait_group 2;" ::: "memory");
}
__device__ __forceinline__ void cpa_wait_all() {
    asm volatile("cp.async.wait_all;" ::: "memory");
}

// ---------------- Kernel 0a: convert x to fp16 -------------------------------
__global__ __launch_bounds__(256) void cvt_x(const float* __restrict__ x)
{
    size_t i4 = (size_t)blockIdx.x * 256 + threadIdx.x;   // < N_POS*CC/4
    float4 v = *(const float4*)(x + i4 * 4);
    __half2 h0 = __floats2half2_rn(v.x, v.y);
    __half2 h1 = __floats2half2_rn(v.z, v.w);
    *(__half2*)(g_xh + i4 * 4)     = h0;
    *(__half2*)(g_xh + i4 * 4 + 2) = h1;
}

// ---------------- Kernel 0b: convert W to fp16, n-major ----------------------
__global__ __launch_bounds__(256) void cvt_w(
    const float* __restrict__ Wq, const float* __restrict__ Wk,
    const float* __restrict__ Wv)
{
    int i = blockIdx.x * 256 + threadIdx.x;      // < 640*512
    int n = i >> 9, k = i & 511;
    float v;
    if (n < 64)       v = Wq[k * 64 + n];
    else if (n < 128) v = Wk[k * 64 + (n - 64)];
    else              v = Wv[k * 512 + (n - 128)];
    g_wth[i] = __float2half_rn(v);
}

// ---------------- Kernel 1: fused QKV projection GEMM (fp16 tensor) ---------
// Grid: (5, 576). ct 0 -> q|k, ct 1..4 -> v cols. 128x128 tile, K-chunk 32,
// 3-stage async pipeline. Epilogue stages output in smem for coalesced stores.
#define QKV_SMEM_BYTES (3 * 20480)

__global__ __launch_bounds__(256, 2) void qkv_gemm(
    const float* __restrict__ bq, const float* __restrict__ bk,
    const float* __restrict__ bv)
{
    extern __shared__ uint32_t smQ[];

    const int ct = blockIdx.x;
    const int rowBase = blockIdx.y * 128;
    const int ctBase = ct * 128;

    const int tid  = threadIdx.x;
    const int lane = tid & 31;
    const int warp = tid >> 5;
    const int wm   = warp >> 1;
    const int wn   = warp & 1;
    const int g8   = lane >> 2;
    const int t4   = lane & 3;

    const uint32_t smBase = s2u(smQ);
    uint32_t aOff[2], bOff[4];
    #pragma unroll
    for (int mi = 0; mi < 2; ++mi)
        aOff[mi] = ((wm * 32 + mi * 16 + (lane & 15)) * 40 + ((lane >> 4) << 3)) * 2;
    #pragma unroll
    for (int g = 0; g < 4; ++g)
        bOff[g] = 10240 + ((wn * 64 + g * 16 + ((lane & 16) >> 1) + (lane & 7)) * 40
                   + ((lane >> 3) & 1) * 8) * 2;

    float acc[2][8][4] = {};

    auto issue_chunk = [&](int c, int s) {
        const uint32_t aDst = smBase + s * 20480;
        const uint32_t bDst = aDst + 10240;
        const int k0 = c * 32;
        #pragma unroll
        for (int i = 0; i < 2; ++i) {
            int idx = tid + i * 256;           // 0..511
            int row = idx >> 2, seg = idx & 3; // 4 segs of 8 halfs
            cpa16(aDst + (row * 40 + seg * 8) * 2,
                  g_xh + (size_t)(rowBase + row) * CC + k0 + seg * 8);
        }
        #pragma unroll
        for (int i = 0; i < 2; ++i) {
            int idx = tid + i * 256;
            int row = idx >> 2, seg = idx & 3;
            cpa16(bDst + (row * 40 + seg * 8) * 2,
                  g_wth + (size_t)(ctBase + row) * 512 + k0 + seg * 8);
        }
        cpa_commit();
    };

    issue_chunk(0, 0);
    issue_chunk(1, 1);

    for (int c = 0; c < 16; ++c) {
        const int s = c % 3;
        cpa_wait1();
        __syncthreads();

        if (c + 2 < 16) issue_chunk(c + 2, (c + 2) % 3);

        const uint32_t stg = smBase + s * 20480;
        #pragma unroll
        for (int ks = 0; ks < 2; ++ks) {
            const uint32_t kbB = ks * 32;    // 16 halfs
            uint32_t a[2][4], bf[4][4];
            ldsm4(a[0], stg + aOff[0] + kbB);
            ldsm4(a[1], stg + aOff[1] + kbB);
            ldsm4(bf[0], stg + bOff[0] + kbB);
            ldsm4(bf[1], stg + bOff[1] + kbB);
            ldsm4(bf[2], stg + bOff[2] + kbB);
            ldsm4(bf[3], stg + bOff[3] + kbB);
            #pragma unroll
            for (int mi = 0; mi < 2; ++mi)
                #pragma unroll
                for (int g = 0; g < 4; ++g) {
                    mma_f16(acc[mi][g * 2    ], a[mi], bf[g]);
                    mma_f16(acc[mi][g * 2 + 1], a[mi], bf[g] + 2);
                }
        }
    }

    // ---- epilogue: bias + fp16, stage in smem, coalesced global sweep ----
    cpa_wait0();
    __syncthreads();          // pipeline smem dead; reuse as output stage
    __half* ostg = (__half*)smQ;   // 128 rows x 128 cols, stride 136 halfs

    const float* biasBase = (ct == 0) ? (wn ? bk : bq)
                                      : bv + (ct - 1) * 128 + wn * 64;
    #pragma unroll
    for (int ni = 0; ni < 8; ++ni) {
        const int colL = ni * 8 + 2 * t4;
        const float b0 = biasBase[colL], b1 = biasBase[colL + 1];
        #pragma unroll
        for (int mi = 0; mi < 2; ++mi) {
            const int r0 = wm * 32 + mi * 16 + g8;
            __half2 o0 = __floats2half2_rn(acc[mi][ni][0] + b0, acc[mi][ni][1] + b1);
            __half2 o1 = __floats2half2_rn(acc[mi][ni][2] + b0, acc[mi][ni][3] + b1);
            *(__half2*)(ostg + r0 * 136 + wn * 64 + colL) = o0;
            *(__half2*)(ostg + (r0 + 8) * 136 + wn * 64 + colL) = o1;
        }
    }
    __syncthreads();

    for (int t = tid; t < 128 * 16; t += 256) {
        int row = t >> 4, seg = t & 15;
        uint4 v = *(uint4*)(ostg + row * 136 + seg * 8);
        if (ct == 0) {
            if (seg < 8) *(uint4*)(g_q + (size_t)(rowBase + row) * 64 + seg * 8) = v;
            else         *(uint4*)(g_k + (size_t)(rowBase + row) * 64 + (seg - 8) * 8) = v;
        } else {
            *(uint4*)(g_vh + (size_t)(rowBase + row) * CC + (ct - 1) * 128 + seg * 8) = v;
        }
    }
}

// ---------------- shared-memory layout for attention kernels ----------------
// words:
// [0 .. 3456)      Qs (96x72 halfs)  -- overlaid by V buf0 after scores
// [3456 .. 6912)   Ks (96x72 halfs)  -- overlaid by V buf1
// [6912 .. 11904)  Pf16 (96x104 halfs)
// [11904 .. 21504) Ps (96x100 fp32 scores)  -- row_attn reuses as xh stage post-softmax
// [21504 .. 21888) stats: ms, ls, fv, fh
// [21888 .. 25344) accv stage: 96 x 36 words (72 bf16, 64 used)
#define QKH_STRIDE 72     // halfs
#define PS_STRIDE 100
#define PF_STRIDE 104     // halfs
#define VH_STRIDE 72      // halfs
#define SM_KSH  3456
#define SM_VH1  3456
#define SM_PF   6912
#define SM_PS   11904
#define SM_MS   21504
#define SM_LS   21600
#define SM_FV   21696
#define SM_FH   21792
#define SM_STAGE 21888
#define ST_STRIDE 36
#define SMEM_FLOATS 25344
#define SMEM_BYTES  (SMEM_FLOATS * 4)
#define NCHUNK 8   // 8 chunks of 64 channels

// ---------------- Kernel 2: column attention pass (per (b,w)) ---------------
__global__ __launch_bounds__(256, 2) void col_attn()
{
    extern __shared__ float sm[];
    float*    Ps  = sm + SM_PS;
    __half*   Pf  = (__half*)(sm + SM_PF);
    __nv_bfloat16* stageB = (__nv_bfloat16*)(sm + SM_STAGE);

    const int tid = threadIdx.x;
    const int lane = tid & 31;
    const int warp = tid >> 5;
    const int g8 = lane >> 2, t4 = lane & 3;
    const int b = blockIdx.x / WW;
    const int w = blockIdx.x % WW;

    const uint32_t qBase = s2u(sm);
    const uint32_t kBase = s2u(sm + SM_KSH);
    const uint32_t pfBase = s2u(Pf);
    const uint32_t vhBase0 = qBase;
    const uint32_t vhBase1 = kBase;

    // fill Q,K fp16 (96 rows x 64 halfs each)
    for (int idx = tid; idx < HH * 8; idx += 256) {
        int pos = idx >> 3, seg = idx & 7;
        size_t off = (size_t)((b * HH + pos) * WW + w) * DD + seg * 8;
        uint32_t d = (pos * QKH_STRIDE + seg * 8) * 2;
        cpa16(qBase + d, g_q + off);
        cpa16(kBase + d, g_k + off);
    }
    cpa_commit();
    cpa_wait_all();
    __syncthreads();

    // ---- scores S = Q @ K^T (fp16 MMA m16n8k16), warps 2(M) x 4(N=24) ----
    {
        const int sm0 = (warp & 1) * 48, sn0 = (warp >> 1) * 24;
        uint32_t qOff[3];
        #pragma unroll
        for (int mi = 0; mi < 3; ++mi)
            qOff[mi] = ((sm0 + mi * 16 + (lane & 15)) * QKH_STRIDE + ((lane >> 4) << 3)) * 2;
        const uint32_t kOff01 = ((sn0 + ((lane & 16) >> 1) + (lane & 7)) * QKH_STRIDE
                                 + ((lane >> 3) & 1) * 8) * 2;
        const uint32_t kOff2  = ((sn0 + 16 + (lane & 7)) * QKH_STRIDE
                                 + ((lane >> 3) & 1) * 8) * 2;

        float acc[3][3][4] = {};
        #pragma unroll
        for (int ks = 0; ks < 4; ++ks) {
            const uint32_t kbB = ks * 32;   // 16 halfs
            uint32_t a[3][4], b01[4], b2[2];
            ldsm4(a[0], qBase + qOff[0] + kbB);
            ldsm4(a[1], qBase + qOff[1] + kbB);
            ldsm4(a[2], qBase + qOff[2] + kbB);
            ldsm4(b01, kBase + kOff01 + kbB);
            ldsm2(b2,  kBase + kOff2  + kbB);
            #pragma unroll
            for (int mi = 0; mi < 3; ++mi) {
                mma_f16(acc[mi][0], a[mi], b01);
                mma_f16(acc[mi][1], a[mi], b01 + 2);
                mma_f16(acc[mi][2], a[mi], b2);
            }
        }

        #pragma unroll
        for (int mi = 0; mi < 3; ++mi) {
            const int r0 = sm0 + mi * 16 + g8, r1 = r0 + 8;
            #pragma unroll
            for (int ni = 0; ni < 3; ++ni) {
                const int c0 = sn0 + ni * 8 + 2 * t4, c1 = c0 + 1;
                Ps[r0 * PS_STRIDE + c0] = (r0 == c0) ? -1e30f : acc[mi][ni][0];
                Ps[r0 * PS_STRIDE + c1] = (r0 == c1) ? -1e30f : acc[mi][ni][1];
                Ps[r1 * PS_STRIDE + c0] = (r1 == c0) ? -1e30f : acc[mi][ni][2];
                Ps[r1 * PS_STRIDE + c1] = (r1 == c1) ? -1e30f : acc[mi][ni][3];
            }
        }
    }
    __syncthreads();   // Qs/Ks now dead

    // issue V chunk 0 (fp16) into Vh0
    for (int idx = tid; idx < HH * 8; idx += 256) {
        int gg = idx >> 3, seg = idx & 7;
        cpa16(vhBase0 + (gg * VH_STRIDE + seg * 8) * 2,
              g_vh + (size_t)((b * HH + gg) * WW + w) * CC + seg * 8);
    }
    cpa_commit();

    // ---- softmax: stats + write P as fp16 ----
    for (int h = warp; h < HH; h += 8) {
        float m = -3.4e38f;
        for (int g = lane; g < HH; g += 32) m = fmaxf(m, Ps[h * PS_STRIDE + g]);
        #pragma unroll
        for (int o = 16; o; o >>= 1) m = fmaxf(m, __shfl_xor_sync(0xffffffffu, m, o));
        float l = 0.f;
        for (int g = lane; g < HH; g += 32) {
            __half hp = __float2half_rn(__expf(Ps[h * PS_STRIDE + g] - m));
            Pf[h * PF_STRIDE + g] = hp;
            l += __half2float(hp);
        }
        #pragma unroll
        for (int o = 16; o; o >>= 1) l += __shfl_xor_sync(0xffffffffu, l, o);
        if (lane == 0) {
            int n = (b * HH + h) * WW + w;
            g_mv[n] = m;
            g_lv[n] = l;
        }
    }

    // ---- acc_v = P @ V (fp16 MMA), 8 chunks of 64 channels ----
    const int pm0 = (warp & 1) * 48, pn0 = (warp >> 1) * 16;
    uint32_t pOff[3];
    #pragma unroll
    for (int mi = 0; mi < 3; ++mi)
        pOff[mi] = ((pm0 + mi * 16 + (lane & 15)) * PF_STRIDE + ((lane >> 4) << 3)) * 2;
    const uint32_t vOff = (((lane & 15) * VH_STRIDE) + pn0 + ((lane >> 4) << 3)) * 2;

    for (int c = 0; c < NCHUNK; ++c) {
        if (c + 1 < NCHUNK) {
            const uint32_t dst = (((c + 1) & 1) ? vhBase1 : vhBase0);
            for (int idx = tid; idx < HH * 8; idx += 256) {
                int gg = idx >> 3, seg = idx & 7;
                cpa16(dst + (gg * VH_STRIDE + seg * 8) * 2,
                      g_vh + (size_t)((b * HH + gg) * WW + w) * CC + (c + 1) * 64 + seg * 8);
            }
            cpa_commit();
            cpa_wait1();
        } else {
            cpa_wait0();
        }
        __syncthreads();

        const uint32_t vb = ((c & 1) ? vhBase1 : vhBase0);
        float acc[3][2][4] = {};
        #pragma unroll
        for (int ks = 0; ks < 6; ++ks) {
            uint32_t a[3][4], bf[4];
            ldsm4(a[0], pfBase + pOff[0] + ks * 32);
            ldsm4(a[1], pfBase + pOff[1] + ks * 32);
            ldsm4(a[2], pfBase + pOff[2] + ks * 32);
            ldsm4t(bf, vb + vOff + ks * (16 * VH_STRIDE * 2));
            #pragma unroll
            for (int mi = 0; mi < 3; ++mi) {
                mma_f16(acc[mi][0], a[mi], bf);
                mma_f16(acc[mi][1], a[mi], bf + 2);
            }
        }

        // fragments -> bf16 stage
        #pragma unroll
        for (int mi = 0; mi < 3; ++mi) {
            const int rA = pm0 + mi * 16 + g8;
            #pragma unroll
            for (int ni = 0; ni < 2; ++ni) {
                const int colL = pn0 + ni * 8 + 2 * t4;
                float2 o0 = { acc[mi][ni][0], acc[mi][ni][1] };
                float2 o1 = { acc[mi][ni][2], acc[mi][ni][3] };
                *(__nv_bfloat162*)(stageB + rA * 72 + colL) = __float22bfloat162_rn(o0);
                *(__nv_bfloat162*)(stageB + (rA + 8) * 72 + colL) = __float22bfloat162_rn(o1);
            }
        }
        __syncthreads();

        // coalesced store: 96 rows x 128B
        for (int t = tid; t < HH * 8; t += 256) {
            int row = t >> 3, seg = t & 7;
            uint4 vv = *(uint4*)(sm + SM_STAGE + row * ST_STRIDE + seg * 4);
            *(uint4*)(g_accv + (size_t)((b * HH + row) * WW + w) * CC + c * 64 + seg * 8) = vv;
        }
    }
}

// ---------------- Kernel 3: row attention pass + combine (per (b,h)) --------
__global__ __launch_bounds__(256, 2) void row_attn(
    const float* __restrict__ gammap, float* __restrict__ out)
{
    extern __shared__ float sm[];
    float*    Ps  = sm + SM_PS;
    __half*   Pf  = (__half*)(sm + SM_PF);
    __half*   xstage = (__half*)(sm + SM_PS);   // overlays Ps after softmax
    float* ms = sm + SM_MS;
    float* ls = sm + SM_LS;
    float* fv = sm + SM_FV;
    float* fh = sm + SM_FH;
    __nv_bfloat16* stageB = (__nv_bfloat16*)(sm + SM_STAGE);

    const int tid = threadIdx.x;
    const int lane = tid & 31;
    const int warp = tid >> 5;
    const int g8 = lane >> 2, t4 = lane & 3;
    const int b = blockIdx.x / HH;
    const int h = blockIdx.x % HH;
    const int nbase = (b * HH + h) * WW;

    const uint32_t qBase = s2u(sm);
    const uint32_t kBase = s2u(sm + SM_KSH);
    const uint32_t pfBase = s2u(Pf);
    const uint32_t vhBase0 = qBase;
    const uint32_t vhBase1 = kBase;
    const uint32_t stBase = s2u(stageB);
    const uint32_t xsBase = s2u(xstage);

    for (int idx = tid; idx < WW * 8; idx += 256) {
        int pos = idx >> 3, seg = idx & 7;
        size_t off = (size_t)(nbase + pos) * DD + seg * 8;
        uint32_t d = (pos * QKH_STRIDE + seg * 8) * 2;
        cpa16(qBase + d, g_q + off);
        cpa16(kBase + d, g_k + off);
    }
    if (tid < WW) {
        fv[tid] = g_mv[nbase + tid];
        fh[tid] = g_lv[nbase + tid];
    }
    cpa_commit();
    cpa_wait_all();
    __syncthreads();

    // scores (no mask), fp16 MMA
    {
        const int sm0 = (warp & 1) * 48, sn0 = (warp >> 1) * 24;
        uint32_t qOff[3];
        #pragma unroll
        for (int mi = 0; mi < 3; ++mi)
            qOff[mi] = ((sm0 + mi * 16 + (lane & 15)) * QKH_STRIDE + ((lane >> 4) << 3)) * 2;
        const uint32_t kOff01 = ((sn0 + ((lane & 16) >> 1) + (lane & 7)) * QKH_STRIDE
                                 + ((lane >> 3) & 1) * 8) * 2;
        const uint32_t kOff2  = ((sn0 + 16 + (lane & 7)) * QKH_STRIDE
                                 + ((lane >> 3) & 1) * 8) * 2;

        float acc[3][3][4] = {};
        #pragma unroll
        for (int ks = 0; ks < 4; ++ks) {
            const uint32_t kbB = ks * 32;
            uint32_t a[3][4], b01[4], b2[2];
            ldsm4(a[0], qBase + qOff[0] + kbB);
            ldsm4(a[1], qBase + qOff[1] + kbB);
            ldsm4(a[2], qBase + qOff[2] + kbB);
            ldsm4(b01, kBase + kOff01 + kbB);
            ldsm2(b2,  kBase + kOff2  + kbB);
            #pragma unroll
            for (int mi = 0; mi < 3; ++mi) {
                mma_f16(acc[mi][0], a[mi], b01);
                mma_f16(acc[mi][1], a[mi], b01 + 2);
                mma_f16(acc[mi][2], a[mi], b2);
            }
        }

        #pragma unroll
        for (int mi = 0; mi < 3; ++mi) {
            const int r0 = sm0 + mi * 16 + g8, r1 = r0 + 8;
            #pragma unroll
            for (int ni = 0; ni < 3; ++ni) {
                const int c0 = sn0 + ni * 8 + 2 * t4;
                *(float2*)&Ps[r0 * PS_STRIDE + c0] = *(float2*)&acc[mi][ni][0];
                *(float2*)&Ps[r1 * PS_STRIDE + c0] = *(float2*)&acc[mi][ni][2];
            }
        }
    }
    __syncthreads();   // Qs/Ks dead

    // issue V chunk 0 (own group); accv chunk 0 (group left open, xh joins)
    for (int idx = tid; idx < WW * 8; idx += 256) {
        int u0 = idx >> 3, seg = idx & 7;
        cpa16(vhBase0 + (u0 * VH_STRIDE + seg * 8) * 2,
              g_vh + (size_t)(nbase + u0) * CC + seg * 8);
    }
    cpa_commit();
    for (int t = tid; t < WW * 8; t += 256) {
        int row = t >> 3, seg = t & 7;
        cpa16(stBase + (row * ST_STRIDE + seg * 4) * 4,
              g_accv + (size_t)(nbase + row) * CC + seg * 8);
    }
    // (no commit yet — xh(0) joins this group after softmax)

    // softmax -> fp16 P (reads Ps fp32)
    for (int wq = warp; wq < WW; wq += 8) {
        float m = -3.4e38f;
        for (int g = lane; g < WW; g += 32) m = fmaxf(m, Ps[wq * PS_STRIDE + g]);
        #pragma unroll
        for (int o = 16; o; o >>= 1) m = fmaxf(m, __shfl_xor_sync(0xffffffffu, m, o));
        float l = 0.f;
        for (int g = lane; g < WW; g += 32) {
            __half hp = __float2half_rn(__expf(Ps[wq * PS_STRIDE + g] - m));
            Pf[wq * PF_STRIDE + g] = hp;
            l += __half2float(hp);
        }
        #pragma unroll
        for (int o = 16; o; o >>= 1) l += __shfl_xor_sync(0xffffffffu, l, o);
        if (lane == 0) { ms[wq] = m; ls[wq] = l; }
    }
    __syncthreads();   // all done reading Ps -> region reusable as xh stage

    // issue xh(0) into dead Ps region; commit closes the accv(0)+xh(0) group
    for (int t = tid; t < WW * 8; t += 256) {
        int row = t >> 3, seg = t & 7;
        cpa16(xsBase + (row * QKH_STRIDE + seg * 8) * 2,
              g_xh + (size_t)(nbase + row) * CC + seg * 8);
    }
    cpa_commit();

    if (tid < WW) {
        float mh = ms[tid], lh = ls[tid];
        float mv = fv[tid], lv = fh[tid];
        float M  = fmaxf(mh, mv);
        float ev = __expf(mv - M), eh = __expf(mh - M);
        float inv = 1.f / (ev * lv + eh * lh);
        fv[tid] = ev * inv;
        fh[tid] = eh * inv;
    }

    const float gamma = *gammap;
    const int pm0 = (warp & 1) * 48, pn0 = (warp >> 1) * 16;
    uint32_t pOff[3];
    #pragma unroll
    for (int mi = 0; mi < 3; ++mi)
        pOff[mi] = ((pm0 + mi * 16 + (lane & 15)) * PF_STRIDE + ((lane >> 4) << 3)) * 2;
    const uint32_t vOff = (((lane & 15) * VH_STRIDE) + pn0 + ((lane >> 4) << 3)) * 2;

    // invariant at iter c entry: pending groups = [V(c), AX(c)]
    for (int c = 0; c < NCHUNK; ++c) {
        if (c + 1 < NCHUNK) {
            const uint32_t dst = (((c + 1) & 1) ? vhBase1 : vhBase0);
            for (int idx = tid; idx < WW * 8; idx += 256) {
                int u0 = idx >> 3, seg = idx & 7;
                cpa16(dst + (u0 * VH_STRIDE + seg * 8) * 2,
                      g_vh + (size_t)(nbase + u0) * CC + (c + 1) * 64 + seg * 8);
            }
            cpa_commit();
            cpa_wait2();    // V(c) done; [AX(c), V(c+1)] pending
        } else {
            cpa_wait1();    // V(7) done; [AX(7)] pending
        }
        __syncthreads();

        const uint32_t vb = ((c & 1) ? vhBase1 : vhBase0);
        float acc[3][2][4] = {};
        #pragma unroll
        for (int ks = 0; ks < 6; ++ks) {
            uint32_t a[3][4], bf[4];
            ldsm4(a[0], pfBase + pOff[0] + ks * 32);
            ldsm4(a[1], pfBase + pOff[1] + ks * 32);
            ldsm4(a[2], pfBase + pOff[2] + ks * 32);
            ldsm4t(bf, vb + vOff + ks * (16 * VH_STRIDE * 2));
            #pragma unroll
            for (int mi = 0; mi < 3; ++mi) {
                mma_f16(acc[mi][0], a[mi], bf);
                mma_f16(acc[mi][1], a[mi], bf + 2);
            }
        }

        if (c + 1 < NCHUNK) cpa_wait1();   // AX(c) done; V(c+1) pending
        else                cpa_wait0();
        __syncthreads();

        #pragma unroll
        for (int mi = 0; mi < 3; ++mi) {
            const int rA = pm0 + mi * 16 + g8;
            const int rB = rA + 8;
            const float fvA = fv[rA], fhA = fh[rA];
            const float fvB = fv[rB], fhB = fh[rB];
            const size_t oA = (size_t)(nbase + rA) * CC;
            const size_t oB = (size_t)(nbase + rB) * CC;
            #pragma unroll
            for (int ni = 0; ni < 2; ++ni) {
                const int colL = pn0 + ni * 8 + 2 * t4;
                const int col = c * 64 + colL;
                float2 avA = __bfloat1622float2(*(__nv_bfloat162*)(stageB + rA * 72 + colL));
                float2 avB = __bfloat1622float2(*(__nv_bfloat162*)(stageB + rB * 72 + colL));
                float2 xvA = __half22float2(*(__half2*)(xstage + rA * QKH_STRIDE + colL));
                float2 xvB = __half22float2(*(__half2*)(xstage + rB * QKH_STRIDE + colL));
                float2 o0, o1;
                o0.x = xvA.x + gamma * (fvA * avA.x + fhA * acc[mi][ni][0]);
                o0.y = xvA.y + gamma * (fvA * avA.y + fhA * acc[mi][ni][1]);
                o1.x = xvB.x + gamma * (fvB * avB.x + fhB * acc[mi][ni][2]);
                o1.y = xvB.y + gamma * (fvB * avB.y + fhB * acc[mi][ni][3]);
                *(float2*)(out + oA + col) = o0;
                *(float2*)(out + oB + col) = o1;
            }
        }
        __syncthreads();   // all threads done reading accv/xh stages

        if (c + 1 < NCHUNK) {
            for (int t = tid; t < WW * 8; t += 256) {
                int row = t >> 3, seg = t & 7;
                cpa16(stBase + (row * ST_STRIDE + seg * 4) * 4,
                      g_accv + (size_t)(nbase + row) * CC + (c + 1) * 64 + seg * 8);
                cpa16(xsBase + (row * QKH_STRIDE + seg * 8) * 2,
                      g_xh + (size_t)(nbase + row) * CC + (c + 1) * 64 + seg * 8);
            }
            cpa_commit();
        }
    }
}

// ---------------- launch ----------------------------------------------------
extern "C" void kernel_launch(void* const* d_in, const int* in_sizes, int n_in,
                              void* d_out, int out_size)
{
    const float* x  = (const float*)d_in[0];
    const float* Wq = (const float*)d_in[1];
    const float* bq = (const float*)d_in[2];
    const float* Wk = (const float*)d_in[3];
    const float* bk = (const float*)d_in[4];
    const float* Wv = (const float*)d_in[5];
    const float* bv = (const float*)d_in[6];
    const float* gm = (const float*)d_in[7];
    float* out = (float*)d_out;

    cudaFuncSetAttribute(qkv_gemm, cudaFuncAttributeMaxDynamicSharedMemorySize, QKV_SMEM_BYTES);
    cudaFuncSetAttribute(col_attn, cudaFuncAttributeMaxDynamicSharedMemorySize, SMEM_BYTES);
    cudaFuncSetAttribute(row_attn, cudaFuncAttributeMaxDynamicSharedMemorySize, SMEM_BYTES);

    cvt_x<<<36864, 256>>>(x);
    cvt_w<<<1280, 256>>>(Wq, Wk, Wv);
    dim3 gA(5, 576);
    qkv_gemm<<<gA, 256, QKV_SMEM_BYTES>>>(bq, bk, bv);
    col_attn<<<768, 256, SMEM_BYTES>>>();
    row_attn<<<768, 256, SMEM_BYTES>>>(gm, out);
}